// round 9
// baseline (speedup 1.0000x reference)
#include <cuda_runtime.h>
#include <math.h>
#include <stdint.h>

#define NTOK 2048
#define TSEQ 1024
#define D    768
#define FFN  3072
#define NS   6
#define VOC  32000

// ---------------- fp32 scratch ----------------
#define ROW (NTOK*D)
#define OFF_MU    0
#define OFF_LAM   (1*ROW)
#define OFF_MUHAT (2*ROW)
#define OFF_MUN   (3*ROW)
#define OFF_SO    (4*ROW)
#define OFF_Q     (5*ROW)
#define OFF_DLAM  (8*ROW)
#define OFF_MHAT  (9*ROW)
#define OFF_TRH   (10*ROW)
#define OFF_PI    (10*ROW + NTOK*1536)
#define SCRATCH_FLOATS (OFF_PI + NTOK*NS)

__device__ float g_scratch[SCRATCH_FLOATS];
__device__ int   g_cnt[NS];
__device__ int   g_list[NS * NTOK];
__device__ int   g_cnt2[2 * NS];
__device__ int   g_slot2[2 * NS * NTOK];
__device__ int   g_tok2[2 * NS * NTOK];

// ---------------- activation split arena (hi/lo tf32) ----------------
#define S_H    0
#define S_MU   (1*ROW)
#define S_MUN  (2*ROW)
#define S_MUR  (3*ROW)
#define S_MSG  (4*ROW)
#define S_FIN  (5*ROW)
#define S_HB   (6*ROW)
#define ASPLIT (6*ROW + NS*NTOK*FFN)

__device__ float g_ahi[ASPLIT];
__device__ float g_alo[ASPLIT];

// ---------------- pre-split weight arena ----------------
#define W_MU   0
#define W_LAM  589824
#define W_TR1  1179648
#define W_RTQ  2359296
#define W_RTK  2949120
#define W_RTV  3538944
#define W_WRL  4128768
#define W_WRM  4718592
#define W_B1   5308416
#define W_B2   19464192
#define W_EMBT 33619968
#define WSPLIT 58195968

__device__ float g_whi[WSPLIT];
__device__ float g_wlo[WSPLIT];

// ---------------- helpers ----------------
__device__ __forceinline__ float gelu_f(float x) {
    float x3 = x * x * x;
    return 0.5f * x * (1.f + tanhf(0.7978845608028654f * (x + 0.044715f * x3)));
}
__device__ __forceinline__ float softplus_f(float x) {
    return fmaxf(x, 0.f) + log1pf(expf(-fabsf(x)));
}
__device__ __forceinline__ float block_sum(float v, float* red) {
    int tid = threadIdx.x;
    __syncthreads();
#pragma unroll
    for (int o = 16; o > 0; o >>= 1) v += __shfl_xor_sync(0xffffffffu, v, o);
    if ((tid & 31) == 0) red[tid >> 5] = v;
    __syncthreads();
    if (tid < 32) {
        float t = (tid < (int)(blockDim.x >> 5)) ? red[tid] : 0.f;
#pragma unroll
        for (int o = 4; o > 0; o >>= 1) t += __shfl_xor_sync(0xffffffffu, t, o);
        if (tid == 0) red[0] = t;
    }
    __syncthreads();
    return red[0];
}

__device__ __forceinline__ void cvt_split(float x, float& hi, float& lo) {
    uint32_t hb; asm("cvt.rna.tf32.f32 %0, %1;" : "=r"(hb) : "f"(x));
    hi = __uint_as_float(hb);
    float lf = x - hi;
    uint32_t lb; asm("cvt.rna.tf32.f32 %0, %1;" : "=r"(lb) : "f"(lf));
    lo = __uint_as_float(lb);
}

// ---------------- weight prep ----------------
__global__ void split_k(const float* __restrict__ src, float* __restrict__ hi,
                        float* __restrict__ lo, int n4)
{
    int i = blockIdx.x * blockDim.x + threadIdx.x;
    if (i >= n4) return;
    float4 v = ((const float4*)src)[i];
    float4 h, l;
    cvt_split(v.x, h.x, l.x); cvt_split(v.y, h.y, l.y);
    cvt_split(v.z, h.z, l.z); cvt_split(v.w, h.w, l.w);
    ((float4*)hi)[i] = h;
    ((float4*)lo)[i] = l;
}

__global__ void tsplit_emb_k(const float* __restrict__ emb,
                             float* __restrict__ hi, float* __restrict__ lo)
{
    __shared__ float tile[32][33];
    int v0 = blockIdx.x * 32, d0 = blockIdx.y * 32;
    int tx = threadIdx.x, ty = threadIdx.y;
    for (int r = ty; r < 32; r += 8)
        tile[r][tx] = emb[(long)(v0 + r) * D + d0 + tx];
    __syncthreads();
    for (int r = ty; r < 32; r += 8) {
        float hf, lf;
        cvt_split(tile[tx][r], hf, lf);
        long o = (long)(d0 + r) * VOC + v0 + tx;
        hi[o] = hf;
        lo[o] = lf;
    }
}

// ---------------- tf32 mma core ----------------
// smem: AHI[3][128][20] @0, ALO @7680, BHI[3][16][136] @15360, BLO @21888
// total 28416 floats = 113664 B -> 2 CTAs/SM
#define A_ST   2560
#define B_STF  2176
#define SM_AHI 0
#define SM_ALO 7680
#define SM_BHI 15360
#define SM_BLO 21888
#define SM_BYTES (28416 * 4)

__device__ __forceinline__ void mma8(float* c, const uint32_t* a, uint32_t b0, uint32_t b1) {
    asm volatile(
        "mma.sync.aligned.m16n8k8.row.col.f32.tf32.tf32.f32 "
        "{%0,%1,%2,%3},{%4,%5,%6,%7},{%8,%9},{%0,%1,%2,%3};"
        : "+f"(c[0]), "+f"(c[1]), "+f"(c[2]), "+f"(c[3])
        : "r"(a[0]), "r"(a[1]), "r"(a[2]), "r"(a[3]), "r"(b0), "r"(b1));
}

__device__ __forceinline__ void cp16(uint32_t dst, const float* src) {
    asm volatile("cp.async.ca.shared.global [%0], [%1], 16;" :: "r"(dst), "l"(src) : "memory");
}

// block 128x128, 8 warps (4m x 2n), warp tile 32x64, BK=16.
// A and B both pre-split in gmem; 3-stage ring; ONE barrier per slice.
// issue(i+2) sits after barrier(i): stage (i+2)%3's previous readers comp(i-1)
// all finished before barrier(i) -> no write-after-read race.
template <bool GATHER>
__device__ __forceinline__ void tf32_loop(
    const float* __restrict__ Ahi_g, const float* __restrict__ Alo_g,
    const float* __restrict__ Bhi, const float* __restrict__ Blo,
    int K, int N, int bm0, int bn0, const int* __restrict__ rowTok,
    float* __restrict__ sm, float c[2][8][4])
{
    const int tid = threadIdx.x;
    const int lane = tid & 31, warp = tid >> 5;
    const int wm0 = (warp >> 1) * 32, wn0 = (warp & 1) * 64;
    const int g = lane >> 2, tig = lane & 3;

    const int arow0 = tid >> 2, arow1 = arow0 + 64, aq = tid & 3;
    long agr0, agr1;
    if (GATHER) { agr0 = rowTok[arow0]; agr1 = rowTok[arow1]; }
    else        { agr0 = bm0 + arow0;   agr1 = bm0 + arow1;   }
    const int bkr = tid >> 5;
    const int bn4 = (tid & 31) * 4;

    const uint32_t smb = (uint32_t)__cvta_generic_to_shared(sm);

    auto issue = [&](int st, int k0) {
        uint32_t ah = smb + (uint32_t)(SM_AHI + st * A_ST) * 4u;
        uint32_t al = smb + (uint32_t)(SM_ALO + st * A_ST) * 4u;
        cp16(ah + (uint32_t)(arow0 * 20 + aq * 4) * 4u, Ahi_g + agr0 * K + k0 + aq * 4);
        cp16(ah + (uint32_t)(arow1 * 20 + aq * 4) * 4u, Ahi_g + agr1 * K + k0 + aq * 4);
        cp16(al + (uint32_t)(arow0 * 20 + aq * 4) * 4u, Alo_g + agr0 * K + k0 + aq * 4);
        cp16(al + (uint32_t)(arow1 * 20 + aq * 4) * 4u, Alo_g + agr1 * K + k0 + aq * 4);
        uint32_t bh = smb + (uint32_t)(SM_BHI + st * B_STF) * 4u;
        uint32_t bl = smb + (uint32_t)(SM_BLO + st * B_STF) * 4u;
        cp16(bh + (uint32_t)(bkr * 136 + bn4) * 4u,
             Bhi + (long)(k0 + bkr) * N + bn0 + bn4);
        cp16(bh + (uint32_t)((bkr + 8) * 136 + bn4) * 4u,
             Bhi + (long)(k0 + bkr + 8) * N + bn0 + bn4);
        cp16(bl + (uint32_t)(bkr * 136 + bn4) * 4u,
             Blo + (long)(k0 + bkr) * N + bn0 + bn4);
        cp16(bl + (uint32_t)((bkr + 8) * 136 + bn4) * 4u,
             Blo + (long)(k0 + bkr + 8) * N + bn0 + bn4);
        asm volatile("cp.async.commit_group;" ::: "memory");
    };

    auto comp = [&](int st) {
        const float* ahp = sm + SM_AHI + st * A_ST;
        const float* alp = sm + SM_ALO + st * A_ST;
        const float* bhp = sm + SM_BHI + st * B_STF;
        const float* blp = sm + SM_BLO + st * B_STF;
#pragma unroll
        for (int ks = 0; ks < 16; ks += 8) {
            uint32_t ah[2][4], al[2][4];
#pragma unroll
            for (int mt = 0; mt < 2; mt++) {
                int rb = wm0 + mt * 16 + g;
                ah[mt][0] = __float_as_uint(ahp[rb * 20 + ks + tig]);
                ah[mt][1] = __float_as_uint(ahp[(rb + 8) * 20 + ks + tig]);
                ah[mt][2] = __float_as_uint(ahp[rb * 20 + ks + tig + 4]);
                ah[mt][3] = __float_as_uint(ahp[(rb + 8) * 20 + ks + tig + 4]);
                al[mt][0] = __float_as_uint(alp[rb * 20 + ks + tig]);
                al[mt][1] = __float_as_uint(alp[(rb + 8) * 20 + ks + tig]);
                al[mt][2] = __float_as_uint(alp[rb * 20 + ks + tig + 4]);
                al[mt][3] = __float_as_uint(alp[(rb + 8) * 20 + ks + tig + 4]);
            }
#pragma unroll
            for (int nt = 0; nt < 8; nt++) {
                int cb = wn0 + nt * 8 + g;
                uint32_t bh0 = __float_as_uint(bhp[(ks + tig) * 136 + cb]);
                uint32_t bh1 = __float_as_uint(bhp[(ks + tig + 4) * 136 + cb]);
                uint32_t bl0 = __float_as_uint(blp[(ks + tig) * 136 + cb]);
                uint32_t bl1 = __float_as_uint(blp[(ks + tig + 4) * 136 + cb]);
#pragma unroll
                for (int mt = 0; mt < 2; mt++) {
                    mma8(c[mt][nt], ah[mt], bh0, bh1);
                    mma8(c[mt][nt], ah[mt], bl0, bl1);
                    mma8(c[mt][nt], al[mt], bh0, bh1);
                }
            }
        }
    };

    const int nk = K >> 4;  // >= 48 at all call sites
    issue(0, 0);
    issue(1, 16);
    int st = 0, stn = 2;
    for (int i = 0; i < nk; i++) {
        if (i < nk - 1) asm volatile("cp.async.wait_group 1;" ::: "memory");
        else            asm volatile("cp.async.wait_group 0;" ::: "memory");
        __syncthreads();
        if (i + 2 < nk) {
            issue(stn, (i + 2) << 4);
            stn = (stn == 2) ? 0 : stn + 1;
        }
        comp(st);
        st = (st == 2) ? 0 : st + 1;
    }
}

// ---------------- epilogues ----------------
enum { EPI_NONE = 0, EPI_BIAS = 1, EPI_GELU = 2, EPI_GSP = 3, EPI_SCALE = 4, EPI_SP01 = 5 };

template <int EPI>
__device__ __forceinline__ float epi_apply(float v, float b, float rs, float alpha) {
    if (EPI == EPI_BIAS)  return v + b;
    if (EPI == EPI_GELU)  return gelu_f(v + b);
    if (EPI == EPI_GSP)   return rs * softplus_f(v + b);
    if (EPI == EPI_SCALE) return v * alpha;
    if (EPI == EPI_SP01)  return softplus_f(v + b) + 0.1f;
    return v;
}

template <int EPI, bool WF32, bool WSPL>
__device__ __forceinline__ void epi_store_dense(
    float c[2][8][4], float* __restrict__ C,
    float* __restrict__ Chi, float* __restrict__ Clo,
    const float* __restrict__ bias,
    int N, int bm0, int bn0, const float* __restrict__ pi, float alpha)
{
    const int tid = threadIdx.x, lane = tid & 31, warp = tid >> 5;
    const int wm0 = (warp >> 1) * 32, wn0 = (warp & 1) * 64;
    const int g = lane >> 2, tig = lane & 3;
    const int colbase = bn0 + wn0;
#pragma unroll
    for (int mt = 0; mt < 2; mt++) {
#pragma unroll
        for (int half = 0; half < 2; half++) {
            int row = bm0 + wm0 + mt * 16 + g + half * 8;
            float rs = (EPI == EPI_GSP) ? pi[row * NS + 4] : 0.f;
            long base = (long)row * N + colbase;
#pragma unroll
            for (int nt = 0; nt < 8; nt++) {
                int col = nt * 8 + tig * 2;
                float b0 = 0.f, b1 = 0.f;
                if (EPI == EPI_BIAS || EPI == EPI_GELU || EPI == EPI_GSP || EPI == EPI_SP01) {
                    b0 = bias[colbase + col];
                    b1 = bias[colbase + col + 1];
                }
                float v0 = epi_apply<EPI>(c[mt][nt][half * 2], b0, rs, alpha);
                float v1 = epi_apply<EPI>(c[mt][nt][half * 2 + 1], b1, rs, alpha);
                if (WF32) *(float2*)(C + base + col) = make_float2(v0, v1);
                if (WSPL) {
                    float h0, l0, h1, l1;
                    cvt_split(v0, h0, l0);
                    cvt_split(v1, h1, l1);
                    *(float2*)(Chi + base + col) = make_float2(h0, h1);
                    *(float2*)(Clo + base + col) = make_float2(l0, l1);
                }
            }
        }
    }
}

// ---------------- GEMM kernels ----------------
template <int EPI>
__global__ void __launch_bounds__(256, 2) tgemm_k(
    const float* __restrict__ Ahi, const float* __restrict__ Alo,
    const float* __restrict__ Bhi, const float* __restrict__ Blo,
    const float* __restrict__ bias, float* __restrict__ C,
    int N, int K, float alpha)
{
    extern __shared__ float sm[];
    const int bm0 = blockIdx.y * 128, bn0 = blockIdx.x * 128;
    float c[2][8][4];
#pragma unroll
    for (int a = 0; a < 2; a++)
#pragma unroll
        for (int b = 0; b < 8; b++)
#pragma unroll
            for (int r = 0; r < 4; r++) c[a][b][r] = 0.f;
    tf32_loop<false>(Ahi, Alo, Bhi, Blo, K, N, bm0, bn0, nullptr, sm, c);
    epi_store_dense<EPI, true, false>(c, C, nullptr, nullptr, bias, N, bm0, bn0, nullptr, alpha);
}

// z-pair: z selects weight slab (stride D*D), bias, epi. SPL0: z0 also writes split.
template <int EPI0, int EPI1, bool SPL0>
__global__ void __launch_bounds__(256, 2) tgemm_pair_k(
    const float* __restrict__ Ahi, const float* __restrict__ Alo,
    const float* __restrict__ Whi, const float* __restrict__ Wlo,
    const float* __restrict__ b0, const float* __restrict__ b1,
    const float* __restrict__ pi, float* __restrict__ Cbase,
    float* __restrict__ Chi0, float* __restrict__ Clo0)
{
    extern __shared__ float sm[];
    const int z = blockIdx.z;
    const float* Bhi = Whi + (long)z * D * D;
    const float* Blo = Wlo + (long)z * D * D;
    const float* bias = z ? b1 : b0;
    float* C = Cbase + (long)z * ROW;
    const int bm0 = blockIdx.y * 128, bn0 = blockIdx.x * 128;
    float c[2][8][4];
#pragma unroll
    for (int a = 0; a < 2; a++)
#pragma unroll
        for (int b = 0; b < 8; b++)
#pragma unroll
            for (int r = 0; r < 4; r++) c[a][b][r] = 0.f;
    tf32_loop<false>(Ahi, Alo, Bhi, Blo, D, D, bm0, bn0, nullptr, sm, c);
    if (z == 0) {
        if (SPL0) epi_store_dense<EPI0, true, true>(c, C, Chi0, Clo0, bias, D, bm0, bn0, pi, 1.f);
        else      epi_store_dense<EPI0, true, false>(c, C, nullptr, nullptr, bias, D, bm0, bn0, pi, 1.f);
    } else {
        epi_store_dense<EPI1, true, false>(c, C, nullptr, nullptr, bias, D, bm0, bn0, pi, 1.f);
    }
}

__global__ void __launch_bounds__(256, 2) tqkv_k(
    const float* __restrict__ Ahi, const float* __restrict__ Alo,
    const float* __restrict__ Whi, const float* __restrict__ Wlo,
    float* __restrict__ Cbase)
{
    extern __shared__ float sm[];
    const int z = blockIdx.z;
    const float* Bhi = Whi + (long)z * D * D;
    const float* Blo = Wlo + (long)z * D * D;
    float* C = Cbase + (long)z * ROW;
    const int bm0 = blockIdx.y * 128, bn0 = blockIdx.x * 128;
    float c[2][8][4];
#pragma unroll
    for (int a = 0; a < 2; a++)
#pragma unroll
        for (int b = 0; b < 8; b++)
#pragma unroll
            for (int r = 0; r < 4; r++) c[a][b][r] = 0.f;
    tf32_loop<false>(Ahi, Alo, Bhi, Blo, D, D, bm0, bn0, nullptr, sm, c);
    epi_store_dense<EPI_NONE, true, false>(c, C, nullptr, nullptr, nullptr, D, bm0, bn0, nullptr, 1.f);
}

// bank1: gathered mun split -> hb split (gelu)
__global__ void __launch_bounds__(256, 2) tbank1_k(
    const float* __restrict__ Ahi, const float* __restrict__ Alo,
    const float* __restrict__ Whi, const float* __restrict__ Wlo,
    const float* __restrict__ b1all,
    float* __restrict__ hbhi, float* __restrict__ hblo,
    const int* __restrict__ list, const int* __restrict__ cnt)
{
    extern __shared__ float sm[];
    __shared__ int rowTok[128];
    const int s = blockIdx.z;
    const int cn = cnt[s];
    const int bm0 = blockIdx.y * 128;
    if (bm0 >= cn) return;
    const int tid = threadIdx.x;
    if (tid < 128) rowTok[tid] = list[s * NTOK + min(bm0 + tid, cn - 1)];
    __syncthreads();

    const float* Bhi = Whi + (long)s * D * FFN;
    const float* Blo = Wlo + (long)s * D * FFN;
    const float* bias = b1all + s * FFN;
    float* Chi = hbhi + (long)s * NTOK * FFN;
    float* Clo = hblo + (long)s * NTOK * FFN;
    const int bn0 = blockIdx.x * 128;

    float c[2][8][4];
#pragma unroll
    for (int a = 0; a < 2; a++)
#pragma unroll
        for (int b = 0; b < 8; b++)
#pragma unroll
            for (int r = 0; r < 4; r++) c[a][b][r] = 0.f;
    tf32_loop<true>(Ahi, Alo, Bhi, Blo, D, FFN, 0, bn0, rowTok, sm, c);

    const int lane = tid & 31, warp = tid >> 5;
    const int wm0 = (warp >> 1) * 32, wn0 = (warp & 1) * 64;
    const int g = lane >> 2, tig = lane & 3;
    const int colbase = bn0 + wn0;
#pragma unroll
    for (int mt = 0; mt < 2; mt++) {
#pragma unroll
        for (int half = 0; half < 2; half++) {
            int slot = bm0 + wm0 + mt * 16 + g + half * 8;
            if (slot >= cn) continue;
            long base = (long)slot * FFN + colbase;
#pragma unroll
            for (int nt = 0; nt < 8; nt++) {
                int col = nt * 8 + tig * 2;
                float v0 = gelu_f(c[mt][nt][half * 2] + bias[colbase + col]);
                float v1 = gelu_f(c[mt][nt][half * 2 + 1] + bias[colbase + col + 1]);
                float h0, l0, h1, l1;
                cvt_split(v0, h0, l0);
                cvt_split(v1, h1, l1);
                *(float2*)(Chi + base + col) = make_float2(h0, h1);
                *(float2*)(Clo + base + col) = make_float2(l0, l1);
            }
        }
    }
}

// bank2: gathered hb split -> scatter into so fp32
template <int RANK>
__global__ void __launch_bounds__(256, 2) tbank2_k(
    const float* __restrict__ hbhi, const float* __restrict__ hblo,
    const float* __restrict__ Whi, const float* __restrict__ Wlo,
    const float* __restrict__ b2all, float* __restrict__ so,
    const int* __restrict__ cnt2, const int* __restrict__ slot2,
    const int* __restrict__ tok2, const float* __restrict__ pi)
{
    extern __shared__ float sm[];
    __shared__ int rowSlot[128];
    const int s = blockIdx.z;
    const int cn = cnt2[RANK * NS + s];
    const int bm0 = blockIdx.y * 128;
    if (bm0 >= cn) return;
    const int tid = threadIdx.x;
    const int lbase = (RANK * NS + s) * NTOK;
    if (tid < 128) rowSlot[tid] = slot2[lbase + min(bm0 + tid, cn - 1)];
    __syncthreads();

    const float* Ahi = hbhi + (long)s * NTOK * FFN;
    const float* Alo = hblo + (long)s * NTOK * FFN;
    const float* Bhi = Whi + (long)s * FFN * D;
    const float* Blo = Wlo + (long)s * FFN * D;
    const float* bias = b2all + s * D;
    const int bn0 = blockIdx.x * 128;

    float c[2][8][4];
#pragma unroll
    for (int a = 0; a < 2; a++)
#pragma unroll
        for (int b = 0; b < 8; b++)
#pragma unroll
            for (int r = 0; r < 4; r++) c[a][b][r] = 0.f;
    tf32_loop<true>(Ahi, Alo, Bhi, Blo, FFN, D, 0, bn0, rowSlot, sm, c);

    const int lane = tid & 31, warp = tid >> 5;
    const int wm0 = (warp >> 1) * 32, wn0 = (warp & 1) * 64;
    const int g = lane >> 2, tig = lane & 3;
    const int colbase = bn0 + wn0;
#pragma unroll
    for (int mt = 0; mt < 2; mt++) {
#pragma unroll
        for (int half = 0; half < 2; half++) {
            int idx = bm0 + wm0 + mt * 16 + g + half * 8;
            if (idx >= cn) continue;
            int tok = tok2[lbase + idx];
            float rs = pi[tok * NS + s];
            float* cp = so + (long)tok * D + colbase;
#pragma unroll
            for (int nt = 0; nt < 8; nt++) {
                int col = nt * 8 + tig * 2;
                float v0 = rs * (c[mt][nt][half * 2] + bias[colbase + col]);
                float v1 = rs * (c[mt][nt][half * 2 + 1] + bias[colbase + col + 1]);
                if (RANK == 0) {
                    *(float2*)(cp + col) = make_float2(v0, v1);
                } else {
                    float2 old = *(float2*)(cp + col);
                    *(float2*)(cp + col) = make_float2(old.x + v0, old.y + v1);
                }
            }
        }
    }
}

// ---------------- small kernels ----------------
__global__ void emb_k(const int* __restrict__ x, const float* __restrict__ emb,
                      const float* __restrict__ pos,
                      float* __restrict__ hhi, float* __restrict__ hlo)
{
    int n = blockIdx.x;
    int vx = x[n];
    int t = n % TSEQ;
    const float* e = emb + (long)vx * D;
    const float* p = pos + (long)t * D;
    for (int j = threadIdx.x; j < D; j += blockDim.x) {
        float v = e[j] + p[j];
        float hf, lf;
        cvt_split(v, hf, lf);
        hhi[(long)n * D + j] = hf;
        hlo[(long)n * D + j] = lf;
    }
}

__global__ void pi_init_k(float* __restrict__ pi)
{
    int i = blockIdx.x * blockDim.x + threadIdx.x;
    if (i < NTOK * NS) pi[i] = ((i % NS) == 2) ? 1.f : 0.f;
}

__global__ void reset_cnt_k(int* cnt, int* cnt2)
{
    if (threadIdx.x < NS) cnt[threadIdx.x] = 0;
    if (threadIdx.x < 2 * NS) cnt2[threadIdx.x] = 0;
}

__global__ void build_lists_k(const float* __restrict__ pi,
                              int* __restrict__ cnt, int* __restrict__ list,
                              int* __restrict__ cnt2, int* __restrict__ slot2,
                              int* __restrict__ tok2)
{
    int t = blockIdx.x * blockDim.x + threadIdx.x;
    if (t >= NTOK) return;
    int r = 0;
#pragma unroll
    for (int s = 0; s < NS; s++) {
        if (pi[t * NS + s] != 0.f) {
            int p = atomicAdd(&cnt[s], 1);
            list[s * NTOK + p] = t;
            int rr = min(r, 1);
            int q = atomicAdd(&cnt2[rr * NS + s], 1);
            slot2[(rr * NS + s) * NTOK + q] = p;
            tok2[(rr * NS + s) * NTOK + q] = t;
            r++;
        }
    }
}

// ln(mu,0)->mun (fp32 + split), ln(mu,2)->mur (split only), core -> muhat
__global__ void ln012_k(const float* __restrict__ mu, float* __restrict__ muhat,
                        float* __restrict__ mun,
                        float* __restrict__ munhi, float* __restrict__ munlo,
                        float* __restrict__ murhi, float* __restrict__ murlo,
                        const float* __restrict__ ln_g, const float* __restrict__ ln_b)
{
    __shared__ float red[8];
    int n = blockIdx.x, tid = threadIdx.x;
    const float* row = mu + (long)n * D;
    float v[3], s = 0.f;
#pragma unroll
    for (int r = 0; r < 3; r++) { v[r] = row[tid + r * 256]; s += v[r]; }
    float mean = block_sum(s, red) / D;
    float qv = 0.f;
#pragma unroll
    for (int r = 0; r < 3; r++) { float d = v[r] - mean; qv += d * d; }
    float var = block_sum(qv, red) / D;
    float inv = rsqrtf(var + 1e-5f);
#pragma unroll
    for (int r = 0; r < 3; r++) {
        int j = tid + r * 256;
        float nh = (v[r] - mean) * inv;
        long idx = (long)n * D + j;
        muhat[idx] = nh;
        float mn = nh * ln_g[j] + ln_b[j];
        float mr = nh * ln_g[2 * D + j] + ln_b[2 * D + j];
        mun[idx] = mn;
        float hf, lf;
        cvt_split(mn, hf, lf);
        munhi[idx] = hf; munlo[idx] = lf;
        cvt_split(mr, hf, lf);
        murhi[idx] = hf; murlo[idx] = lf;
    }
}

__global__ void ln_gen_k(const float* __restrict__ in, float* __restrict__ out,
                         const float* __restrict__ g, const float* __restrict__ b)
{
    __shared__ float red[8];
    int n = blockIdx.x, tid = threadIdx.x;
    const float* row = in + (long)n * D;
    float v[3], s = 0.f;
#pragma unroll
    for (int r = 0; r < 3; r++) { v[r] = row[tid + r * 256]; s += v[r]; }
    float mean = block_sum(s, red) / D;
    float qv = 0.f;
#pragma unroll
    for (int r = 0; r < 3; r++) { float d = v[r] - mean; qv += d * d; }
    float var = block_sum(qv, red) / D;
    float inv = rsqrtf(var + 1e-5f);
#pragma unroll
    for (int r = 0; r < 3; r++) {
        int j = tid + r * 256;
        out[(long)n * D + j] = (v[r] - mean) * inv * g[j] + b[j];
    }
}

// LN -> split only (fin)
__global__ void ln_split_k(const float* __restrict__ in,
                           float* __restrict__ ohi, float* __restrict__ olo,
                           const float* __restrict__ g, const float* __restrict__ b)
{
    __shared__ float red[8];
    int n = blockIdx.x, tid = threadIdx.x;
    const float* row = in + (long)n * D;
    float v[3], s = 0.f;
#pragma unroll
    for (int r = 0; r < 3; r++) { v[r] = row[tid + r * 256]; s += v[r]; }
    float mean = block_sum(s, red) / D;
    float qv = 0.f;
#pragma unroll
    for (int r = 0; r < 3; r++) { float d = v[r] - mean; qv += d * d; }
    float var = block_sum(qv, red) / D;
    float inv = rsqrtf(var + 1e-5f);
#pragma unroll
    for (int r = 0; r < 3; r++) {
        int j = tid + r * 256;
        float val = (v[r] - mean) * inv * g[j] + b[j];
        float hf, lf;
        cvt_split(val, hf, lf);
        long idx = (long)n * D + j;
        ohi[idx] = hf;
        olo[idx] = lf;
    }
}

__global__ void routing_k(const float* __restrict__ trh, const float* __restrict__ w2,
                          const float* __restrict__ b2, const float* __restrict__ mun,
                          const float* __restrict__ evw, const float* __restrict__ evb,
                          float* __restrict__ pi)
{
    __shared__ float sh[1536];
    __shared__ float smn[D];
    __shared__ float kz[36];
    __shared__ float ev[6];
    __shared__ float spi[6];
    int n = blockIdx.x, tid = threadIdx.x;
    for (int i = tid; i < 1536; i += 128) sh[i] = trh[(long)n * 1536 + i];
    for (int i = tid; i < D; i += 128)    smn[i] = mun[(long)n * D + i];
    if (tid < NS) spi[tid] = pi[n * NS + tid];
    __syncthreads();
    if (tid < 36) {
        float acc = b2[tid];
        for (int k = 0; k < 1536; k++) acc += sh[k] * w2[k * 36 + tid];
        kz[tid] = acc;
    } else if (tid < 42) {
        int j = tid - 36;
        float acc = evb[j];
        for (int k = 0; k < D; k++) acc += smn[k] * evw[k * NS + j];
        ev[j] = acc;
    }
    __syncthreads();
    if (tid == 0) {
        float Kr[6][6];
        for (int s = 0; s < 6; s++) {
            float mx = kz[s * 6];
            for (int u = 1; u < 6; u++) mx = fmaxf(mx, kz[s * 6 + u]);
            float sum = 0.f;
            for (int u = 0; u < 6; u++) { float e = expf(kz[s * 6 + u] - mx); Kr[s][u] = e; sum += e; }
            float invr = 1.f / sum;
            for (int u = 0; u < 6; u++) Kr[s][u] *= invr;
        }
        float pev[6];
        for (int u = 0; u < 6; u++) {
            float a = 0.f;
            for (int s = 0; s < 6; s++) a += spi[s] * Kr[s][u];
            pev[u] = a;
        }
        float mx = ev[0] * 2.f;
        for (int u = 1; u < 6; u++) mx = fmaxf(mx, ev[u] * 2.f);
        float wv[6], sw = 0.f;
        for (int u = 0; u < 6; u++) { wv[u] = expf(ev[u] * 2.f - mx); sw += wv[u]; }
        float invw = 1.f / sw;
        float pn[6], s1 = 0.f;
        for (int u = 0; u < 6; u++) { pn[u] = pev[u] * wv[u] * invw; s1 += pn[u]; }
        float inv1 = 1.f / fmaxf(s1, 1e-8f);
        for (int u = 0; u < 6; u++) pn[u] *= inv1;
        int i1 = 0;
        for (int u = 1; u < 6; u++) if (pn[u] > pn[i1]) i1 = u;
        int i2 = (i1 == 0) ? 1 : 0;
        for (int u = 0; u < 6; u++) if (u != i1 && pn[u] > pn[i2]) i2 = u;
        float inv2 = 1.f / fmaxf(pn[i1] + pn[i2], 1e-8f);
        for (int u = 0; u < 6; u++)
            pi[n * NS + u] = (u == i1 || u == i2) ? pn[u] * inv2 : 0.f;
    }
}

__global__ void attn_k(const float* __restrict__ q, const float* __restrict__ k,
                       const float* __restrict__ v, const float* __restrict__ pi,
                       const float* __restrict__ ln_g, const float* __restrict__ ln_b,
                       float* __restrict__ msghi, float* __restrict__ msglo)
{
    __shared__ float sw[4];
    __shared__ float mb[D];
    __shared__ float red[8];
    int n = blockIdx.x, tid = threadIdx.x;
    int t = n % TSEQ;
    int warp = tid >> 5, lane = tid & 31;
    const int offs[4] = {-2, -1, 1, 2};
    {
        int o = offs[warp];
        int tt = t + o;
        float dot = 0.f;
        if (tt >= 0 && tt < TSEQ) {
            const float* qp = q + (long)n * D;
            const float* kp = k + (long)(n + o) * D;
            for (int j = lane; j < D; j += 32) dot += qp[j] * kp[j];
        }
#pragma unroll
        for (int s = 16; s > 0; s >>= 1) dot += __shfl_xor_sync(0xffffffffu, dot, s);
        if (lane == 0)
            sw[warp] = (tt >= 0 && tt < TSEQ) ? dot / 27.712812921102035f : -1e9f;
    }
    __syncthreads();
    float w0 = sw[0], w1 = sw[1], w2 = sw[2], w3 = sw[3];
    float mx = fmaxf(fmaxf(w0, w1), fmaxf(w2, w3));
    float wt[4] = {expf(w0 - mx), expf(w1 - mx), expf(w2 - mx), expf(w3 - mx)};
    float invs = 1.f / (wt[0] + wt[1] + wt[2] + wt[3]);
#pragma unroll
    for (int w = 0; w < 4; w++) wt[w] *= invs;
    float pi3 = pi[n * NS + 3];
    for (int j = tid; j < D; j += 128) {
        float m = 0.f;
#pragma unroll
        for (int w = 0; w < 4; w++) {
            int tt = t + offs[w];
            if (tt >= 0 && tt < TSEQ) m += wt[w] * v[(long)(n + offs[w]) * D + j];
        }
        mb[j] = m * pi3;
    }
    __syncthreads();
    float loc[6], s = 0.f;
#pragma unroll
    for (int r = 0; r < 6; r++) { loc[r] = mb[tid + r * 128]; s += loc[r]; }
    float mean = block_sum(s, red) / D;
    float qv = 0.f;
#pragma unroll
    for (int r = 0; r < 6; r++) { float d = loc[r] - mean; qv += d * d; }
    float var = block_sum(qv, red) / D;
    float inv = rsqrtf(var + 1e-5f);
#pragma unroll
    for (int r = 0; r < 6; r++) {
        int j = tid + r * 128;
        float val = (loc[r] - mean) * inv * ln_g[3 * D + j] + ln_b[3 * D + j];
        float hf, lf;
        cvt_split(val, hf, lf);
        long idx = (long)n * D + j;
        msghi[idx] = hf;
        msglo[idx] = lf;
    }
}

__global__ void update_k(const float* __restrict__ muhat, float* __restrict__ lam,
                         const float* __restrict__ dlam, const float* __restrict__ mhat,
                         const float* __restrict__ so,
                         const float* __restrict__ ln_g, const float* __restrict__ ln_b,
                         float* __restrict__ mu,
                         float* __restrict__ muhi, float* __restrict__ mulo)
{
    __shared__ float red[8];
    int n = blockIdx.x, tid = threadIdx.x;
    float mval[3], s = 0.f;
#pragma unroll
    for (int r = 0; r < 3; r++) {
        int j = tid + r * 256;
        long idx = (long)n * D + j;
        float l = lam[idx], dl = dlam[idx];
        float mwn = muhat[idx] * ln_g[4 * D + j] + ln_b[4 * D + j];
        float lnw = l + dl;
        float m = (l * mwn + dl * mhat[idx]) / lnw;
        lam[idx] = lnw;
        mval[r] = m;
        s += m;
    }
    float mean = block_sum(s, red) / D;
    float qv = 0.f;
#pragma unroll
    for (int r = 0; r < 3; r++) { float d = mval[r] - mean; qv += d * d; }
    float var = block_sum(qv, red) / D;
    float inv = rsqrtf(var + 1e-5f);
#pragma unroll
    for (int r = 0; r < 3; r++) {
        int j = tid + r * 256;
        long idx = (long)n * D + j;
        float val = (mval[r] - mean) * inv * ln_g[5 * D + j] + ln_b[5 * D + j] + so[idx] * 0.1f;
        mu[idx] = val;
        float hf, lf;
        cvt_split(val, hf, lf);
        muhi[idx] = hf;
        mulo[idx] = lf;
    }
}

// ---------------- launcher ----------------
extern "C" void kernel_launch(void* const* d_in, const int* in_sizes, int n_in,
                              void* d_out, int out_size)
{
    const int*   x        = (const int*)d_in[0];
    const float* emb_w    = (const float*)d_in[1];
    const float* pos_w    = (const float*)d_in[2];
    const float* mu_w     = (const float*)d_in[3];
    const float* mu_b     = (const float*)d_in[4];
    const float* lam_w    = (const float*)d_in[5];
    const float* lam_b    = (const float*)d_in[6];
    const float* tr_w1    = (const float*)d_in[7];
    const float* tr_b1    = (const float*)d_in[8];
    const float* tr_w2    = (const float*)d_in[9];
    const float* tr_b2    = (const float*)d_in[10];
    const float* bank_w1  = (const float*)d_in[11];
    const float* bank_b1  = (const float*)d_in[12];
    const float* bank_w2  = (const float*)d_in[13];
    const float* bank_b2  = (const float*)d_in[14];
    const float* ev_w     = (const float*)d_in[15];
    const float* ev_b     = (const float*)d_in[16];
    const float* rt_q     = (const float*)d_in[17];
    const float* rt_k     = (const float*)d_in[18];
    const float* rt_v     = (const float*)d_in[19];
    const float* wr_lam_w = (const float*)d_in[20];
    const float* wr_lam_b = (const float*)d_in[21];
    const float* wr_mu_w  = (const float*)d_in[22];
    const float* wr_mu_b  = (const float*)d_in[23];
    const float* ln_g     = (const float*)d_in[24];
    const float* ln_b     = (const float*)d_in[25];
    float* out = (float*)d_out;

    cudaFuncSetAttribute(tgemm_k<EPI_GELU>, cudaFuncAttributeMaxDynamicSharedMemorySize, SM_BYTES);
    cudaFuncSetAttribute(tgemm_k<EPI_SCALE>, cudaFuncAttributeMaxDynamicSharedMemorySize, SM_BYTES);
    cudaFuncSetAttribute(tgemm_pair_k<EPI_BIAS, EPI_SP01, true>, cudaFuncAttributeMaxDynamicSharedMemorySize, SM_BYTES);
    cudaFuncSetAttribute(tgemm_pair_k<EPI_GSP, EPI_BIAS, false>, cudaFuncAttributeMaxDynamicSharedMemorySize, SM_BYTES);
    cudaFuncSetAttribute(tqkv_k, cudaFuncAttributeMaxDynamicSharedMemorySize, SM_BYTES);
    cudaFuncSetAttribute(tbank1_k, cudaFuncAttributeMaxDynamicSharedMemorySize, SM_BYTES);
    cudaFuncSetAttribute(tbank2_k<0>, cudaFuncAttributeMaxDynamicSharedMemorySize, SM_BYTES);
    cudaFuncSetAttribute(tbank2_k<1>, cudaFuncAttributeMaxDynamicSharedMemorySize, SM_BYTES);

    float* base = nullptr;
    cudaGetSymbolAddress((void**)&base, g_scratch);
    float *ahi = nullptr, *alo = nullptr;
    cudaGetSymbolAddress((void**)&ahi, g_ahi);
    cudaGetSymbolAddress((void**)&alo, g_alo);
    float *whi = nullptr, *wlo = nullptr;
    cudaGetSymbolAddress((void**)&whi, g_whi);
    cudaGetSymbolAddress((void**)&wlo, g_wlo);
    int *cnt, *list, *cnt2, *slot2, *tok2;
    cudaGetSymbolAddress((void**)&cnt, g_cnt);
    cudaGetSymbolAddress((void**)&list, g_list);
    cudaGetSymbolAddress((void**)&cnt2, g_cnt2);
    cudaGetSymbolAddress((void**)&slot2, g_slot2);
    cudaGetSymbolAddress((void**)&tok2, g_tok2);

    float* mu    = base + OFF_MU;
    float* lam   = base + OFF_LAM;
    float* muhat = base + OFF_MUHAT;
    float* mun   = base + OFF_MUN;
    float* so    = base + OFF_SO;
    float* qb    = base + OFF_Q;
    float* dlam  = base + OFF_DLAM;
    float* mhat  = base + OFF_MHAT;
    float* trh   = base + OFF_TRH;
    float* pi    = base + OFF_PI;

    const float inv_sqrt_d = 0.03608439182435161f;

    // ---- weight prep ----
    {
        const int DD4 = D * D / 4;
        split_k<<<(DD4 + 255) / 256, 256>>>(mu_w,     whi + W_MU,  wlo + W_MU,  DD4);
        split_k<<<(DD4 + 255) / 256, 256>>>(lam_w,    whi + W_LAM, wlo + W_LAM, DD4);
        split_k<<<(D * 1536 / 4 + 255) / 256, 256>>>(tr_w1, whi + W_TR1, wlo + W_TR1, D * 1536 / 4);
        split_k<<<(DD4 + 255) / 256, 256>>>(rt_q,     whi + W_RTQ, wlo + W_RTQ, DD4);
        split_k<<<(DD4 + 255) / 256, 256>>>(rt_k,     whi + W_RTK, wlo + W_RTK, DD4);
        split_k<<<(DD4 + 255) / 256, 256>>>(rt_v,     whi + W_RTV, wlo + W_RTV, DD4);
        split_k<<<(DD4 + 255) / 256, 256>>>(wr_lam_w, whi + W_WRL, wlo + W_WRL, DD4);
        split_k<<<(DD4 + 255) / 256, 256>>>(wr_mu_w,  whi + W_WRM, wlo + W_WRM, DD4);
        const int B14 = NS * D * FFN / 4;
        split_k<<<(B14 + 255) / 256, 256>>>(bank_w1, whi + W_B1, wlo + W_B1, B14);
        split_k<<<(B14 + 255) / 256, 256>>>(bank_w2, whi + W_B2, wlo + W_B2, B14);
        dim3 gt(VOC / 32, D / 32);
        tsplit_emb_k<<<gt, dim3(32, 8)>>>(emb_w, whi + W_EMBT, wlo + W_EMBT);
    }

    emb_k<<<NTOK, 256>>>(x, emb_w, pos_w, ahi + S_H, alo + S_H);
    {
        dim3 g(D / 128, NTOK / 128, 2);
        tgemm_pair_k<EPI_BIAS, EPI_SP01, true><<<g, 256, SM_BYTES>>>(
            ahi + S_H, alo + S_H, whi + W_MU, wlo + W_MU,
            mu_b, lam_b, nullptr, mu, ahi + S_MU, alo + S_MU);
    }
    pi_init_k<<<(NTOK * NS + 255) / 256, 256>>>(pi);

    for (int step = 0; step < 3; step++) {
        ln012_k<<<NTOK, 256>>>(mu, muhat, mun, ahi + S_MUN, alo + S_MUN,
                               ahi + S_MUR, alo + S_MUR, ln_g, ln_b);
        {
            dim3 g(1536 / 128, NTOK / 128);
            tgemm_k<EPI_GELU><<<g, 256, SM_BYTES>>>(
                ahi + S_MU, alo + S_MU, whi + W_TR1, wlo + W_TR1,
                tr_b1, trh, 1536, D, 1.f);
        }
        reset_cnt_k<<<1, 32>>>(cnt, cnt2);
        build_lists_k<<<NTOK / 256, 256>>>(pi, cnt, list, cnt2, slot2, tok2);
        {
            dim3 g1(FFN / 128, NTOK / 128, NS);
            tbank1_k<<<g1, 256, SM_BYTES>>>(ahi + S_MUN, alo + S_MUN,
                                            whi + W_B1, wlo + W_B1, bank_b1,
                                            ahi + S_HB, alo + S_HB, list, cnt);
            dim3 g2(D / 128, NTOK / 128, NS);
            tbank2_k<0><<<g2, 256, SM_BYTES>>>(ahi + S_HB, alo + S_HB,
                                               whi + W_B2, wlo + W_B2, bank_b2,
                                               so, cnt2, slot2, tok2, pi);
            tbank2_k<1><<<g2, 256, SM_BYTES>>>(ahi + S_HB, alo + S_HB,
                                               whi + W_B2, wlo + W_B2, bank_b2,
                                               so, cnt2, slot2, tok2, pi);
        }
        ln_gen_k<<<NTOK, 256>>>(so, so, ln_g + 1 * D, ln_b + 1 * D);
        routing_k<<<NTOK, 128>>>(trh, tr_w2, tr_b2, mun, ev_w, ev_b, pi);
        {
            dim3 g(D / 128, NTOK / 128, 3);
            tqkv_k<<<g, 256, SM_BYTES>>>(ahi + S_MUR, alo + S_MUR,
                                         whi + W_RTQ, wlo + W_RTQ, qb);
        }
        attn_k<<<NTOK, 128>>>(qb, qb + ROW, qb + 2 * ROW, pi, ln_g, ln_b,
                              ahi + S_MSG, alo + S_MSG);
        {
            dim3 g(D / 128, NTOK / 128, 2);
            tgemm_pair_k<EPI_GSP, EPI_BIAS, false><<<g, 256, SM_BYTES>>>(
                ahi + S_MSG, alo + S_MSG, whi + W_WRL, wlo + W_WRL,
                wr_lam_b, wr_mu_b, pi, dlam, nullptr, nullptr);
        }
        update_k<<<NTOK, 256>>>(muhat, lam, dlam, mhat, so, ln_g, ln_b, mu,
                                ahi + S_MU, alo + S_MU);
    }

    ln_split_k<<<NTOK, 256>>>(mu, ahi + S_FIN, alo + S_FIN, ln_g + 6 * D, ln_b + 6 * D);
    {
        dim3 g(VOC / 128, NTOK / 128);
        tgemm_k<EPI_SCALE><<<g, 256, SM_BYTES>>>(
            ahi + S_FIN, alo + S_FIN, whi + W_EMBT, wlo + W_EMBT,
            nullptr, out, VOC, D, inv_sqrt_d);
    }
}

// round 10
// speedup vs baseline: 1.1962x; 1.1962x over previous
#include <cuda_runtime.h>
#include <math.h>
#include <stdint.h>

#define NTOK 2048
#define TSEQ 1024
#define D    768
#define FFN  3072
#define NS   6
#define VOC  32000

// ---------------- scratch ----------------
#define ROW (NTOK*D)
#define OFF_H     0
#define OFF_MU    (1*ROW)
#define OFF_LAM   (2*ROW)
#define OFF_MUHAT (3*ROW)
#define OFF_MUN   (4*ROW)
#define OFF_MUR   (5*ROW)
#define OFF_SO    (6*ROW)
#define OFF_Q     (7*ROW)
#define OFF_K     (8*ROW)
#define OFF_V     (9*ROW)
#define OFF_MSG   (10*ROW)
#define OFF_DLAM  (11*ROW)
#define OFF_MHAT  (12*ROW)
#define OFF_FIN   (13*ROW)
#define OFF_TRH   (14*ROW)
#define OFF_HB    (14*ROW + NTOK*1536)
#define OFF_PI    (OFF_HB + NS*NTOK*FFN)
#define SCRATCH_FLOATS (OFF_PI + NTOK*NS)

__device__ float g_scratch[SCRATCH_FLOATS];
__device__ int   g_cnt[NS];
__device__ int   g_list[NS * NTOK];
__device__ int   g_cnt2[2 * NS];
__device__ int   g_slot2[2 * NS * NTOK];
__device__ int   g_tok2[2 * NS * NTOK];

// ---------------- pre-split weight arena (hi/lo tf32 split) ----------------
#define W_MU   0
#define W_LAM  589824
#define W_TR1  1179648
#define W_RTQ  2359296
#define W_RTK  2949120
#define W_RTV  3538944
#define W_WRL  4128768
#define W_WRM  4718592
#define W_B1   5308416
#define W_B2   19464192
#define W_EMBT 33619968
#define WSPLIT 58195968

__device__ float g_whi[WSPLIT];
__device__ float g_wlo[WSPLIT];

// ---------------- helpers ----------------
__device__ __forceinline__ float gelu_f(float x) {
    float x3 = x * x * x;
    return 0.5f * x * (1.f + tanhf(0.7978845608028654f * (x + 0.044715f * x3)));
}
__device__ __forceinline__ float softplus_f(float x) {
    return fmaxf(x, 0.f) + log1pf(expf(-fabsf(x)));
}
__device__ __forceinline__ float block_sum(float v, float* red) {
    int tid = threadIdx.x;
    __syncthreads();
#pragma unroll
    for (int o = 16; o > 0; o >>= 1) v += __shfl_xor_sync(0xffffffffu, v, o);
    if ((tid & 31) == 0) red[tid >> 5] = v;
    __syncthreads();
    if (tid < 32) {
        float t = (tid < (int)(blockDim.x >> 5)) ? red[tid] : 0.f;
#pragma unroll
        for (int o = 4; o > 0; o >>= 1) t += __shfl_xor_sync(0xffffffffu, t, o);
        if (tid == 0) red[0] = t;
    }
    __syncthreads();
    return red[0];
}

__device__ __forceinline__ void cvt_split(float x, float& hi, float& lo) {
    uint32_t hb; asm("cvt.rna.tf32.f32 %0, %1;" : "=r"(hb) : "f"(x));
    hi = __uint_as_float(hb);
    float lf = x - hi;
    uint32_t lb; asm("cvt.rna.tf32.f32 %0, %1;" : "=r"(lb) : "f"(lf));
    lo = __uint_as_float(lb);
}

// ---------------- weight prep kernels ----------------
__global__ void split_k(const float* __restrict__ src, float* __restrict__ hi,
                        float* __restrict__ lo, int n4)
{
    int i = blockIdx.x * blockDim.x + threadIdx.x;
    if (i >= n4) return;
    float4 v = ((const float4*)src)[i];
    float4 h, l;
    cvt_split(v.x, h.x, l.x); cvt_split(v.y, h.y, l.y);
    cvt_split(v.z, h.z, l.z); cvt_split(v.w, h.w, l.w);
    ((float4*)hi)[i] = h;
    ((float4*)lo)[i] = l;
}

// transpose emb_w [VOC][D] -> split into [D][VOC] hi/lo
__global__ void tsplit_emb_k(const float* __restrict__ emb,
                             float* __restrict__ hi, float* __restrict__ lo)
{
    __shared__ float tile[32][33];
    int v0 = blockIdx.x * 32, d0 = blockIdx.y * 32;
    int tx = threadIdx.x, ty = threadIdx.y; // 32 x 8
    for (int r = ty; r < 32; r += 8)
        tile[r][tx] = emb[(long)(v0 + r) * D + d0 + tx];
    __syncthreads();
    for (int r = ty; r < 32; r += 8) {
        float hf, lf;
        cvt_split(tile[tx][r], hf, lf);
        long o = (long)(d0 + r) * VOC + v0 + tx;
        hi[o] = hf;
        lo[o] = lf;
    }
}

// ---------------- tf32 mma core ----------------
// smem (float offsets): RAWA[3][128][20] @0 (7680),
// BHI[3][16][136] @7680 (6528), BLO[3][16][136] @14208 (6528)
// total 20736 floats = 82944 B -> 2 CTAs/SM
#define A_ST    2560
#define B_STF   2176
#define SM_RAWA 0
#define SM_BHI  7680
#define SM_BLO  14208
#define SM_BYTES (20736 * 4)

__device__ __forceinline__ void mma8(float* c, const uint32_t* a, uint32_t b0, uint32_t b1) {
    asm volatile(
        "mma.sync.aligned.m16n8k8.row.col.f32.tf32.tf32.f32 "
        "{%0,%1,%2,%3},{%4,%5,%6,%7},{%8,%9},{%0,%1,%2,%3};"
        : "+f"(c[0]), "+f"(c[1]), "+f"(c[2]), "+f"(c[3])
        : "r"(a[0]), "r"(a[1]), "r"(a[2]), "r"(a[3]), "r"(b0), "r"(b1));
}

__device__ __forceinline__ void cp16(uint32_t dst, const float* src) {
    asm volatile("cp.async.ca.shared.global [%0], [%1], 16;" :: "r"(dst), "l"(src) : "memory");
}

// block 128x128, 8 warps (4m x 2n), warp tile 32x64, BK=16.
// Raw A (fp32, read ONCE from gmem) + pre-split B, 3-stage rings, ONE barrier
// per slice. A's hi/lo split happens inline in comp (registers) — overlaps the
// tensor pipe. issue(i+2) sits after barrier(i); stage (i+2)%3's previous
// readers comp(i-1) finished before barrier(i) -> no WAR race.
template <bool GATHER>
__device__ __forceinline__ void tf32_loop(
    const float* __restrict__ A, const float* __restrict__ Bhi,
    const float* __restrict__ Blo,
    int K, int N, int bm0, int bn0, const int* __restrict__ rowTok,
    float* __restrict__ sm, float c[2][8][4])
{
    const int tid = threadIdx.x;
    const int lane = tid & 31, warp = tid >> 5;
    const int wm0 = (warp >> 1) * 32, wn0 = (warp & 1) * 64;
    const int g = lane >> 2, tig = lane & 3;

    const int arow0 = tid >> 2, arow1 = arow0 + 64, aq = tid & 3;
    long agr0, agr1;
    if (GATHER) { agr0 = rowTok[arow0]; agr1 = rowTok[arow1]; }
    else        { agr0 = bm0 + arow0;   agr1 = bm0 + arow1;   }
    const int bkr = tid >> 5;
    const int bn4 = (tid & 31) * 4;

    const uint32_t smb = (uint32_t)__cvta_generic_to_shared(sm);

    auto issue = [&](int st, int k0) {
        uint32_t ra = smb + (uint32_t)(SM_RAWA + st * A_ST) * 4u;
        cp16(ra + (uint32_t)(arow0 * 20 + aq * 4) * 4u, A + agr0 * K + k0 + aq * 4);
        cp16(ra + (uint32_t)(arow1 * 20 + aq * 4) * 4u, A + agr1 * K + k0 + aq * 4);
        uint32_t bh = smb + (uint32_t)(SM_BHI + st * B_STF) * 4u;
        uint32_t bl = smb + (uint32_t)(SM_BLO + st * B_STF) * 4u;
        cp16(bh + (uint32_t)(bkr * 136 + bn4) * 4u,
             Bhi + (long)(k0 + bkr) * N + bn0 + bn4);
        cp16(bh + (uint32_t)((bkr + 8) * 136 + bn4) * 4u,
             Bhi + (long)(k0 + bkr + 8) * N + bn0 + bn4);
        cp16(bl + (uint32_t)(bkr * 136 + bn4) * 4u,
             Blo + (long)(k0 + bkr) * N + bn0 + bn4);
        cp16(bl + (uint32_t)((bkr + 8) * 136 + bn4) * 4u,
             Blo + (long)(k0 + bkr + 8) * N + bn0 + bn4);
        asm volatile("cp.async.commit_group;" ::: "memory");
    };

    auto comp = [&](int st) {
        const float* rap = sm + SM_RAWA + st * A_ST;
        const float* bhp = sm + SM_BHI + st * B_STF;
        const float* blp = sm + SM_BLO + st * B_STF;
#pragma unroll
        for (int ks = 0; ks < 16; ks += 8) {
            uint32_t ah[2][4], al[2][4];
#pragma unroll
            for (int mt = 0; mt < 2; mt++) {
                int rb = wm0 + mt * 16 + g;
                float r0 = rap[rb * 20 + ks + tig];
                float r1 = rap[(rb + 8) * 20 + ks + tig];
                float r2 = rap[rb * 20 + ks + tig + 4];
                float r3 = rap[(rb + 8) * 20 + ks + tig + 4];
                float hf, lf;
                cvt_split(r0, hf, lf); ah[mt][0] = __float_as_uint(hf); al[mt][0] = __float_as_uint(lf);
                cvt_split(r1, hf, lf); ah[mt][1] = __float_as_uint(hf); al[mt][1] = __float_as_uint(lf);
                cvt_split(r2, hf, lf); ah[mt][2] = __float_as_uint(hf); al[mt][2] = __float_as_uint(lf);
                cvt_split(r3, hf, lf); ah[mt][3] = __float_as_uint(hf); al[mt][3] = __float_as_uint(lf);
            }
#pragma unroll
            for (int nt = 0; nt < 8; nt++) {
                int cb = wn0 + nt * 8 + g;
                uint32_t bh0 = __float_as_uint(bhp[(ks + tig) * 136 + cb]);
                uint32_t bh1 = __float_as_uint(bhp[(ks + tig + 4) * 136 + cb]);
                uint32_t bl0 = __float_as_uint(blp[(ks + tig) * 136 + cb]);
                uint32_t bl1 = __float_as_uint(blp[(ks + tig + 4) * 136 + cb]);
#pragma unroll
                for (int mt = 0; mt < 2; mt++) {
                    mma8(c[mt][nt], ah[mt], bh0, bh1);
                    mma8(c[mt][nt], ah[mt], bl0, bl1);
                    mma8(c[mt][nt], al[mt], bh0, bh1);
                }
            }
        }
    };

    const int nk = K >> 4;  // >= 48 at all call sites
    issue(0, 0);
    issue(1, 16);
    int st = 0, stn = 2;
    for (int i = 0; i < nk; i++) {
        if (i < nk - 1) asm volatile("cp.async.wait_group 1;" ::: "memory");
        else            asm volatile("cp.async.wait_group 0;" ::: "memory");
        __syncthreads();
        if (i + 2 < nk) {
            issue(stn, (i + 2) << 4);
            stn = (stn == 2) ? 0 : stn + 1;
        }
        comp(st);
        st = (st == 2) ? 0 : st + 1;
    }
}

// ---------------- epilogues ----------------
enum { EPI_NONE = 0, EPI_BIAS = 1, EPI_GELU = 2, EPI_GSP = 3, EPI_SCALE = 4, EPI_SP01 = 5 };

template <int EPI>
__device__ __forceinline__ float epi_apply(float v, float b, float rs, float alpha) {
    if (EPI == EPI_BIAS)  return v + b;
    if (EPI == EPI_GELU)  return gelu_f(v + b);
    if (EPI == EPI_GSP)   return rs * softplus_f(v + b);
    if (EPI == EPI_SCALE) return v * alpha;
    if (EPI == EPI_SP01)  return softplus_f(v + b) + 0.1f;
    return v;
}

template <int EPI>
__device__ __forceinline__ void epi_store_dense(
    float c[2][8][4], float* __restrict__ C, const float* __restrict__ bias,
    int N, int bm0, int bn0, const float* __restrict__ pi, float alpha)
{
    const int tid = threadIdx.x, lane = tid & 31, warp = tid >> 5;
    const int wm0 = (warp >> 1) * 32, wn0 = (warp & 1) * 64;
    const int g = lane >> 2, tig = lane & 3;
    const int colbase = bn0 + wn0;
#pragma unroll
    for (int mt = 0; mt < 2; mt++) {
#pragma unroll
        for (int half = 0; half < 2; half++) {
            int row = bm0 + wm0 + mt * 16 + g + half * 8;
            float rs = (EPI == EPI_GSP) ? pi[row * NS + 4] : 0.f;
            float* cp = C + (long)row * N + colbase;
#pragma unroll
            for (int nt = 0; nt < 8; nt++) {
                int col = nt * 8 + tig * 2;
                float b0 = 0.f, b1 = 0.f;
                if (EPI == EPI_BIAS || EPI == EPI_GELU || EPI == EPI_GSP || EPI == EPI_SP01) {
                    b0 = bias[colbase + col];
                    b1 = bias[colbase + col + 1];
                }
                float v0 = epi_apply<EPI>(c[mt][nt][half * 2], b0, rs, alpha);
                float v1 = epi_apply<EPI>(c[mt][nt][half * 2 + 1], b1, rs, alpha);
                *(float2*)(cp + col) = make_float2(v0, v1);
            }
        }
    }
}

// ---------------- GEMM kernels ----------------
template <int EPI>
__global__ void __launch_bounds__(256, 2) tgemm_k(
    const float* __restrict__ A, const float* __restrict__ Bhi,
    const float* __restrict__ Blo, const float* __restrict__ bias,
    float* __restrict__ C, int N, int K, float alpha,
    const float* __restrict__ pi)
{
    extern __shared__ float sm[];
    const int bm0 = blockIdx.y * 128, bn0 = blockIdx.x * 128;
    float c[2][8][4];
#pragma unroll
    for (int a = 0; a < 2; a++)
#pragma unroll
        for (int b = 0; b < 8; b++)
#pragma unroll
            for (int r = 0; r < 4; r++) c[a][b][r] = 0.f;
    tf32_loop<false>(A, Bhi, Blo, K, N, bm0, bn0, nullptr, sm, c);
    epi_store_dense<EPI>(c, C, bias, N, bm0, bn0, pi, alpha);
}

// z-pair over adjacent arena weights (stride D*D)
template <int EPI0, int EPI1>
__global__ void __launch_bounds__(256, 2) tgemm_pair_k(
    const float* __restrict__ A, const float* __restrict__ Whi,
    const float* __restrict__ Wlo, const float* __restrict__ b0,
    const float* __restrict__ b1, const float* __restrict__ pi,
    float* __restrict__ Cbase)
{
    extern __shared__ float sm[];
    const int z = blockIdx.z;
    const float* Bhi = Whi + (long)z * D * D;
    const float* Blo = Wlo + (long)z * D * D;
    const float* bias = z ? b1 : b0;
    float* C = Cbase + (long)z * ROW;
    const int bm0 = blockIdx.y * 128, bn0 = blockIdx.x * 128;
    float c[2][8][4];
#pragma unroll
    for (int a = 0; a < 2; a++)
#pragma unroll
        for (int b = 0; b < 8; b++)
#pragma unroll
            for (int r = 0; r < 4; r++) c[a][b][r] = 0.f;
    tf32_loop<false>(A, Bhi, Blo, D, D, bm0, bn0, nullptr, sm, c);
    if (z == 0) epi_store_dense<EPI0>(c, C, bias, D, bm0, bn0, pi, 1.f);
    else        epi_store_dense<EPI1>(c, C, bias, D, bm0, bn0, pi, 1.f);
}

__global__ void __launch_bounds__(256, 2) tqkv_k(
    const float* __restrict__ A, const float* __restrict__ Whi,
    const float* __restrict__ Wlo, float* __restrict__ Cbase)
{
    extern __shared__ float sm[];
    const int z = blockIdx.z;
    const float* Bhi = Whi + (long)z * D * D;
    const float* Blo = Wlo + (long)z * D * D;
    float* C = Cbase + (long)z * ROW;
    const int bm0 = blockIdx.y * 128, bn0 = blockIdx.x * 128;
    float c[2][8][4];
#pragma unroll
    for (int a = 0; a < 2; a++)
#pragma unroll
        for (int b = 0; b < 8; b++)
#pragma unroll
            for (int r = 0; r < 4; r++) c[a][b][r] = 0.f;
    tf32_loop<false>(A, Bhi, Blo, D, D, bm0, bn0, nullptr, sm, c);
    epi_store_dense<EPI_NONE>(c, C, nullptr, D, bm0, bn0, nullptr, 1.f);
}

__global__ void __launch_bounds__(256, 2) tbank1_k(
    const float* __restrict__ A, const float* __restrict__ Whi,
    const float* __restrict__ Wlo, const float* __restrict__ b1all,
    float* __restrict__ hb, const int* __restrict__ list,
    const int* __restrict__ cnt)
{
    extern __shared__ float sm[];
    __shared__ int rowTok[128];
    const int s = blockIdx.z;
    const int cn = cnt[s];
    const int bm0 = blockIdx.y * 128;
    if (bm0 >= cn) return;
    const int tid = threadIdx.x;
    if (tid < 128) rowTok[tid] = list[s * NTOK + min(bm0 + tid, cn - 1)];
    __syncthreads();

    const float* Bhi = Whi + (long)s * D * FFN;
    const float* Blo = Wlo + (long)s * D * FFN;
    const float* bias = b1all + s * FFN;
    float* C = hb + (long)s * NTOK * FFN;
    const int bn0 = blockIdx.x * 128;

    float c[2][8][4];
#pragma unroll
    for (int a = 0; a < 2; a++)
#pragma unroll
        for (int b = 0; b < 8; b++)
#pragma unroll
            for (int r = 0; r < 4; r++) c[a][b][r] = 0.f;
    tf32_loop<true>(A, Bhi, Blo, D, FFN, 0, bn0, rowTok, sm, c);

    const int lane = tid & 31, warp = tid >> 5;
    const int wm0 = (warp >> 1) * 32, wn0 = (warp & 1) * 64;
    const int g = lane >> 2, tig = lane & 3;
    const int colbase = bn0 + wn0;
#pragma unroll
    for (int mt = 0; mt < 2; mt++) {
#pragma unroll
        for (int half = 0; half < 2; half++) {
            int slot = bm0 + wm0 + mt * 16 + g + half * 8;
            if (slot >= cn) continue;
            float* cp = C + (long)slot * FFN + colbase;
#pragma unroll
            for (int nt = 0; nt < 8; nt++) {
                int col = nt * 8 + tig * 2;
                float v0 = gelu_f(c[mt][nt][half * 2] + bias[colbase + col]);
                float v1 = gelu_f(c[mt][nt][half * 2 + 1] + bias[colbase + col + 1]);
                *(float2*)(cp + col) = make_float2(v0, v1);
            }
        }
    }
}

template <int RANK>
__global__ void __launch_bounds__(256, 2) tbank2_k(
    const float* __restrict__ hb, const float* __restrict__ Whi,
    const float* __restrict__ Wlo, const float* __restrict__ b2all,
    float* __restrict__ so, const int* __restrict__ cnt2,
    const int* __restrict__ slot2, const int* __restrict__ tok2,
    const float* __restrict__ pi)
{
    extern __shared__ float sm[];
    __shared__ int rowSlot[128];
    const int s = blockIdx.z;
    const int cn = cnt2[RANK * NS + s];
    const int bm0 = blockIdx.y * 128;
    if (bm0 >= cn) return;
    const int tid = threadIdx.x;
    const int lbase = (RANK * NS + s) * NTOK;
    if (tid < 128) rowSlot[tid] = slot2[lbase + min(bm0 + tid, cn - 1)];
    __syncthreads();

    const float* A = hb + (long)s * NTOK * FFN;
    const float* Bhi = Whi + (long)s * FFN * D;
    const float* Blo = Wlo + (long)s * FFN * D;
    const float* bias = b2all + s * D;
    const int bn0 = blockIdx.x * 128;

    float c[2][8][4];
#pragma unroll
    for (int a = 0; a < 2; a++)
#pragma unroll
        for (int b = 0; b < 8; b++)
#pragma unroll
            for (int r = 0; r < 4; r++) c[a][b][r] = 0.f;
    tf32_loop<true>(A, Bhi, Blo, FFN, D, 0, bn0, rowSlot, sm, c);

    const int lane = tid & 31, warp = tid >> 5;
    const int wm0 = (warp >> 1) * 32, wn0 = (warp & 1) * 64;
    const int g = lane >> 2, tig = lane & 3;
    const int colbase = bn0 + wn0;
#pragma unroll
    for (int mt = 0; mt < 2; mt++) {
#pragma unroll
        for (int half = 0; half < 2; half++) {
            int idx = bm0 + wm0 + mt * 16 + g + half * 8;
            if (idx >= cn) continue;
            int tok = tok2[lbase + idx];
            float rs = pi[tok * NS + s];
            float* cp = so + (long)tok * D + colbase;
#pragma unroll
            for (int nt = 0; nt < 8; nt++) {
                int col = nt * 8 + tig * 2;
                float v0 = rs * (c[mt][nt][half * 2] + bias[colbase + col]);
                float v1 = rs * (c[mt][nt][half * 2 + 1] + bias[colbase + col + 1]);
                if (RANK == 0) {
                    *(float2*)(cp + col) = make_float2(v0, v1);
                } else {
                    float2 old = *(float2*)(cp + col);
                    *(float2*)(cp + col) = make_float2(old.x + v0, old.y + v1);
                }
            }
        }
    }
}

// ---------------- small kernels ----------------
__global__ void emb_k(const int* __restrict__ x, const float* __restrict__ emb,
                      const float* __restrict__ pos, float* __restrict__ h)
{
    int n = blockIdx.x;
    int vx = x[n];
    int t = n % TSEQ;
    const float* e = emb + (long)vx * D;
    const float* p = pos + (long)t * D;
    for (int j = threadIdx.x; j < D; j += blockDim.x)
        h[(long)n * D + j] = e[j] + p[j];
}

__global__ void pi_init_k(float* __restrict__ pi)
{
    int i = blockIdx.x * blockDim.x + threadIdx.x;
    if (i < NTOK * NS) pi[i] = ((i % NS) == 2) ? 1.f : 0.f;
}

__global__ void reset_cnt_k(int* cnt, int* cnt2)
{
    if (threadIdx.x < NS) cnt[threadIdx.x] = 0;
    if (threadIdx.x < 2 * NS) cnt2[threadIdx.x] = 0;
}

__global__ void build_lists_k(const float* __restrict__ pi,
                              int* __restrict__ cnt, int* __restrict__ list,
                              int* __restrict__ cnt2, int* __restrict__ slot2,
                              int* __restrict__ tok2)
{
    int t = blockIdx.x * blockDim.x + threadIdx.x;
    if (t >= NTOK) return;
    int r = 0;
#pragma unroll
    for (int s = 0; s < NS; s++) {
        if (pi[t * NS + s] != 0.f) {
            int p = atomicAdd(&cnt[s], 1);
            list[s * NTOK + p] = t;
            int rr = min(r, 1);
            int q = atomicAdd(&cnt2[rr * NS + s], 1);
            slot2[(rr * NS + s) * NTOK + q] = p;
            tok2[(rr * NS + s) * NTOK + q] = t;
            r++;
        }
    }
}

__global__ void ln012_k(const float* __restrict__ mu, float* __restrict__ muhat,
                        float* __restrict__ mun, float* __restrict__ mur,
                        const float* __restrict__ ln_g, const float* __restrict__ ln_b)
{
    __shared__ float red[8];
    int n = blockIdx.x, tid = threadIdx.x;
    const float* row = mu + (long)n * D;
    float v[3], s = 0.f;
#pragma unroll
    for (int r = 0; r < 3; r++) { v[r] = row[tid + r * 256]; s += v[r]; }
    float mean = block_sum(s, red) / D;
    float qv = 0.f;
#pragma unroll
    for (int r = 0; r < 3; r++) { float d = v[r] - mean; qv += d * d; }
    float var = block_sum(qv, red) / D;
    float inv = rsqrtf(var + 1e-5f);
#pragma unroll
    for (int r = 0; r < 3; r++) {
        int j = tid + r * 256;
        float nh = (v[r] - mean) * inv;
        long idx = (long)n * D + j;
        muhat[idx] = nh;
        mun[idx] = nh * ln_g[j] + ln_b[j];
        mur[idx] = nh * ln_g[2 * D + j] + ln_b[2 * D + j];
    }
}

__global__ void ln_gen_k(const float* __restrict__ in, float* __restrict__ out,
                         const float* __restrict__ g, const float* __restrict__ b)
{
    __shared__ float red[8];
    int n = blockIdx.x, tid = threadIdx.x;
    const float* row = in + (long)n * D;
    float v[3], s = 0.f;
#pragma unroll
    for (int r = 0; r < 3; r++) { v[r] = row[tid + r * 256]; s += v[r]; }
    float mean = block_sum(s, red) / D;
    float qv = 0.f;
#pragma unroll
    for (int r = 0; r < 3; r++) { float d = v[r] - mean; qv += d * d; }
    float var = block_sum(qv, red) / D;
    float inv = rsqrtf(var + 1e-5f);
#pragma unroll
    for (int r = 0; r < 3; r++) {
        int j = tid + r * 256;
        out[(long)n * D + j] = (v[r] - mean) * inv * g[j] + b[j];
    }
}

__global__ void routing_k(const float* __restrict__ trh, const float* __restrict__ w2,
                          const float* __restrict__ b2, const float* __restrict__ mun,
                          const float* __restrict__ evw, const float* __restrict__ evb,
                          float* __restrict__ pi)
{
    __shared__ float sh[1536];
    __shared__ float smn[D];
    __shared__ float kz[36];
    __shared__ float ev[6];
    __shared__ float spi[6];
    int n = blockIdx.x, tid = threadIdx.x;
    for (int i = tid; i < 1536; i += 128) sh[i] = trh[(long)n * 1536 + i];
    for (int i = tid; i < D; i += 128)    smn[i] = mun[(long)n * D + i];
    if (tid < NS) spi[tid] = pi[n * NS + tid];
    __syncthreads();
    if (tid < 36) {
        float acc = b2[tid];
        for (int k = 0; k < 1536; k++) acc += sh[k] * w2[k * 36 + tid];
        kz[tid] = acc;
    } else if (tid < 42) {
        int j = tid - 36;
        float acc = evb[j];
        for (int k = 0; k < D; k++) acc += smn[k] * evw[k * NS + j];
        ev[j] = acc;
    }
    __syncthreads();
    if (tid == 0) {
        float Kr[6][6];
        for (int s = 0; s < 6; s++) {
            float mx = kz[s * 6];
            for (int u = 1; u < 6; u++) mx = fmaxf(mx, kz[s * 6 + u]);
            float sum = 0.f;
            for (int u = 0; u < 6; u++) { float e = expf(kz[s * 6 + u] - mx); Kr[s][u] = e; sum += e; }
            float invr = 1.f / sum;
            for (int u = 0; u < 6; u++) Kr[s][u] *= invr;
        }
        float pev[6];
        for (int u = 0; u < 6; u++) {
            float a = 0.f;
            for (int s = 0; s < 6; s++) a += spi[s] * Kr[s][u];
            pev[u] = a;
        }
        float mx = ev[0] * 2.f;
        for (int u = 1; u < 6; u++) mx = fmaxf(mx, ev[u] * 2.f);
        float wv[6], sw = 0.f;
        for (int u = 0; u < 6; u++) { wv[u] = expf(ev[u] * 2.f - mx); sw += wv[u]; }
        float invw = 1.f / sw;
        float pn[6], s1 = 0.f;
        for (int u = 0; u < 6; u++) { pn[u] = pev[u] * wv[u] * invw; s1 += pn[u]; }
        float inv1 = 1.f / fmaxf(s1, 1e-8f);
        for (int u = 0; u < 6; u++) pn[u] *= inv1;
        int i1 = 0;
        for (int u = 1; u < 6; u++) if (pn[u] > pn[i1]) i1 = u;
        int i2 = (i1 == 0) ? 1 : 0;
        for (int u = 0; u < 6; u++) if (u != i1 && pn[u] > pn[i2]) i2 = u;
        float inv2 = 1.f / fmaxf(pn[i1] + pn[i2], 1e-8f);
        for (int u = 0; u < 6; u++)
            pi[n * NS + u] = (u == i1 || u == i2) ? pn[u] * inv2 : 0.f;
    }
}

__global__ void attn_k(const float* __restrict__ q, const float* __restrict__ k,
                       const float* __restrict__ v, const float* __restrict__ pi,
                       const float* __restrict__ ln_g, const float* __restrict__ ln_b,
                       float* __restrict__ msg)
{
    __shared__ float sw[4];
    __shared__ float mb[D];
    __shared__ float red[8];
    int n = blockIdx.x, tid = threadIdx.x;
    int t = n % TSEQ;
    int warp = tid >> 5, lane = tid & 31;
    const int offs[4] = {-2, -1, 1, 2};
    {
        int o = offs[warp];
        int tt = t + o;
        float dot = 0.f;
        if (tt >= 0 && tt < TSEQ) {
            const float* qp = q + (long)n * D;
            const float* kp = k + (long)(n + o) * D;
            for (int j = lane; j < D; j += 32) dot += qp[j] * kp[j];
        }
#pragma unroll
        for (int s = 16; s > 0; s >>= 1) dot += __shfl_xor_sync(0xffffffffu, dot, s);
        if (lane == 0)
            sw[warp] = (tt >= 0 && tt < TSEQ) ? dot / 27.712812921102035f : -1e9f;
    }
    __syncthreads();
    float w0 = sw[0], w1 = sw[1], w2 = sw[2], w3 = sw[3];
    float mx = fmaxf(fmaxf(w0, w1), fmaxf(w2, w3));
    float wt[4] = {expf(w0 - mx), expf(w1 - mx), expf(w2 - mx), expf(w3 - mx)};
    float invs = 1.f / (wt[0] + wt[1] + wt[2] + wt[3]);
#pragma unroll
    for (int w = 0; w < 4; w++) wt[w] *= invs;
    float pi3 = pi[n * NS + 3];
    for (int j = tid; j < D; j += 128) {
        float m = 0.f;
#pragma unroll
        for (int w = 0; w < 4; w++) {
            int tt = t + offs[w];
            if (tt >= 0 && tt < TSEQ) m += wt[w] * v[(long)(n + offs[w]) * D + j];
        }
        mb[j] = m * pi3;
    }
    __syncthreads();
    float loc[6], s = 0.f;
#pragma unroll
    for (int r = 0; r < 6; r++) { loc[r] = mb[tid + r * 128]; s += loc[r]; }
    float mean = block_sum(s, red) / D;
    float qv = 0.f;
#pragma unroll
    for (int r = 0; r < 6; r++) { float d = loc[r] - mean; qv += d * d; }
    float var = block_sum(qv, red) / D;
    float inv = rsqrtf(var + 1e-5f);
#pragma unroll
    for (int r = 0; r < 6; r++) {
        int j = tid + r * 128;
        msg[(long)n * D + j] = (loc[r] - mean) * inv * ln_g[3 * D + j] + ln_b[3 * D + j];
    }
}

__global__ void update_k(const float* __restrict__ muhat, float* __restrict__ lam,
                         const float* __restrict__ dlam, const float* __restrict__ mhat,
                         const float* __restrict__ so,
                         const float* __restrict__ ln_g, const float* __restrict__ ln_b,
                         float* __restrict__ mu)
{
    __shared__ float red[8];
    int n = blockIdx.x, tid = threadIdx.x;
    float mval[3], s = 0.f;
#pragma unroll
    for (int r = 0; r < 3; r++) {
        int j = tid + r * 256;
        long idx = (long)n * D + j;
        float l = lam[idx], dl = dlam[idx];
        float mwn = muhat[idx] * ln_g[4 * D + j] + ln_b[4 * D + j];
        float lnw = l + dl;
        float m = (l * mwn + dl * mhat[idx]) / lnw;
        lam[idx] = lnw;
        mval[r] = m;
        s += m;
    }
    float mean = block_sum(s, red) / D;
    float qv = 0.f;
#pragma unroll
    for (int r = 0; r < 3; r++) { float d = mval[r] - mean; qv += d * d; }
    float var = block_sum(qv, red) / D;
    float inv = rsqrtf(var + 1e-5f);
#pragma unroll
    for (int r = 0; r < 3; r++) {
        int j = tid + r * 256;
        long idx = (long)n * D + j;
        mu[idx] = (mval[r] - mean) * inv * ln_g[5 * D + j] + ln_b[5 * D + j] + so[idx] * 0.1f;
    }
}

// ---------------- launcher ----------------
extern "C" void kernel_launch(void* const* d_in, const int* in_sizes, int n_in,
                              void* d_out, int out_size)
{
    const int*   x        = (const int*)d_in[0];
    const float* emb_w    = (const float*)d_in[1];
    const float* pos_w    = (const float*)d_in[2];
    const float* mu_w     = (const float*)d_in[3];
    const float* mu_b     = (const float*)d_in[4];
    const float* lam_w    = (const float*)d_in[5];
    const float* lam_b    = (const float*)d_in[6];
    const float* tr_w1    = (const float*)d_in[7];
    const float* tr_b1    = (const float*)d_in[8];
    const float* tr_w2    = (const float*)d_in[9];
    const float* tr_b2    = (const float*)d_in[10];
    const float* bank_w1  = (const float*)d_in[11];
    const float* bank_b1  = (const float*)d_in[12];
    const float* bank_w2  = (const float*)d_in[13];
    const float* bank_b2  = (const float*)d_in[14];
    const float* ev_w     = (const float*)d_in[15];
    const float* ev_b     = (const float*)d_in[16];
    const float* rt_q     = (const float*)d_in[17];
    const float* rt_k     = (const float*)d_in[18];
    const float* rt_v     = (const float*)d_in[19];
    const float* wr_lam_w = (const float*)d_in[20];
    const float* wr_lam_b = (const float*)d_in[21];
    const float* wr_mu_w  = (const float*)d_in[22];
    const float* wr_mu_b  = (const float*)d_in[23];
    const float* ln_g     = (const float*)d_in[24];
    const float* ln_b     = (const float*)d_in[25];
    float* out = (float*)d_out;

    cudaFuncSetAttribute(tgemm_k<EPI_GELU>, cudaFuncAttributeMaxDynamicSharedMemorySize, SM_BYTES);
    cudaFuncSetAttribute(tgemm_k<EPI_SCALE>, cudaFuncAttributeMaxDynamicSharedMemorySize, SM_BYTES);
    cudaFuncSetAttribute(tgemm_pair_k<EPI_BIAS, EPI_SP01>, cudaFuncAttributeMaxDynamicSharedMemorySize, SM_BYTES);
    cudaFuncSetAttribute(tgemm_pair_k<EPI_GSP, EPI_BIAS>, cudaFuncAttributeMaxDynamicSharedMemorySize, SM_BYTES);
    cudaFuncSetAttribute(tqkv_k, cudaFuncAttributeMaxDynamicSharedMemorySize, SM_BYTES);
    cudaFuncSetAttribute(tbank1_k, cudaFuncAttributeMaxDynamicSharedMemorySize, SM_BYTES);
    cudaFuncSetAttribute(tbank2_k<0>, cudaFuncAttributeMaxDynamicSharedMemorySize, SM_BYTES);
    cudaFuncSetAttribute(tbank2_k<1>, cudaFuncAttributeMaxDynamicSharedMemorySize, SM_BYTES);

    float* base = nullptr;
    cudaGetSymbolAddress((void**)&base, g_scratch);
    float *whi = nullptr, *wlo = nullptr;
    cudaGetSymbolAddress((void**)&whi, g_whi);
    cudaGetSymbolAddress((void**)&wlo, g_wlo);
    int *cnt, *list, *cnt2, *slot2, *tok2;
    cudaGetSymbolAddress((void**)&cnt, g_cnt);
    cudaGetSymbolAddress((void**)&list, g_list);
    cudaGetSymbolAddress((void**)&cnt2, g_cnt2);
    cudaGetSymbolAddress((void**)&slot2, g_slot2);
    cudaGetSymbolAddress((void**)&tok2, g_tok2);

    float* h     = base + OFF_H;
    float* mu    = base + OFF_MU;
    float* muhat = base + OFF_MUHAT;
    float* mun   = base + OFF_MUN;
    float* mur   = base + OFF_MUR;
    float* so    = base + OFF_SO;
    float* qb    = base + OFF_Q;
    float* lam   = base + OFF_LAM;
    float* msg   = base + OFF_MSG;
    float* dlam  = base + OFF_DLAM;
    float* mhat  = base + OFF_MHAT;
    float* fin   = base + OFF_FIN;
    float* trh   = base + OFF_TRH;
    float* hb    = base + OFF_HB;
    float* pi    = base + OFF_PI;

    const float inv_sqrt_d = 0.03608439182435161f;

    // ---- weight prep: split (and transpose emb) into hi/lo arena ----
    {
        const int DD4 = D * D / 4;
        split_k<<<(DD4 + 255) / 256, 256>>>(mu_w,     whi + W_MU,  wlo + W_MU,  DD4);
        split_k<<<(DD4 + 255) / 256, 256>>>(lam_w,    whi + W_LAM, wlo + W_LAM, DD4);
        split_k<<<(D * 1536 / 4 + 255) / 256, 256>>>(tr_w1, whi + W_TR1, wlo + W_TR1, D * 1536 / 4);
        split_k<<<(DD4 + 255) / 256, 256>>>(rt_q,     whi + W_RTQ, wlo + W_RTQ, DD4);
        split_k<<<(DD4 + 255) / 256, 256>>>(rt_k,     whi + W_RTK, wlo + W_RTK, DD4);
        split_k<<<(DD4 + 255) / 256, 256>>>(rt_v,     whi + W_RTV, wlo + W_RTV, DD4);
        split_k<<<(DD4 + 255) / 256, 256>>>(wr_lam_w, whi + W_WRL, wlo + W_WRL, DD4);
        split_k<<<(DD4 + 255) / 256, 256>>>(wr_mu_w,  whi + W_WRM, wlo + W_WRM, DD4);
        const int B14 = NS * D * FFN / 4;
        split_k<<<(B14 + 255) / 256, 256>>>(bank_w1, whi + W_B1, wlo + W_B1, B14);
        split_k<<<(B14 + 255) / 256, 256>>>(bank_w2, whi + W_B2, wlo + W_B2, B14);
        dim3 gt(VOC / 32, D / 32);
        tsplit_emb_k<<<gt, dim3(32, 8)>>>(emb_w, whi + W_EMBT, wlo + W_EMBT);
    }

    emb_k<<<NTOK, 256>>>(x, emb_w, pos_w, h);
    {
        dim3 g(D / 128, NTOK / 128, 2);
        tgemm_pair_k<EPI_BIAS, EPI_SP01><<<g, 256, SM_BYTES>>>(h, whi + W_MU, wlo + W_MU,
                                                               mu_b, lam_b, nullptr, mu);
    }
    pi_init_k<<<(NTOK * NS + 255) / 256, 256>>>(pi);

    for (int step = 0; step < 3; step++) {
        ln012_k<<<NTOK, 256>>>(mu, muhat, mun, mur, ln_g, ln_b);
        {
            dim3 g(1536 / 128, NTOK / 128);
            tgemm_k<EPI_GELU><<<g, 256, SM_BYTES>>>(mu, whi + W_TR1, wlo + W_TR1,
                                                    tr_b1, trh, 1536, D, 1.f, nullptr);
        }
        reset_cnt_k<<<1, 32>>>(cnt, cnt2);
        build_lists_k<<<NTOK / 256, 256>>>(pi, cnt, list, cnt2, slot2, tok2);
        {
            dim3 g1(FFN / 128, NTOK / 128, NS);
            tbank1_k<<<g1, 256, SM_BYTES>>>(mun, whi + W_B1, wlo + W_B1, bank_b1, hb, list, cnt);
            dim3 g2(D / 128, NTOK / 128, NS);
            tbank2_k<0><<<g2, 256, SM_BYTES>>>(hb, whi + W_B2, wlo + W_B2, bank_b2,
                                               so, cnt2, slot2, tok2, pi);
            tbank2_k<1><<<g2, 256, SM_BYTES>>>(hb, whi + W_B2, wlo + W_B2, bank_b2,
                                               so, cnt2, slot2, tok2, pi);
        }
        ln_gen_k<<<NTOK, 256>>>(so, so, ln_g + 1 * D, ln_b + 1 * D);
        routing_k<<<NTOK, 128>>>(trh, tr_w2, tr_b2, mun, ev_w, ev_b, pi);
        {
            dim3 g(D / 128, NTOK / 128, 3);
            tqkv_k<<<g, 256, SM_BYTES>>>(mur, whi + W_RTQ, wlo + W_RTQ, qb);
        }
        attn_k<<<NTOK, 128>>>(qb, qb + ROW, qb + 2 * ROW, pi, ln_g, ln_b, msg);
        {
            dim3 g(D / 128, NTOK / 128, 2);
            tgemm_pair_k<EPI_GSP, EPI_BIAS><<<g, 256, SM_BYTES>>>(msg, whi + W_WRL, wlo + W_WRL,
                                                                  wr_lam_b, wr_mu_b, pi, dlam);
        }
        update_k<<<NTOK, 256>>>(muhat, lam, dlam, mhat, so, ln_g, ln_b, mu);
    }

    ln_gen_k<<<NTOK, 256>>>(mu, fin, ln_g + 6 * D, ln_b + 6 * D);
    {
        dim3 g(VOC / 128, NTOK / 128);
        tgemm_k<EPI_SCALE><<<g, 256, SM_BYTES>>>(fin, whi + W_EMBT, wlo + W_EMBT,
                                                 nullptr, out, VOC, D, inv_sqrt_d, nullptr);
    }
}

// round 11
// speedup vs baseline: 1.2593x; 1.0527x over previous
#include <cuda_runtime.h>
#include <math.h>
#include <stdint.h>

#define NTOK 2048
#define TSEQ 1024
#define D    768
#define FFN  3072
#define NS   6
#define VOC  32000

// ---------------- scratch ----------------
#define ROW (NTOK*D)
#define OFF_H     0
#define OFF_MU    (1*ROW)
#define OFF_LAM   (2*ROW)
#define OFF_MUHAT (3*ROW)
#define OFF_MUN   (4*ROW)
#define OFF_MUR   (5*ROW)
#define OFF_SO    (6*ROW)
#define OFF_Q     (7*ROW)
#define OFF_K     (8*ROW)
#define OFF_V     (9*ROW)
#define OFF_MSG   (10*ROW)
#define OFF_DLAM  (11*ROW)
#define OFF_MHAT  (12*ROW)
#define OFF_FIN   (13*ROW)
#define OFF_TRH   (14*ROW)
#define OFF_HB    (14*ROW + NTOK*1536)
#define OFF_PI    (OFF_HB + NS*NTOK*FFN)
#define SCRATCH_FLOATS (OFF_PI + NTOK*NS)

__device__ float g_scratch[SCRATCH_FLOATS];
__device__ int   g_cnt[NS];
__device__ int   g_list[NS * NTOK];
__device__ int   g_cnt2[2 * NS];
__device__ int   g_slot2[2 * NS * NTOK];
__device__ int   g_tok2[2 * NS * NTOK];

// ---------------- pre-split weight arena (hi/lo tf32 split) ----------------
#define W_MU   0
#define W_LAM  589824
#define W_TR1  1179648
#define W_RTQ  2359296
#define W_RTK  2949120
#define W_RTV  3538944
#define W_WRL  4128768
#define W_WRM  4718592
#define W_B1   5308416
#define W_B2   19464192
#define W_EMBT 33619968
#define WSPLIT 58195968

__device__ float g_whi[WSPLIT];
__device__ float g_wlo[WSPLIT];

// ---------------- helpers ----------------
__device__ __forceinline__ float gelu_f(float x) {
    float x3 = x * x * x;
    return 0.5f * x * (1.f + tanhf(0.7978845608028654f * (x + 0.044715f * x3)));
}
__device__ __forceinline__ float softplus_f(float x) {
    return fmaxf(x, 0.f) + log1pf(expf(-fabsf(x)));
}
__device__ __forceinline__ float block_sum(float v, float* red) {
    int tid = threadIdx.x;
    __syncthreads();
#pragma unroll
    for (int o = 16; o > 0; o >>= 1) v += __shfl_xor_sync(0xffffffffu, v, o);
    if ((tid & 31) == 0) red[tid >> 5] = v;
    __syncthreads();
    if (tid < 32) {
        float t = (tid < (int)(blockDim.x >> 5)) ? red[tid] : 0.f;
#pragma unroll
        for (int o = 4; o > 0; o >>= 1) t += __shfl_xor_sync(0xffffffffu, t, o);
        if (tid == 0) red[0] = t;
    }
    __syncthreads();
    return red[0];
}

__device__ __forceinline__ void cvt_split(float x, float& hi, float& lo) {
    uint32_t hb; asm("cvt.rna.tf32.f32 %0, %1;" : "=r"(hb) : "f"(x));
    hi = __uint_as_float(hb);
    float lf = x - hi;
    uint32_t lb; asm("cvt.rna.tf32.f32 %0, %1;" : "=r"(lb) : "f"(lf));
    lo = __uint_as_float(lb);
}

// ---------------- weight prep kernels ----------------
__global__ void split_k(const float* __restrict__ src, float* __restrict__ hi,
                        float* __restrict__ lo, int n4)
{
    int i = blockIdx.x * blockDim.x + threadIdx.x;
    if (i >= n4) return;
    float4 v = ((const float4*)src)[i];
    float4 h, l;
    cvt_split(v.x, h.x, l.x); cvt_split(v.y, h.y, l.y);
    cvt_split(v.z, h.z, l.z); cvt_split(v.w, h.w, l.w);
    ((float4*)hi)[i] = h;
    ((float4*)lo)[i] = l;
}

// transpose emb_w [VOC][D] -> split into [D][VOC] hi/lo
__global__ void tsplit_emb_k(const float* __restrict__ emb,
                             float* __restrict__ hi, float* __restrict__ lo)
{
    __shared__ float tile[32][33];
    int v0 = blockIdx.x * 32, d0 = blockIdx.y * 32;
    int tx = threadIdx.x, ty = threadIdx.y; // 32 x 8
    for (int r = ty; r < 32; r += 8)
        tile[r][tx] = emb[(long)(v0 + r) * D + d0 + tx];
    __syncthreads();
    for (int r = ty; r < 32; r += 8) {
        float hf, lf;
        cvt_split(tile[tx][r], hf, lf);
        long o = (long)(d0 + r) * VOC + v0 + tx;
        hi[o] = hf;
        lo[o] = lf;
    }
}

// ---------------- tf32 mma core ----------------
// smem (float offsets): RAWA[3][128][20] @0 (7680),
// BHI[3][16][136] @7680 (6528), BLO[3][16][136] @14208 (6528)
// total 20736 floats = 82944 B -> 2 CTAs/SM
#define A_ST    2560
#define B_STF   2176
#define SM_RAWA 0
#define SM_BHI  7680
#define SM_BLO  14208
#define SM_BYTES (20736 * 4)

__device__ __forceinline__ void mma8(float* c, const uint32_t* a, uint32_t b0, uint32_t b1) {
    asm volatile(
        "mma.sync.aligned.m16n8k8.row.col.f32.tf32.tf32.f32 "
        "{%0,%1,%2,%3},{%4,%5,%6,%7},{%8,%9},{%0,%1,%2,%3};"
        : "+f"(c[0]), "+f"(c[1]), "+f"(c[2]), "+f"(c[3])
        : "r"(a[0]), "r"(a[1]), "r"(a[2]), "r"(a[3]), "r"(b0), "r"(b1));
}

__device__ __forceinline__ void cp16(uint32_t dst, const float* src) {
    asm volatile("cp.async.ca.shared.global [%0], [%1], 16;" :: "r"(dst), "l"(src) : "memory");
}

// block 128x128, 8 warps (4m x 2n), warp tile 32x64, BK=16.
// Raw A (fp32, read ONCE from gmem) + pre-split B, 3-stage rings, ONE barrier
// per slice. A's hi/lo split happens inline in comp (registers).
// FAST: drop the al*bh correction mma (2 instead of 3). ONLY legal for the
// final logits GEMM — its error lands directly in the output (no routing
// amplification); everywhere else keeps the full 3-term split.
template <bool GATHER, bool FAST>
__device__ __forceinline__ void tf32_loop(
    const float* __restrict__ A, const float* __restrict__ Bhi,
    const float* __restrict__ Blo,
    int K, int N, int bm0, int bn0, const int* __restrict__ rowTok,
    float* __restrict__ sm, float c[2][8][4])
{
    const int tid = threadIdx.x;
    const int lane = tid & 31, warp = tid >> 5;
    const int wm0 = (warp >> 1) * 32, wn0 = (warp & 1) * 64;
    const int g = lane >> 2, tig = lane & 3;

    const int arow0 = tid >> 2, arow1 = arow0 + 64, aq = tid & 3;
    long agr0, agr1;
    if (GATHER) { agr0 = rowTok[arow0]; agr1 = rowTok[arow1]; }
    else        { agr0 = bm0 + arow0;   agr1 = bm0 + arow1;   }
    const int bkr = tid >> 5;
    const int bn4 = (tid & 31) * 4;

    const uint32_t smb = (uint32_t)__cvta_generic_to_shared(sm);

    auto issue = [&](int st, int k0) {
        uint32_t ra = smb + (uint32_t)(SM_RAWA + st * A_ST) * 4u;
        cp16(ra + (uint32_t)(arow0 * 20 + aq * 4) * 4u, A + agr0 * K + k0 + aq * 4);
        cp16(ra + (uint32_t)(arow1 * 20 + aq * 4) * 4u, A + agr1 * K + k0 + aq * 4);
        uint32_t bh = smb + (uint32_t)(SM_BHI + st * B_STF) * 4u;
        uint32_t bl = smb + (uint32_t)(SM_BLO + st * B_STF) * 4u;
        cp16(bh + (uint32_t)(bkr * 136 + bn4) * 4u,
             Bhi + (long)(k0 + bkr) * N + bn0 + bn4);
        cp16(bh + (uint32_t)((bkr + 8) * 136 + bn4) * 4u,
             Bhi + (long)(k0 + bkr + 8) * N + bn0 + bn4);
        cp16(bl + (uint32_t)(bkr * 136 + bn4) * 4u,
             Blo + (long)(k0 + bkr) * N + bn0 + bn4);
        cp16(bl + (uint32_t)((bkr + 8) * 136 + bn4) * 4u,
             Blo + (long)(k0 + bkr + 8) * N + bn0 + bn4);
        asm volatile("cp.async.commit_group;" ::: "memory");
    };

    auto comp = [&](int st) {
        const float* rap = sm + SM_RAWA + st * A_ST;
        const float* bhp = sm + SM_BHI + st * B_STF;
        const float* blp = sm + SM_BLO + st * B_STF;
#pragma unroll
        for (int ks = 0; ks < 16; ks += 8) {
            uint32_t ah[2][4], al[2][4];
#pragma unroll
            for (int mt = 0; mt < 2; mt++) {
                int rb = wm0 + mt * 16 + g;
                float r0 = rap[rb * 20 + ks + tig];
                float r1 = rap[(rb + 8) * 20 + ks + tig];
                float r2 = rap[rb * 20 + ks + tig + 4];
                float r3 = rap[(rb + 8) * 20 + ks + tig + 4];
                float hf, lf;
                cvt_split(r0, hf, lf); ah[mt][0] = __float_as_uint(hf); al[mt][0] = __float_as_uint(lf);
                cvt_split(r1, hf, lf); ah[mt][1] = __float_as_uint(hf); al[mt][1] = __float_as_uint(lf);
                cvt_split(r2, hf, lf); ah[mt][2] = __float_as_uint(hf); al[mt][2] = __float_as_uint(lf);
                cvt_split(r3, hf, lf); ah[mt][3] = __float_as_uint(hf); al[mt][3] = __float_as_uint(lf);
            }
#pragma unroll
            for (int nt = 0; nt < 8; nt++) {
                int cb = wn0 + nt * 8 + g;
                uint32_t bh0 = __float_as_uint(bhp[(ks + tig) * 136 + cb]);
                uint32_t bh1 = __float_as_uint(bhp[(ks + tig + 4) * 136 + cb]);
                uint32_t bl0 = __float_as_uint(blp[(ks + tig) * 136 + cb]);
                uint32_t bl1 = __float_as_uint(blp[(ks + tig + 4) * 136 + cb]);
#pragma unroll
                for (int mt = 0; mt < 2; mt++) {
                    mma8(c[mt][nt], ah[mt], bh0, bh1);
                    mma8(c[mt][nt], ah[mt], bl0, bl1);
                    if (!FAST) mma8(c[mt][nt], al[mt], bh0, bh1);
                }
            }
        }
    };

    const int nk = K >> 4;  // >= 48 at all call sites
    issue(0, 0);
    issue(1, 16);
    int st = 0, stn = 2;
    for (int i = 0; i < nk; i++) {
        if (i < nk - 1) asm volatile("cp.async.wait_group 1;" ::: "memory");
        else            asm volatile("cp.async.wait_group 0;" ::: "memory");
        __syncthreads();
        if (i + 2 < nk) {
            issue(stn, (i + 2) << 4);
            stn = (stn == 2) ? 0 : stn + 1;
        }
        comp(st);
        st = (st == 2) ? 0 : st + 1;
    }
}

// ---------------- epilogues ----------------
enum { EPI_NONE = 0, EPI_BIAS = 1, EPI_GELU = 2, EPI_GSP = 3, EPI_SCALE = 4, EPI_SP01 = 5 };

template <int EPI>
__device__ __forceinline__ float epi_apply(float v, float b, float rs, float alpha) {
    if (EPI == EPI_BIAS)  return v + b;
    if (EPI == EPI_GELU)  return gelu_f(v + b);
    if (EPI == EPI_GSP)   return rs * softplus_f(v + b);
    if (EPI == EPI_SCALE) return v * alpha;
    if (EPI == EPI_SP01)  return softplus_f(v + b) + 0.1f;
    return v;
}

template <int EPI>
__device__ __forceinline__ void epi_store_dense(
    float c[2][8][4], float* __restrict__ C, const float* __restrict__ bias,
    int N, int bm0, int bn0, const float* __restrict__ pi, float alpha)
{
    const int tid = threadIdx.x, lane = tid & 31, warp = tid >> 5;
    const int wm0 = (warp >> 1) * 32, wn0 = (warp & 1) * 64;
    const int g = lane >> 2, tig = lane & 3;
    const int colbase = bn0 + wn0;
#pragma unroll
    for (int mt = 0; mt < 2; mt++) {
#pragma unroll
        for (int half = 0; half < 2; half++) {
            int row = bm0 + wm0 + mt * 16 + g + half * 8;
            float rs = (EPI == EPI_GSP) ? pi[row * NS + 4] : 0.f;
            float* cp = C + (long)row * N + colbase;
#pragma unroll
            for (int nt = 0; nt < 8; nt++) {
                int col = nt * 8 + tig * 2;
                float b0 = 0.f, b1 = 0.f;
                if (EPI == EPI_BIAS || EPI == EPI_GELU || EPI == EPI_GSP || EPI == EPI_SP01) {
                    b0 = bias[colbase + col];
                    b1 = bias[colbase + col + 1];
                }
                float v0 = epi_apply<EPI>(c[mt][nt][half * 2], b0, rs, alpha);
                float v1 = epi_apply<EPI>(c[mt][nt][half * 2 + 1], b1, rs, alpha);
                *(float2*)(cp + col) = make_float2(v0, v1);
            }
        }
    }
}

// ---------------- GEMM kernels ----------------
template <int EPI, bool FAST>
__global__ void __launch_bounds__(256, 2) tgemm_k(
    const float* __restrict__ A, const float* __restrict__ Bhi,
    const float* __restrict__ Blo, const float* __restrict__ bias,
    float* __restrict__ C, int N, int K, float alpha,
    const float* __restrict__ pi)
{
    extern __shared__ float sm[];
    const int bm0 = blockIdx.y * 128, bn0 = blockIdx.x * 128;
    float c[2][8][4];
#pragma unroll
    for (int a = 0; a < 2; a++)
#pragma unroll
        for (int b = 0; b < 8; b++)
#pragma unroll
            for (int r = 0; r < 4; r++) c[a][b][r] = 0.f;
    tf32_loop<false, FAST>(A, Bhi, Blo, K, N, bm0, bn0, nullptr, sm, c);
    epi_store_dense<EPI>(c, C, bias, N, bm0, bn0, pi, alpha);
}

// z-pair over adjacent arena weights (stride D*D)
template <int EPI0, int EPI1>
__global__ void __launch_bounds__(256, 2) tgemm_pair_k(
    const float* __restrict__ A, const float* __restrict__ Whi,
    const float* __restrict__ Wlo, const float* __restrict__ b0,
    const float* __restrict__ b1, const float* __restrict__ pi,
    float* __restrict__ Cbase)
{
    extern __shared__ float sm[];
    const int z = blockIdx.z;
    const float* Bhi = Whi + (long)z * D * D;
    const float* Blo = Wlo + (long)z * D * D;
    const float* bias = z ? b1 : b0;
    float* C = Cbase + (long)z * ROW;
    const int bm0 = blockIdx.y * 128, bn0 = blockIdx.x * 128;
    float c[2][8][4];
#pragma unroll
    for (int a = 0; a < 2; a++)
#pragma unroll
        for (int b = 0; b < 8; b++)
#pragma unroll
            for (int r = 0; r < 4; r++) c[a][b][r] = 0.f;
    tf32_loop<false, false>(A, Bhi, Blo, D, D, bm0, bn0, nullptr, sm, c);
    if (z == 0) epi_store_dense<EPI0>(c, C, bias, D, bm0, bn0, pi, 1.f);
    else        epi_store_dense<EPI1>(c, C, bias, D, bm0, bn0, pi, 1.f);
}

__global__ void __launch_bounds__(256, 2) tqkv_k(
    const float* __restrict__ A, const float* __restrict__ Whi,
    const float* __restrict__ Wlo, float* __restrict__ Cbase)
{
    extern __shared__ float sm[];
    const int z = blockIdx.z;
    const float* Bhi = Whi + (long)z * D * D;
    const float* Blo = Wlo + (long)z * D * D;
    float* C = Cbase + (long)z * ROW;
    const int bm0 = blockIdx.y * 128, bn0 = blockIdx.x * 128;
    float c[2][8][4];
#pragma unroll
    for (int a = 0; a < 2; a++)
#pragma unroll
        for (int b = 0; b < 8; b++)
#pragma unroll
            for (int r = 0; r < 4; r++) c[a][b][r] = 0.f;
    tf32_loop<false, false>(A, Bhi, Blo, D, D, bm0, bn0, nullptr, sm, c);
    epi_store_dense<EPI_NONE>(c, C, nullptr, D, bm0, bn0, nullptr, 1.f);
}

__global__ void __launch_bounds__(256, 2) tbank1_k(
    const float* __restrict__ A, const float* __restrict__ Whi,
    const float* __restrict__ Wlo, const float* __restrict__ b1all,
    float* __restrict__ hb, const int* __restrict__ list,
    const int* __restrict__ cnt)
{
    extern __shared__ float sm[];
    __shared__ int rowTok[128];
    const int s = blockIdx.z;
    const int cn = cnt[s];
    const int bm0 = blockIdx.y * 128;
    if (bm0 >= cn) return;
    const int tid = threadIdx.x;
    if (tid < 128) rowTok[tid] = list[s * NTOK + min(bm0 + tid, cn - 1)];
    __syncthreads();

    const float* Bhi = Whi + (long)s * D * FFN;
    const float* Blo = Wlo + (long)s * D * FFN;
    const float* bias = b1all + s * FFN;
    float* C = hb + (long)s * NTOK * FFN;
    const int bn0 = blockIdx.x * 128;

    float c[2][8][4];
#pragma unroll
    for (int a = 0; a < 2; a++)
#pragma unroll
        for (int b = 0; b < 8; b++)
#pragma unroll
            for (int r = 0; r < 4; r++) c[a][b][r] = 0.f;
    tf32_loop<true, false>(A, Bhi, Blo, D, FFN, 0, bn0, rowTok, sm, c);

    const int lane = tid & 31, warp = tid >> 5;
    const int wm0 = (warp >> 1) * 32, wn0 = (warp & 1) * 64;
    const int g = lane >> 2, tig = lane & 3;
    const int colbase = bn0 + wn0;
#pragma unroll
    for (int mt = 0; mt < 2; mt++) {
#pragma unroll
        for (int half = 0; half < 2; half++) {
            int slot = bm0 + wm0 + mt * 16 + g + half * 8;
            if (slot >= cn) continue;
            float* cp = C + (long)slot * FFN + colbase;
#pragma unroll
            for (int nt = 0; nt < 8; nt++) {
                int col = nt * 8 + tig * 2;
                float v0 = gelu_f(c[mt][nt][half * 2] + bias[colbase + col]);
                float v1 = gelu_f(c[mt][nt][half * 2 + 1] + bias[colbase + col + 1]);
                *(float2*)(cp + col) = make_float2(v0, v1);
            }
        }
    }
}

template <int RANK>
__global__ void __launch_bounds__(256, 2) tbank2_k(
    const float* __restrict__ hb, const float* __restrict__ Whi,
    const float* __restrict__ Wlo, const float* __restrict__ b2all,
    float* __restrict__ so, const int* __restrict__ cnt2,
    const int* __restrict__ slot2, const int* __restrict__ tok2,
    const float* __restrict__ pi)
{
    extern __shared__ float sm[];
    __shared__ int rowSlot[128];
    const int s = blockIdx.z;
    const int cn = cnt2[RANK * NS + s];
    const int bm0 = blockIdx.y * 128;
    if (bm0 >= cn) return;
    const int tid = threadIdx.x;
    const int lbase = (RANK * NS + s) * NTOK;
    if (tid < 128) rowSlot[tid] = slot2[lbase + min(bm0 + tid, cn - 1)];
    __syncthreads();

    const float* A = hb + (long)s * NTOK * FFN;
    const float* Bhi = Whi + (long)s * FFN * D;
    const float* Blo = Wlo + (long)s * FFN * D;
    const float* bias = b2all + s * D;
    const int bn0 = blockIdx.x * 128;

    float c[2][8][4];
#pragma unroll
    for (int a = 0; a < 2; a++)
#pragma unroll
        for (int b = 0; b < 8; b++)
#pragma unroll
            for (int r = 0; r < 4; r++) c[a][b][r] = 0.f;
    tf32_loop<true, false>(A, Bhi, Blo, FFN, D, 0, bn0, rowSlot, sm, c);

    const int lane = tid & 31, warp = tid >> 5;
    const int wm0 = (warp >> 1) * 32, wn0 = (warp & 1) * 64;
    const int g = lane >> 2, tig = lane & 3;
    const int colbase = bn0 + wn0;
#pragma unroll
    for (int mt = 0; mt < 2; mt++) {
#pragma unroll
        for (int half = 0; half < 2; half++) {
            int idx = bm0 + wm0 + mt * 16 + g + half * 8;
            if (idx >= cn) continue;
            int tok = tok2[lbase + idx];
            float rs = pi[tok * NS + s];
            float* cp = so + (long)tok * D + colbase;
#pragma unroll
            for (int nt = 0; nt < 8; nt++) {
                int col = nt * 8 + tig * 2;
                float v0 = rs * (c[mt][nt][half * 2] + bias[colbase + col]);
                float v1 = rs * (c[mt][nt][half * 2 + 1] + bias[colbase + col + 1]);
                if (RANK == 0) {
                    *(float2*)(cp + col) = make_float2(v0, v1);
                } else {
                    float2 old = *(float2*)(cp + col);
                    *(float2*)(cp + col) = make_float2(old.x + v0, old.y + v1);
                }
            }
        }
    }
}

// ---------------- small kernels ----------------
__global__ void emb_k(const int* __restrict__ x, const float* __restrict__ emb,
                      const float* __restrict__ pos, float* __restrict__ h)
{
    int n = blockIdx.x;
    int vx = x[n];
    int t = n % TSEQ;
    const float* e = emb + (long)vx * D;
    const float* p = pos + (long)t * D;
    for (int j = threadIdx.x; j < D; j += blockDim.x)
        h[(long)n * D + j] = e[j] + p[j];
}

__global__ void pi_init_k(float* __restrict__ pi)
{
    int i = blockIdx.x * blockDim.x + threadIdx.x;
    if (i < NTOK * NS) pi[i] = ((i % NS) == 2) ? 1.f : 0.f;
}

__global__ void reset_cnt_k(int* cnt, int* cnt2)
{
    if (threadIdx.x < NS) cnt[threadIdx.x] = 0;
    if (threadIdx.x < 2 * NS) cnt2[threadIdx.x] = 0;
}

__global__ void build_lists_k(const float* __restrict__ pi,
                              int* __restrict__ cnt, int* __restrict__ list,
                              int* __restrict__ cnt2, int* __restrict__ slot2,
                              int* __restrict__ tok2)
{
    int t = blockIdx.x * blockDim.x + threadIdx.x;
    if (t >= NTOK) return;
    int r = 0;
#pragma unroll
    for (int s = 0; s < NS; s++) {
        if (pi[t * NS + s] != 0.f) {
            int p = atomicAdd(&cnt[s], 1);
            list[s * NTOK + p] = t;
            int rr = min(r, 1);
            int q = atomicAdd(&cnt2[rr * NS + s], 1);
            slot2[(rr * NS + s) * NTOK + q] = p;
            tok2[(rr * NS + s) * NTOK + q] = t;
            r++;
        }
    }
}

__global__ void ln012_k(const float* __restrict__ mu, float* __restrict__ muhat,
                        float* __restrict__ mun, float* __restrict__ mur,
                        const float* __restrict__ ln_g, const float* __restrict__ ln_b)
{
    __shared__ float red[8];
    int n = blockIdx.x, tid = threadIdx.x;
    const float* row = mu + (long)n * D;
    float v[3], s = 0.f;
#pragma unroll
    for (int r = 0; r < 3; r++) { v[r] = row[tid + r * 256]; s += v[r]; }
    float mean = block_sum(s, red) / D;
    float qv = 0.f;
#pragma unroll
    for (int r = 0; r < 3; r++) { float d = v[r] - mean; qv += d * d; }
    float var = block_sum(qv, red) / D;
    float inv = rsqrtf(var + 1e-5f);
#pragma unroll
    for (int r = 0; r < 3; r++) {
        int j = tid + r * 256;
        float nh = (v[r] - mean) * inv;
        long idx = (long)n * D + j;
        muhat[idx] = nh;
        mun[idx] = nh * ln_g[j] + ln_b[j];
        mur[idx] = nh * ln_g[2 * D + j] + ln_b[2 * D + j];
    }
}

__global__ void ln_gen_k(const float* __restrict__ in, float* __restrict__ out,
                         const float* __restrict__ g, const float* __restrict__ b)
{
    __shared__ float red[8];
    int n = blockIdx.x, tid = threadIdx.x;
    const float* row = in + (long)n * D;
    float v[3], s = 0.f;
#pragma unroll
    for (int r = 0; r < 3; r++) { v[r] = row[tid + r * 256]; s += v[r]; }
    float mean = block_sum(s, red) / D;
    float qv = 0.f;
#pragma unroll
    for (int r = 0; r < 3; r++) { float d = v[r] - mean; qv += d * d; }
    float var = block_sum(qv, red) / D;
    float inv = rsqrtf(var + 1e-5f);
#pragma unroll
    for (int r = 0; r < 3; r++) {
        int j = tid + r * 256;
        out[(long)n * D + j] = (v[r] - mean) * inv * g[j] + b[j];
    }
}

__global__ void routing_k(const float* __restrict__ trh, const float* __restrict__ w2,
                          const float* __restrict__ b2, const float* __restrict__ mun,
                          const float* __restrict__ evw, const float* __restrict__ evb,
                          float* __restrict__ pi)
{
    __shared__ float sh[1536];
    __shared__ float smn[D];
    __shared__ float kz[36];
    __shared__ float ev[6];
    __shared__ float spi[6];
    int n = blockIdx.x, tid = threadIdx.x;
    for (int i = tid; i < 1536; i += 128) sh[i] = trh[(long)n * 1536 + i];
    for (int i = tid; i < D; i += 128)    smn[i] = mun[(long)n * D + i];
    if (tid < NS) spi[tid] = pi[n * NS + tid];
    __syncthreads();
    if (tid < 36) {
        float acc = b2[tid];
        for (int k = 0; k < 1536; k++) acc += sh[k] * w2[k * 36 + tid];
        kz[tid] = acc;
    } else if (tid < 42) {
        int j = tid - 36;
        float acc = evb[j];
        for (int k = 0; k < D; k++) acc += smn[k] * evw[k * NS + j];
        ev[j] = acc;
    }
    __syncthreads();
    if (tid == 0) {
        float Kr[6][6];
        for (int s = 0; s < 6; s++) {
            float mx = kz[s * 6];
            for (int u = 1; u < 6; u++) mx = fmaxf(mx, kz[s * 6 + u]);
            float sum = 0.f;
            for (int u = 0; u < 6; u++) { float e = expf(kz[s * 6 + u] - mx); Kr[s][u] = e; sum += e; }
            float invr = 1.f / sum;
            for (int u = 0; u < 6; u++) Kr[s][u] *= invr;
        }
        float pev[6];
        for (int u = 0; u < 6; u++) {
            float a = 0.f;
            for (int s = 0; s < 6; s++) a += spi[s] * Kr[s][u];
            pev[u] = a;
        }
        float mx = ev[0] * 2.f;
        for (int u = 1; u < 6; u++) mx = fmaxf(mx, ev[u] * 2.f);
        float wv[6], sw = 0.f;
        for (int u = 0; u < 6; u++) { wv[u] = expf(ev[u] * 2.f - mx); sw += wv[u]; }
        float invw = 1.f / sw;
        float pn[6], s1 = 0.f;
        for (int u = 0; u < 6; u++) { pn[u] = pev[u] * wv[u] * invw; s1 += pn[u]; }
        float inv1 = 1.f / fmaxf(s1, 1e-8f);
        for (int u = 0; u < 6; u++) pn[u] *= inv1;
        int i1 = 0;
        for (int u = 1; u < 6; u++) if (pn[u] > pn[i1]) i1 = u;
        int i2 = (i1 == 0) ? 1 : 0;
        for (int u = 0; u < 6; u++) if (u != i1 && pn[u] > pn[i2]) i2 = u;
        float inv2 = 1.f / fmaxf(pn[i1] + pn[i2], 1e-8f);
        for (int u = 0; u < 6; u++)
            pi[n * NS + u] = (u == i1 || u == i2) ? pn[u] * inv2 : 0.f;
    }
}

__global__ void attn_k(const float* __restrict__ q, const float* __restrict__ k,
                       const float* __restrict__ v, const float* __restrict__ pi,
                       const float* __restrict__ ln_g, const float* __restrict__ ln_b,
                       float* __restrict__ msg)
{
    __shared__ float sw[4];
    __shared__ float mb[D];
    __shared__ float red[8];
    int n = blockIdx.x, tid = threadIdx.x;
    int t = n % TSEQ;
    int warp = tid >> 5, lane = tid & 31;
    const int offs[4] = {-2, -1, 1, 2};
    {
        int o = offs[warp];
        int tt = t + o;
        float dot = 0.f;
        if (tt >= 0 && tt < TSEQ) {
            const float* qp = q + (long)n * D;
            const float* kp = k + (long)(n + o) * D;
            for (int j = lane; j < D; j += 32) dot += qp[j] * kp[j];
        }
#pragma unroll
        for (int s = 16; s > 0; s >>= 1) dot += __shfl_xor_sync(0xffffffffu, dot, s);
        if (lane == 0)
            sw[warp] = (tt >= 0 && tt < TSEQ) ? dot / 27.712812921102035f : -1e9f;
    }
    __syncthreads();
    float w0 = sw[0], w1 = sw[1], w2 = sw[2], w3 = sw[3];
    float mx = fmaxf(fmaxf(w0, w1), fmaxf(w2, w3));
    float wt[4] = {expf(w0 - mx), expf(w1 - mx), expf(w2 - mx), expf(w3 - mx)};
    float invs = 1.f / (wt[0] + wt[1] + wt[2] + wt[3]);
#pragma unroll
    for (int w = 0; w < 4; w++) wt[w] *= invs;
    float pi3 = pi[n * NS + 3];
    for (int j = tid; j < D; j += 128) {
        float m = 0.f;
#pragma unroll
        for (int w = 0; w < 4; w++) {
            int tt = t + offs[w];
            if (tt >= 0 && tt < TSEQ) m += wt[w] * v[(long)(n + offs[w]) * D + j];
        }
        mb[j] = m * pi3;
    }
    __syncthreads();
    float loc[6], s = 0.f;
#pragma unroll
    for (int r = 0; r < 6; r++) { loc[r] = mb[tid + r * 128]; s += loc[r]; }
    float mean = block_sum(s, red) / D;
    float qv = 0.f;
#pragma unroll
    for (int r = 0; r < 6; r++) { float d = loc[r] - mean; qv += d * d; }
    float var = block_sum(qv, red) / D;
    float inv = rsqrtf(var + 1e-5f);
#pragma unroll
    for (int r = 0; r < 6; r++) {
        int j = tid + r * 128;
        msg[(long)n * D + j] = (loc[r] - mean) * inv * ln_g[3 * D + j] + ln_b[3 * D + j];
    }
}

__global__ void update_k(const float* __restrict__ muhat, float* __restrict__ lam,
                         const float* __restrict__ dlam, const float* __restrict__ mhat,
                         const float* __restrict__ so,
                         const float* __restrict__ ln_g, const float* __restrict__ ln_b,
                         float* __restrict__ mu)
{
    __shared__ float red[8];
    int n = blockIdx.x, tid = threadIdx.x;
    float mval[3], s = 0.f;
#pragma unroll
    for (int r = 0; r < 3; r++) {
        int j = tid + r * 256;
        long idx = (long)n * D + j;
        float l = lam[idx], dl = dlam[idx];
        float mwn = muhat[idx] * ln_g[4 * D + j] + ln_b[4 * D + j];
        float lnw = l + dl;
        float m = (l * mwn + dl * mhat[idx]) / lnw;
        lam[idx] = lnw;
        mval[r] = m;
        s += m;
    }
    float mean = block_sum(s, red) / D;
    float qv = 0.f;
#pragma unroll
    for (int r = 0; r < 3; r++) { float d = mval[r] - mean; qv += d * d; }
    float var = block_sum(qv, red) / D;
    float inv = rsqrtf(var + 1e-5f);
#pragma unroll
    for (int r = 0; r < 3; r++) {
        int j = tid + r * 256;
        long idx = (long)n * D + j;
        mu[idx] = (mval[r] - mean) * inv * ln_g[5 * D + j] + ln_b[5 * D + j] + so[idx] * 0.1f;
    }
}

// ---------------- launcher ----------------
extern "C" void kernel_launch(void* const* d_in, const int* in_sizes, int n_in,
                              void* d_out, int out_size)
{
    const int*   x        = (const int*)d_in[0];
    const float* emb_w    = (const float*)d_in[1];
    const float* pos_w    = (const float*)d_in[2];
    const float* mu_w     = (const float*)d_in[3];
    const float* mu_b     = (const float*)d_in[4];
    const float* lam_w    = (const float*)d_in[5];
    const float* lam_b    = (const float*)d_in[6];
    const float* tr_w1    = (const float*)d_in[7];
    const float* tr_b1    = (const float*)d_in[8];
    const float* tr_w2    = (const float*)d_in[9];
    const float* tr_b2    = (const float*)d_in[10];
    const float* bank_w1  = (const float*)d_in[11];
    const float* bank_b1  = (const float*)d_in[12];
    const float* bank_w2  = (const float*)d_in[13];
    const float* bank_b2  = (const float*)d_in[14];
    const float* ev_w     = (const float*)d_in[15];
    const float* ev_b     = (const float*)d_in[16];
    const float* rt_q     = (const float*)d_in[17];
    const float* rt_k     = (const float*)d_in[18];
    const float* rt_v     = (const float*)d_in[19];
    const float* wr_lam_w = (const float*)d_in[20];
    const float* wr_lam_b = (const float*)d_in[21];
    const float* wr_mu_w  = (const float*)d_in[22];
    const float* wr_mu_b  = (const float*)d_in[23];
    const float* ln_g     = (const float*)d_in[24];
    const float* ln_b     = (const float*)d_in[25];
    float* out = (float*)d_out;

    cudaFuncSetAttribute(tgemm_k<EPI_GELU, false>, cudaFuncAttributeMaxDynamicSharedMemorySize, SM_BYTES);
    cudaFuncSetAttribute(tgemm_k<EPI_SCALE, true>, cudaFuncAttributeMaxDynamicSharedMemorySize, SM_BYTES);
    cudaFuncSetAttribute(tgemm_pair_k<EPI_BIAS, EPI_SP01>, cudaFuncAttributeMaxDynamicSharedMemorySize, SM_BYTES);
    cudaFuncSetAttribute(tgemm_pair_k<EPI_GSP, EPI_BIAS>, cudaFuncAttributeMaxDynamicSharedMemorySize, SM_BYTES);
    cudaFuncSetAttribute(tqkv_k, cudaFuncAttributeMaxDynamicSharedMemorySize, SM_BYTES);
    cudaFuncSetAttribute(tbank1_k, cudaFuncAttributeMaxDynamicSharedMemorySize, SM_BYTES);
    cudaFuncSetAttribute(tbank2_k<0>, cudaFuncAttributeMaxDynamicSharedMemorySize, SM_BYTES);
    cudaFuncSetAttribute(tbank2_k<1>, cudaFuncAttributeMaxDynamicSharedMemorySize, SM_BYTES);

    float* base = nullptr;
    cudaGetSymbolAddress((void**)&base, g_scratch);
    float *whi = nullptr, *wlo = nullptr;
    cudaGetSymbolAddress((void**)&whi, g_whi);
    cudaGetSymbolAddress((void**)&wlo, g_wlo);
    int *cnt, *list, *cnt2, *slot2, *tok2;
    cudaGetSymbolAddress((void**)&cnt, g_cnt);
    cudaGetSymbolAddress((void**)&list, g_list);
    cudaGetSymbolAddress((void**)&cnt2, g_cnt2);
    cudaGetSymbolAddress((void**)&slot2, g_slot2);
    cudaGetSymbolAddress((void**)&tok2, g_tok2);

    float* h     = base + OFF_H;
    float* mu    = base + OFF_MU;
    float* muhat = base + OFF_MUHAT;
    float* mun   = base + OFF_MUN;
    float* mur   = base + OFF_MUR;
    float* so    = base + OFF_SO;
    float* qb    = base + OFF_Q;
    float* lam   = base + OFF_LAM;
    float* msg   = base + OFF_MSG;
    float* dlam  = base + OFF_DLAM;
    float* mhat  = base + OFF_MHAT;
    float* fin   = base + OFF_FIN;
    float* trh   = base + OFF_TRH;
    float* hb    = base + OFF_HB;
    float* pi    = base + OFF_PI;

    const float inv_sqrt_d = 0.03608439182435161f;

    // ---- weight prep: split (and transpose emb) into hi/lo arena ----
    {
        const int DD4 = D * D / 4;
        split_k<<<(DD4 + 255) / 256, 256>>>(mu_w,     whi + W_MU,  wlo + W_MU,  DD4);
        split_k<<<(DD4 + 255) / 256, 256>>>(lam_w,    whi + W_LAM, wlo + W_LAM, DD4);
        split_k<<<(D * 1536 / 4 + 255) / 256, 256>>>(tr_w1, whi + W_TR1, wlo + W_TR1, D * 1536 / 4);
        split_k<<<(DD4 + 255) / 256, 256>>>(rt_q,     whi + W_RTQ, wlo + W_RTQ, DD4);
        split_k<<<(DD4 + 255) / 256, 256>>>(rt_k,     whi + W_RTK, wlo + W_RTK, DD4);
        split_k<<<(DD4 + 255) / 256, 256>>>(rt_v,     whi + W_RTV, wlo + W_RTV, DD4);
        split_k<<<(DD4 + 255) / 256, 256>>>(wr_lam_w, whi + W_WRL, wlo + W_WRL, DD4);
        split_k<<<(DD4 + 255) / 256, 256>>>(wr_mu_w,  whi + W_WRM, wlo + W_WRM, DD4);
        const int B14 = NS * D * FFN / 4;
        split_k<<<(B14 + 255) / 256, 256>>>(bank_w1, whi + W_B1, wlo + W_B1, B14);
        split_k<<<(B14 + 255) / 256, 256>>>(bank_w2, whi + W_B2, wlo + W_B2, B14);
        dim3 gt(VOC / 32, D / 32);
        tsplit_emb_k<<<gt, dim3(32, 8)>>>(emb_w, whi + W_EMBT, wlo + W_EMBT);
    }

    emb_k<<<NTOK, 256>>>(x, emb_w, pos_w, h);
    {
        dim3 g(D / 128, NTOK / 128, 2);
        tgemm_pair_k<EPI_BIAS, EPI_SP01><<<g, 256, SM_BYTES>>>(h, whi + W_MU, wlo + W_MU,
                                                               mu_b, lam_b, nullptr, mu);
    }
    pi_init_k<<<(NTOK * NS + 255) / 256, 256>>>(pi);

    for (int step = 0; step < 3; step++) {
        ln012_k<<<NTOK, 256>>>(mu, muhat, mun, mur, ln_g, ln_b);
        {
            dim3 g(1536 / 128, NTOK / 128);
            tgemm_k<EPI_GELU, false><<<g, 256, SM_BYTES>>>(mu, whi + W_TR1, wlo + W_TR1,
                                                           tr_b1, trh, 1536, D, 1.f, nullptr);
        }
        reset_cnt_k<<<1, 32>>>(cnt, cnt2);
        build_lists_k<<<NTOK / 256, 256>>>(pi, cnt, list, cnt2, slot2, tok2);
        {
            dim3 g1(FFN / 128, NTOK / 128, NS);
            tbank1_k<<<g1, 256, SM_BYTES>>>(mun, whi + W_B1, wlo + W_B1, bank_b1, hb, list, cnt);
            dim3 g2(D / 128, NTOK / 128, NS);
            tbank2_k<0><<<g2, 256, SM_BYTES>>>(hb, whi + W_B2, wlo + W_B2, bank_b2,
                                               so, cnt2, slot2, tok2, pi);
            tbank2_k<1><<<g2, 256, SM_BYTES>>>(hb, whi + W_B2, wlo + W_B2, bank_b2,
                                               so, cnt2, slot2, tok2, pi);
        }
        ln_gen_k<<<NTOK, 256>>>(so, so, ln_g + 1 * D, ln_b + 1 * D);
        routing_k<<<NTOK, 128>>>(trh, tr_w2, tr_b2, mun, ev_w, ev_b, pi);
        {
            dim3 g(D / 128, NTOK / 128, 3);
            tqkv_k<<<g, 256, SM_BYTES>>>(mur, whi + W_RTQ, wlo + W_RTQ, qb);
        }
        attn_k<<<NTOK, 128>>>(qb, qb + ROW, qb + 2 * ROW, pi, ln_g, ln_b, msg);
        {
            dim3 g(D / 128, NTOK / 128, 2);
            tgemm_pair_k<EPI_GSP, EPI_BIAS><<<g, 256, SM_BYTES>>>(msg, whi + W_WRL, wlo + W_WRL,
                                                                  wr_lam_b, wr_mu_b, pi, dlam);
        }
        update_k<<<NTOK, 256>>>(muhat, lam, dlam, mhat, so, ln_g, ln_b, mu);
    }

    ln_gen_k<<<NTOK, 256>>>(mu, fin, ln_g + 6 * D, ln_b + 6 * D);
    {
        dim3 g(VOC / 128, NTOK / 128);
        tgemm_k<EPI_SCALE, true><<<g, 256, SM_BYTES>>>(fin, whi + W_EMBT, wlo + W_EMBT,
                                                       nullptr, out, VOC, D, inv_sqrt_d, nullptr);
    }
}

// round 12
// speedup vs baseline: 1.4080x; 1.1181x over previous
#include <cuda_runtime.h>
#include <math.h>
#include <stdint.h>

#define NTOK 2048
#define TSEQ 1024
#define D    768
#define FFN  3072
#define NS   6
#define VOC  32000

// ---------------- scratch ----------------
#define ROW (NTOK*D)
#define OFF_H     0
#define OFF_MU    (1*ROW)
#define OFF_LAM   (2*ROW)
#define OFF_MUHAT (3*ROW)
#define OFF_MUN   (4*ROW)
#define OFF_MUR   (5*ROW)
#define OFF_SO    (6*ROW)
#define OFF_Q     (7*ROW)
#define OFF_K     (8*ROW)
#define OFF_V     (9*ROW)
#define OFF_MSG   (10*ROW)
#define OFF_DLAM  (11*ROW)
#define OFF_MHAT  (12*ROW)
#define OFF_FIN   (13*ROW)
#define OFF_TRH   (14*ROW)
#define OFF_HB    (14*ROW + NTOK*1536)
#define OFF_PI    (OFF_HB + NS*NTOK*FFN)
#define SCRATCH_FLOATS (OFF_PI + NTOK*NS)

__device__ float g_scratch[SCRATCH_FLOATS];
__device__ int   g_cnt[NS];
__device__ int   g_list[NS * NTOK];
__device__ int   g_cnt2[2 * NS];
__device__ int   g_slot2[2 * NS * NTOK];
__device__ int   g_tok2[2 * NS * NTOK];

// ---------------- pre-split weight arena (hi/lo tf32 split) ----------------
#define W_MU   0
#define W_LAM  589824
#define W_TR1  1179648
#define W_RTQ  2359296
#define W_RTK  2949120
#define W_RTV  3538944
#define W_WRL  4128768
#define W_WRM  4718592
#define W_B1   5308416
#define W_B2   19464192
#define W_EMBT 33619968
#define WSPLIT 58195968

__device__ float g_whi[WSPLIT];
__device__ float g_wlo[WSPLIT];

// ---------------- helpers ----------------
__device__ __forceinline__ float gelu_f(float x) {
    float x3 = x * x * x;
    return 0.5f * x * (1.f + tanhf(0.7978845608028654f * (x + 0.044715f * x3)));
}
__device__ __forceinline__ float softplus_f(float x) {
    return fmaxf(x, 0.f) + log1pf(expf(-fabsf(x)));
}
__device__ __forceinline__ float block_sum(float v, float* red) {
    int tid = threadIdx.x;
    __syncthreads();
#pragma unroll
    for (int o = 16; o > 0; o >>= 1) v += __shfl_xor_sync(0xffffffffu, v, o);
    if ((tid & 31) == 0) red[tid >> 5] = v;
    __syncthreads();
    if (tid < 32) {
        float t = (tid < (int)(blockDim.x >> 5)) ? red[tid] : 0.f;
#pragma unroll
        for (int o = 4; o > 0; o >>= 1) t += __shfl_xor_sync(0xffffffffu, t, o);
        if (tid == 0) red[0] = t;
    }
    __syncthreads();
    return red[0];
}

__device__ __forceinline__ void cvt_split(float x, float& hi, float& lo) {
    uint32_t hb; asm("cvt.rna.tf32.f32 %0, %1;" : "=r"(hb) : "f"(x));
    hi = __uint_as_float(hb);
    float lf = x - hi;
    uint32_t lb; asm("cvt.rna.tf32.f32 %0, %1;" : "=r"(lb) : "f"(lf));
    lo = __uint_as_float(lb);
}

// ---------------- weight prep kernels ----------------
__global__ void split_k(const float* __restrict__ src, float* __restrict__ hi,
                        float* __restrict__ lo, int n4)
{
    int i = blockIdx.x * blockDim.x + threadIdx.x;
    if (i >= n4) return;
    float4 v = ((const float4*)src)[i];
    float4 h, l;
    cvt_split(v.x, h.x, l.x); cvt_split(v.y, h.y, l.y);
    cvt_split(v.z, h.z, l.z); cvt_split(v.w, h.w, l.w);
    ((float4*)hi)[i] = h;
    ((float4*)lo)[i] = l;
}

// transpose emb_w [VOC][D] -> split into [D][VOC] hi (lo unused by FAST logits,
// still produced for generality)
__global__ void tsplit_emb_k(const float* __restrict__ emb,
                             float* __restrict__ hi, float* __restrict__ lo)
{
    __shared__ float tile[32][33];
    int v0 = blockIdx.x * 32, d0 = blockIdx.y * 32;
    int tx = threadIdx.x, ty = threadIdx.y; // 32 x 8
    for (int r = ty; r < 32; r += 8)
        tile[r][tx] = emb[(long)(v0 + r) * D + d0 + tx];
    __syncthreads();
    for (int r = ty; r < 32; r += 8) {
        float hf, lf;
        cvt_split(tile[tx][r], hf, lf);
        long o = (long)(d0 + r) * VOC + v0 + tx;
        hi[o] = hf;
        lo[o] = lf;
    }
}

// ---------------- tf32 mma core ----------------
// smem (float offsets): RAWA[3][128][20] @0 (7680),
// BHI[3][16][136] @7680 (6528), BLO[3][16][136] @14208 (6528)
// total 20736 floats = 82944 B -> 2 CTAs/SM
#define A_ST    2560
#define B_STF   2176
#define SM_RAWA 0
#define SM_BHI  7680
#define SM_BLO  14208
#define SM_BYTES (20736 * 4)

__device__ __forceinline__ void mma8(float* c, const uint32_t* a, uint32_t b0, uint32_t b1) {
    asm volatile(
        "mma.sync.aligned.m16n8k8.row.col.f32.tf32.tf32.f32 "
        "{%0,%1,%2,%3},{%4,%5,%6,%7},{%8,%9},{%0,%1,%2,%3};"
        : "+f"(c[0]), "+f"(c[1]), "+f"(c[2]), "+f"(c[3])
        : "r"(a[0]), "r"(a[1]), "r"(a[2]), "r"(a[3]), "r"(b0), "r"(b1));
}

__device__ __forceinline__ void cp16(uint32_t dst, const float* src) {
    asm volatile("cp.async.ca.shared.global [%0], [%1], 16;" :: "r"(dst), "l"(src) : "memory");
}

// block 128x128, 8 warps (4m x 2n), warp tile 32x64, BK=16.
// Raw A (fp32, read ONCE from gmem) + pre-split B, 3-stage rings, ONE barrier
// per slice. A's hi/lo split happens inline in comp (registers).
// FAST: 2-term split ah*bh + al*bh; Blo is NEVER loaded (halves B traffic).
// ONLY legal where the GEMM's error cannot reach a top-k routing decision:
// the final logits GEMM and the last-step bank/qkv/wr GEMMs (their outputs
// flow only through smooth ops into the final output).
template <bool GATHER, bool FAST>
__device__ __forceinline__ void tf32_loop(
    const float* __restrict__ A, const float* __restrict__ Bhi,
    const float* __restrict__ Blo,
    int K, int N, int bm0, int bn0, const int* __restrict__ rowTok,
    float* __restrict__ sm, float c[2][8][4])
{
    const int tid = threadIdx.x;
    const int lane = tid & 31, warp = tid >> 5;
    const int wm0 = (warp >> 1) * 32, wn0 = (warp & 1) * 64;
    const int g = lane >> 2, tig = lane & 3;

    const int arow0 = tid >> 2, arow1 = arow0 + 64, aq = tid & 3;
    long agr0, agr1;
    if (GATHER) { agr0 = rowTok[arow0]; agr1 = rowTok[arow1]; }
    else        { agr0 = bm0 + arow0;   agr1 = bm0 + arow1;   }
    const int bkr = tid >> 5;
    const int bn4 = (tid & 31) * 4;

    const uint32_t smb = (uint32_t)__cvta_generic_to_shared(sm);

    auto issue = [&](int st, int k0) {
        uint32_t ra = smb + (uint32_t)(SM_RAWA + st * A_ST) * 4u;
        cp16(ra + (uint32_t)(arow0 * 20 + aq * 4) * 4u, A + agr0 * K + k0 + aq * 4);
        cp16(ra + (uint32_t)(arow1 * 20 + aq * 4) * 4u, A + agr1 * K + k0 + aq * 4);
        uint32_t bh = smb + (uint32_t)(SM_BHI + st * B_STF) * 4u;
        cp16(bh + (uint32_t)(bkr * 136 + bn4) * 4u,
             Bhi + (long)(k0 + bkr) * N + bn0 + bn4);
        cp16(bh + (uint32_t)((bkr + 8) * 136 + bn4) * 4u,
             Bhi + (long)(k0 + bkr + 8) * N + bn0 + bn4);
        if (!FAST) {
            uint32_t bl = smb + (uint32_t)(SM_BLO + st * B_STF) * 4u;
            cp16(bl + (uint32_t)(bkr * 136 + bn4) * 4u,
                 Blo + (long)(k0 + bkr) * N + bn0 + bn4);
            cp16(bl + (uint32_t)((bkr + 8) * 136 + bn4) * 4u,
                 Blo + (long)(k0 + bkr + 8) * N + bn0 + bn4);
        }
        asm volatile("cp.async.commit_group;" ::: "memory");
    };

    auto comp = [&](int st) {
        const float* rap = sm + SM_RAWA + st * A_ST;
        const float* bhp = sm + SM_BHI + st * B_STF;
        const float* blp = sm + SM_BLO + st * B_STF;
#pragma unroll
        for (int ks = 0; ks < 16; ks += 8) {
            uint32_t ah[2][4], al[2][4];
#pragma unroll
            for (int mt = 0; mt < 2; mt++) {
                int rb = wm0 + mt * 16 + g;
                float r0 = rap[rb * 20 + ks + tig];
                float r1 = rap[(rb + 8) * 20 + ks + tig];
                float r2 = rap[rb * 20 + ks + tig + 4];
                float r3 = rap[(rb + 8) * 20 + ks + tig + 4];
                float hf, lf;
                cvt_split(r0, hf, lf); ah[mt][0] = __float_as_uint(hf); al[mt][0] = __float_as_uint(lf);
                cvt_split(r1, hf, lf); ah[mt][1] = __float_as_uint(hf); al[mt][1] = __float_as_uint(lf);
                cvt_split(r2, hf, lf); ah[mt][2] = __float_as_uint(hf); al[mt][2] = __float_as_uint(lf);
                cvt_split(r3, hf, lf); ah[mt][3] = __float_as_uint(hf); al[mt][3] = __float_as_uint(lf);
            }
#pragma unroll
            for (int nt = 0; nt < 8; nt++) {
                int cb = wn0 + nt * 8 + g;
                uint32_t bh0 = __float_as_uint(bhp[(ks + tig) * 136 + cb]);
                uint32_t bh1 = __float_as_uint(bhp[(ks + tig + 4) * 136 + cb]);
#pragma unroll
                for (int mt = 0; mt < 2; mt++) {
                    mma8(c[mt][nt], ah[mt], bh0, bh1);
                    mma8(c[mt][nt], al[mt], bh0, bh1);
                }
                if (!FAST) {
                    uint32_t bl0 = __float_as_uint(blp[(ks + tig) * 136 + cb]);
                    uint32_t bl1 = __float_as_uint(blp[(ks + tig + 4) * 136 + cb]);
#pragma unroll
                    for (int mt = 0; mt < 2; mt++)
                        mma8(c[mt][nt], ah[mt], bl0, bl1);
                }
            }
        }
    };

    const int nk = K >> 4;  // >= 48 at all call sites
    issue(0, 0);
    issue(1, 16);
    int st = 0, stn = 2;
    for (int i = 0; i < nk; i++) {
        if (i < nk - 1) asm volatile("cp.async.wait_group 1;" ::: "memory");
        else            asm volatile("cp.async.wait_group 0;" ::: "memory");
        __syncthreads();
        if (i + 2 < nk) {
            issue(stn, (i + 2) << 4);
            stn = (stn == 2) ? 0 : stn + 1;
        }
        comp(st);
        st = (st == 2) ? 0 : st + 1;
    }
}

// ---------------- epilogues ----------------
enum { EPI_NONE = 0, EPI_BIAS = 1, EPI_GELU = 2, EPI_GSP = 3, EPI_SCALE = 4, EPI_SP01 = 5 };

template <int EPI>
__device__ __forceinline__ float epi_apply(float v, float b, float rs, float alpha) {
    if (EPI == EPI_BIAS)  return v + b;
    if (EPI == EPI_GELU)  return gelu_f(v + b);
    if (EPI == EPI_GSP)   return rs * softplus_f(v + b);
    if (EPI == EPI_SCALE) return v * alpha;
    if (EPI == EPI_SP01)  return softplus_f(v + b) + 0.1f;
    return v;
}

template <int EPI>
__device__ __forceinline__ void epi_store_dense(
    float c[2][8][4], float* __restrict__ C, const float* __restrict__ bias,
    int N, int bm0, int bn0, const float* __restrict__ pi, float alpha)
{
    const int tid = threadIdx.x, lane = tid & 31, warp = tid >> 5;
    const int wm0 = (warp >> 1) * 32, wn0 = (warp & 1) * 64;
    const int g = lane >> 2, tig = lane & 3;
    const int colbase = bn0 + wn0;
#pragma unroll
    for (int mt = 0; mt < 2; mt++) {
#pragma unroll
        for (int half = 0; half < 2; half++) {
            int row = bm0 + wm0 + mt * 16 + g + half * 8;
            float rs = (EPI == EPI_GSP) ? pi[row * NS + 4] : 0.f;
            float* cp = C + (long)row * N + colbase;
#pragma unroll
            for (int nt = 0; nt < 8; nt++) {
                int col = nt * 8 + tig * 2;
                float b0 = 0.f, b1 = 0.f;
                if (EPI == EPI_BIAS || EPI == EPI_GELU || EPI == EPI_GSP || EPI == EPI_SP01) {
                    b0 = bias[colbase + col];
                    b1 = bias[colbase + col + 1];
                }
                float v0 = epi_apply<EPI>(c[mt][nt][half * 2], b0, rs, alpha);
                float v1 = epi_apply<EPI>(c[mt][nt][half * 2 + 1], b1, rs, alpha);
                *(float2*)(cp + col) = make_float2(v0, v1);
            }
        }
    }
}

// ---------------- GEMM kernels ----------------
template <int EPI, bool FAST>
__global__ void __launch_bounds__(256, 2) tgemm_k(
    const float* __restrict__ A, const float* __restrict__ Bhi,
    const float* __restrict__ Blo, const float* __restrict__ bias,
    float* __restrict__ C, int N, int K, float alpha,
    const float* __restrict__ pi)
{
    extern __shared__ float sm[];
    const int bm0 = blockIdx.y * 128, bn0 = blockIdx.x * 128;
    float c[2][8][4];
#pragma unroll
    for (int a = 0; a < 2; a++)
#pragma unroll
        for (int b = 0; b < 8; b++)
#pragma unroll
            for (int r = 0; r < 4; r++) c[a][b][r] = 0.f;
    tf32_loop<false, FAST>(A, Bhi, Blo, K, N, bm0, bn0, nullptr, sm, c);
    epi_store_dense<EPI>(c, C, bias, N, bm0, bn0, pi, alpha);
}

// z-pair over adjacent arena weights (stride D*D)
template <int EPI0, int EPI1, bool FAST>
__global__ void __launch_bounds__(256, 2) tgemm_pair_k(
    const float* __restrict__ A, const float* __restrict__ Whi,
    const float* __restrict__ Wlo, const float* __restrict__ b0,
    const float* __restrict__ b1, const float* __restrict__ pi,
    float* __restrict__ Cbase)
{
    extern __shared__ float sm[];
    const int z = blockIdx.z;
    const float* Bhi = Whi + (long)z * D * D;
    const float* Blo = Wlo + (long)z * D * D;
    const float* bias = z ? b1 : b0;
    float* C = Cbase + (long)z * ROW;
    const int bm0 = blockIdx.y * 128, bn0 = blockIdx.x * 128;
    float c[2][8][4];
#pragma unroll
    for (int a = 0; a < 2; a++)
#pragma unroll
        for (int b = 0; b < 8; b++)
#pragma unroll
            for (int r = 0; r < 4; r++) c[a][b][r] = 0.f;
    tf32_loop<false, FAST>(A, Bhi, Blo, D, D, bm0, bn0, nullptr, sm, c);
    if (z == 0) epi_store_dense<EPI0>(c, C, bias, D, bm0, bn0, pi, 1.f);
    else        epi_store_dense<EPI1>(c, C, bias, D, bm0, bn0, pi, 1.f);
}

template <bool FAST>
__global__ void __launch_bounds__(256, 2) tqkv_k(
    const float* __restrict__ A, const float* __restrict__ Whi,
    const float* __restrict__ Wlo, float* __restrict__ Cbase)
{
    extern __shared__ float sm[];
    const int z = blockIdx.z;
    const float* Bhi = Whi + (long)z * D * D;
    const float* Blo = Wlo + (long)z * D * D;
    float* C = Cbase + (long)z * ROW;
    const int bm0 = blockIdx.y * 128, bn0 = blockIdx.x * 128;
    float c[2][8][4];
#pragma unroll
    for (int a = 0; a < 2; a++)
#pragma unroll
        for (int b = 0; b < 8; b++)
#pragma unroll
            for (int r = 0; r < 4; r++) c[a][b][r] = 0.f;
    tf32_loop<false, FAST>(A, Bhi, Blo, D, D, bm0, bn0, nullptr, sm, c);
    epi_store_dense<EPI_NONE>(c, C, nullptr, D, bm0, bn0, nullptr, 1.f);
}

template <bool FAST>
__global__ void __launch_bounds__(256, 2) tbank1_k(
    const float* __restrict__ A, const float* __restrict__ Whi,
    const float* __restrict__ Wlo, const float* __restrict__ b1all,
    float* __restrict__ hb, const int* __restrict__ list,
    const int* __restrict__ cnt)
{
    extern __shared__ float sm[];
    __shared__ int rowTok[128];
    const int s = blockIdx.z;
    const int cn = cnt[s];
    const int bm0 = blockIdx.y * 128;
    if (bm0 >= cn) return;
    const int tid = threadIdx.x;
    if (tid < 128) rowTok[tid] = list[s * NTOK + min(bm0 + tid, cn - 1)];
    __syncthreads();

    const float* Bhi = Whi + (long)s * D * FFN;
    const float* Blo = Wlo + (long)s * D * FFN;
    const float* bias = b1all + s * FFN;
    float* C = hb + (long)s * NTOK * FFN;
    const int bn0 = blockIdx.x * 128;

    float c[2][8][4];
#pragma unroll
    for (int a = 0; a < 2; a++)
#pragma unroll
        for (int b = 0; b < 8; b++)
#pragma unroll
            for (int r = 0; r < 4; r++) c[a][b][r] = 0.f;
    tf32_loop<true, FAST>(A, Bhi, Blo, D, FFN, 0, bn0, rowTok, sm, c);

    const int lane = tid & 31, warp = tid >> 5;
    const int wm0 = (warp >> 1) * 32, wn0 = (warp & 1) * 64;
    const int g = lane >> 2, tig = lane & 3;
    const int colbase = bn0 + wn0;
#pragma unroll
    for (int mt = 0; mt < 2; mt++) {
#pragma unroll
        for (int half = 0; half < 2; half++) {
            int slot = bm0 + wm0 + mt * 16 + g + half * 8;
            if (slot >= cn) continue;
            float* cp = C + (long)slot * FFN + colbase;
#pragma unroll
            for (int nt = 0; nt < 8; nt++) {
                int col = nt * 8 + tig * 2;
                float v0 = gelu_f(c[mt][nt][half * 2] + bias[colbase + col]);
                float v1 = gelu_f(c[mt][nt][half * 2 + 1] + bias[colbase + col + 1]);
                *(float2*)(cp + col) = make_float2(v0, v1);
            }
        }
    }
}

template <int RANK, bool FAST>
__global__ void __launch_bounds__(256, 2) tbank2_k(
    const float* __restrict__ hb, const float* __restrict__ Whi,
    const float* __restrict__ Wlo, const float* __restrict__ b2all,
    float* __restrict__ so, const int* __restrict__ cnt2,
    const int* __restrict__ slot2, const int* __restrict__ tok2,
    const float* __restrict__ pi)
{
    extern __shared__ float sm[];
    __shared__ int rowSlot[128];
    const int s = blockIdx.z;
    const int cn = cnt2[RANK * NS + s];
    const int bm0 = blockIdx.y * 128;
    if (bm0 >= cn) return;
    const int tid = threadIdx.x;
    const int lbase = (RANK * NS + s) * NTOK;
    if (tid < 128) rowSlot[tid] = slot2[lbase + min(bm0 + tid, cn - 1)];
    __syncthreads();

    const float* A = hb + (long)s * NTOK * FFN;
    const float* Bhi = Whi + (long)s * FFN * D;
    const float* Blo = Wlo + (long)s * FFN * D;
    const float* bias = b2all + s * D;
    const int bn0 = blockIdx.x * 128;

    float c[2][8][4];
#pragma unroll
    for (int a = 0; a < 2; a++)
#pragma unroll
        for (int b = 0; b < 8; b++)
#pragma unroll
            for (int r = 0; r < 4; r++) c[a][b][r] = 0.f;
    tf32_loop<true, FAST>(A, Bhi, Blo, FFN, D, 0, bn0, rowSlot, sm, c);

    const int lane = tid & 31, warp = tid >> 5;
    const int wm0 = (warp >> 1) * 32, wn0 = (warp & 1) * 64;
    const int g = lane >> 2, tig = lane & 3;
    const int colbase = bn0 + wn0;
#pragma unroll
    for (int mt = 0; mt < 2; mt++) {
#pragma unroll
        for (int half = 0; half < 2; half++) {
            int idx = bm0 + wm0 + mt * 16 + g + half * 8;
            if (idx >= cn) continue;
            int tok = tok2[lbase + idx];
            float rs = pi[tok * NS + s];
            float* cp = so + (long)tok * D + colbase;
#pragma unroll
            for (int nt = 0; nt < 8; nt++) {
                int col = nt * 8 + tig * 2;
                float v0 = rs * (c[mt][nt][half * 2] + bias[colbase + col]);
                float v1 = rs * (c[mt][nt][half * 2 + 1] + bias[colbase + col + 1]);
                if (RANK == 0) {
                    *(float2*)(cp + col) = make_float2(v0, v1);
                } else {
                    float2 old = *(float2*)(cp + col);
                    *(float2*)(cp + col) = make_float2(old.x + v0, old.y + v1);
                }
            }
        }
    }
}

// ---------------- small kernels ----------------
__global__ void emb_k(const int* __restrict__ x, const float* __restrict__ emb,
                      const float* __restrict__ pos, float* __restrict__ h)
{
    int n = blockIdx.x;
    int vx = x[n];
    int t = n % TSEQ;
    const float* e = emb + (long)vx * D;
    const float* p = pos + (long)t * D;
    for (int j = threadIdx.x; j < D; j += blockDim.x)
        h[(long)n * D + j] = e[j] + p[j];
}

__global__ void pi_init_k(float* __restrict__ pi)
{
    int i = blockIdx.x * blockDim.x + threadIdx.x;
    if (i < NTOK * NS) pi[i] = ((i % NS) == 2) ? 1.f : 0.f;
}

__global__ void reset_cnt_k(int* cnt, int* cnt2)
{
    if (threadIdx.x < NS) cnt[threadIdx.x] = 0;
    if (threadIdx.x < 2 * NS) cnt2[threadIdx.x] = 0;
}

__global__ void build_lists_k(const float* __restrict__ pi,
                              int* __restrict__ cnt, int* __restrict__ list,
                              int* __restrict__ cnt2, int* __restrict__ slot2,
                              int* __restrict__ tok2)
{
    int t = blockIdx.x * blockDim.x + threadIdx.x;
    if (t >= NTOK) return;
    int r = 0;
#pragma unroll
    for (int s = 0; s < NS; s++) {
        if (pi[t * NS + s] != 0.f) {
            int p = atomicAdd(&cnt[s], 1);
            list[s * NTOK + p] = t;
            int rr = min(r, 1);
            int q = atomicAdd(&cnt2[rr * NS + s], 1);
            slot2[(rr * NS + s) * NTOK + q] = p;
            tok2[(rr * NS + s) * NTOK + q] = t;
            r++;
        }
    }
}

__global__ void ln012_k(const float* __restrict__ mu, float* __restrict__ muhat,
                        float* __restrict__ mun, float* __restrict__ mur,
                        const float* __restrict__ ln_g, const float* __restrict__ ln_b)
{
    __shared__ float red[8];
    int n = blockIdx.x, tid = threadIdx.x;
    const float* row = mu + (long)n * D;
    float v[3], s = 0.f;
#pragma unroll
    for (int r = 0; r < 3; r++) { v[r] = row[tid + r * 256]; s += v[r]; }
    float mean = block_sum(s, red) / D;
    float qv = 0.f;
#pragma unroll
    for (int r = 0; r < 3; r++) { float d = v[r] - mean; qv += d * d; }
    float var = block_sum(qv, red) / D;
    float inv = rsqrtf(var + 1e-5f);
#pragma unroll
    for (int r = 0; r < 3; r++) {
        int j = tid + r * 256;
        float nh = (v[r] - mean) * inv;
        long idx = (long)n * D + j;
        muhat[idx] = nh;
        mun[idx] = nh * ln_g[j] + ln_b[j];
        mur[idx] = nh * ln_g[2 * D + j] + ln_b[2 * D + j];
    }
}

__global__ void ln_gen_k(const float* __restrict__ in, float* __restrict__ out,
                         const float* __restrict__ g, const float* __restrict__ b)
{
    __shared__ float red[8];
    int n = blockIdx.x, tid = threadIdx.x;
    const float* row = in + (long)n * D;
    float v[3], s = 0.f;
#pragma unroll
    for (int r = 0; r < 3; r++) { v[r] = row[tid + r * 256]; s += v[r]; }
    float mean = block_sum(s, red) / D;
    float qv = 0.f;
#pragma unroll
    for (int r = 0; r < 3; r++) { float d = v[r] - mean; qv += d * d; }
    float var = block_sum(qv, red) / D;
    float inv = rsqrtf(var + 1e-5f);
#pragma unroll
    for (int r = 0; r < 3; r++) {
        int j = tid + r * 256;
        out[(long)n * D + j] = (v[r] - mean) * inv * g[j] + b[j];
    }
}

__global__ void routing_k(const float* __restrict__ trh, const float* __restrict__ w2,
                          const float* __restrict__ b2, const float* __restrict__ mun,
                          const float* __restrict__ evw, const float* __restrict__ evb,
                          float* __restrict__ pi)
{
    __shared__ float sh[1536];
    __shared__ float smn[D];
    __shared__ float kz[36];
    __shared__ float ev[6];
    __shared__ float spi[6];
    int n = blockIdx.x, tid = threadIdx.x;
    for (int i = tid; i < 1536; i += 128) sh[i] = trh[(long)n * 1536 + i];
    for (int i = tid; i < D; i += 128)    smn[i] = mun[(long)n * D + i];
    if (tid < NS) spi[tid] = pi[n * NS + tid];
    __syncthreads();
    if (tid < 36) {
        float acc = b2[tid];
        for (int k = 0; k < 1536; k++) acc += sh[k] * w2[k * 36 + tid];
        kz[tid] = acc;
    } else if (tid < 42) {
        int j = tid - 36;
        float acc = evb[j];
        for (int k = 0; k < D; k++) acc += smn[k] * evw[k * NS + j];
        ev[j] = acc;
    }
    __syncthreads();
    if (tid == 0) {
        float Kr[6][6];
        for (int s = 0; s < 6; s++) {
            float mx = kz[s * 6];
            for (int u = 1; u < 6; u++) mx = fmaxf(mx, kz[s * 6 + u]);
            float sum = 0.f;
            for (int u = 0; u < 6; u++) { float e = expf(kz[s * 6 + u] - mx); Kr[s][u] = e; sum += e; }
            float invr = 1.f / sum;
            for (int u = 0; u < 6; u++) Kr[s][u] *= invr;
        }
        float pev[6];
        for (int u = 0; u < 6; u++) {
            float a = 0.f;
            for (int s = 0; s < 6; s++) a += spi[s] * Kr[s][u];
            pev[u] = a;
        }
        float mx = ev[0] * 2.f;
        for (int u = 1; u < 6; u++) mx = fmaxf(mx, ev[u] * 2.f);
        float wv[6], sw = 0.f;
        for (int u = 0; u < 6; u++) { wv[u] = expf(ev[u] * 2.f - mx); sw += wv[u]; }
        float invw = 1.f / sw;
        float pn[6], s1 = 0.f;
        for (int u = 0; u < 6; u++) { pn[u] = pev[u] * wv[u] * invw; s1 += pn[u]; }
        float inv1 = 1.f / fmaxf(s1, 1e-8f);
        for (int u = 0; u < 6; u++) pn[u] *= inv1;
        int i1 = 0;
        for (int u = 1; u < 6; u++) if (pn[u] > pn[i1]) i1 = u;
        int i2 = (i1 == 0) ? 1 : 0;
        for (int u = 0; u < 6; u++) if (u != i1 && pn[u] > pn[i2]) i2 = u;
        float inv2 = 1.f / fmaxf(pn[i1] + pn[i2], 1e-8f);
        for (int u = 0; u < 6; u++)
            pi[n * NS + u] = (u == i1 || u == i2) ? pn[u] * inv2 : 0.f;
    }
}

__global__ void attn_k(const float* __restrict__ q, const float* __restrict__ k,
                       const float* __restrict__ v, const float* __restrict__ pi,
                       const float* __restrict__ ln_g, const float* __restrict__ ln_b,
                       float* __restrict__ msg)
{
    __shared__ float sw[4];
    __shared__ float mb[D];
    __shared__ float red[8];
    int n = blockIdx.x, tid = threadIdx.x;
    int t = n % TSEQ;
    int warp = tid >> 5, lane = tid & 31;
    const int offs[4] = {-2, -1, 1, 2};
    {
        int o = offs[warp];
        int tt = t + o;
        float dot = 0.f;
        if (tt >= 0 && tt < TSEQ) {
            const float* qp = q + (long)n * D;
            const float* kp = k + (long)(n + o) * D;
            for (int j = lane; j < D; j += 32) dot += qp[j] * kp[j];
        }
#pragma unroll
        for (int s = 16; s > 0; s >>= 1) dot += __shfl_xor_sync(0xffffffffu, dot, s);
        if (lane == 0)
            sw[warp] = (tt >= 0 && tt < TSEQ) ? dot / 27.712812921102035f : -1e9f;
    }
    __syncthreads();
    float w0 = sw[0], w1 = sw[1], w2 = sw[2], w3 = sw[3];
    float mx = fmaxf(fmaxf(w0, w1), fmaxf(w2, w3));
    float wt[4] = {expf(w0 - mx), expf(w1 - mx), expf(w2 - mx), expf(w3 - mx)};
    float invs = 1.f / (wt[0] + wt[1] + wt[2] + wt[3]);
#pragma unroll
    for (int w = 0; w < 4; w++) wt[w] *= invs;
    float pi3 = pi[n * NS + 3];
    for (int j = tid; j < D; j += 128) {
        float m = 0.f;
#pragma unroll
        for (int w = 0; w < 4; w++) {
            int tt = t + offs[w];
            if (tt >= 0 && tt < TSEQ) m += wt[w] * v[(long)(n + offs[w]) * D + j];
        }
        mb[j] = m * pi3;
    }
    __syncthreads();
    float loc[6], s = 0.f;
#pragma unroll
    for (int r = 0; r < 6; r++) { loc[r] = mb[tid + r * 128]; s += loc[r]; }
    float mean = block_sum(s, red) / D;
    float qv = 0.f;
#pragma unroll
    for (int r = 0; r < 6; r++) { float d = loc[r] - mean; qv += d * d; }
    float var = block_sum(qv, red) / D;
    float inv = rsqrtf(var + 1e-5f);
#pragma unroll
    for (int r = 0; r < 6; r++) {
        int j = tid + r * 128;
        msg[(long)n * D + j] = (loc[r] - mean) * inv * ln_g[3 * D + j] + ln_b[3 * D + j];
    }
}

__global__ void update_k(const float* __restrict__ muhat, float* __restrict__ lam,
                         const float* __restrict__ dlam, const float* __restrict__ mhat,
                         const float* __restrict__ so,
                         const float* __restrict__ ln_g, const float* __restrict__ ln_b,
                         float* __restrict__ mu)
{
    __shared__ float red[8];
    int n = blockIdx.x, tid = threadIdx.x;
    float mval[3], s = 0.f;
#pragma unroll
    for (int r = 0; r < 3; r++) {
        int j = tid + r * 256;
        long idx = (long)n * D + j;
        float l = lam[idx], dl = dlam[idx];
        float mwn = muhat[idx] * ln_g[4 * D + j] + ln_b[4 * D + j];
        float lnw = l + dl;
        float m = (l * mwn + dl * mhat[idx]) / lnw;
        lam[idx] = lnw;
        mval[r] = m;
        s += m;
    }
    float mean = block_sum(s, red) / D;
    float qv = 0.f;
#pragma unroll
    for (int r = 0; r < 3; r++) { float d = mval[r] - mean; qv += d * d; }
    float var = block_sum(qv, red) / D;
    float inv = rsqrtf(var + 1e-5f);
#pragma unroll
    for (int r = 0; r < 3; r++) {
        int j = tid + r * 256;
        long idx = (long)n * D + j;
        mu[idx] = (mval[r] - mean) * inv * ln_g[5 * D + j] + ln_b[5 * D + j] + so[idx] * 0.1f;
    }
}

// ---------------- launcher ----------------
extern "C" void kernel_launch(void* const* d_in, const int* in_sizes, int n_in,
                              void* d_out, int out_size)
{
    const int*   x        = (const int*)d_in[0];
    const float* emb_w    = (const float*)d_in[1];
    const float* pos_w    = (const float*)d_in[2];
    const float* mu_w     = (const float*)d_in[3];
    const float* mu_b     = (const float*)d_in[4];
    const float* lam_w    = (const float*)d_in[5];
    const float* lam_b    = (const float*)d_in[6];
    const float* tr_w1    = (const float*)d_in[7];
    const float* tr_b1    = (const float*)d_in[8];
    const float* tr_w2    = (const float*)d_in[9];
    const float* tr_b2    = (const float*)d_in[10];
    const float* bank_w1  = (const float*)d_in[11];
    const float* bank_b1  = (const float*)d_in[12];
    const float* bank_w2  = (const float*)d_in[13];
    const float* bank_b2  = (const float*)d_in[14];
    const float* ev_w     = (const float*)d_in[15];
    const float* ev_b     = (const float*)d_in[16];
    const float* rt_q     = (const float*)d_in[17];
    const float* rt_k     = (const float*)d_in[18];
    const float* rt_v     = (const float*)d_in[19];
    const float* wr_lam_w = (const float*)d_in[20];
    const float* wr_lam_b = (const float*)d_in[21];
    const float* wr_mu_w  = (const float*)d_in[22];
    const float* wr_mu_b  = (const float*)d_in[23];
    const float* ln_g     = (const float*)d_in[24];
    const float* ln_b     = (const float*)d_in[25];
    float* out = (float*)d_out;

    cudaFuncSetAttribute(tgemm_k<EPI_GELU, false>, cudaFuncAttributeMaxDynamicSharedMemorySize, SM_BYTES);
    cudaFuncSetAttribute(tgemm_k<EPI_SCALE, true>, cudaFuncAttributeMaxDynamicSharedMemorySize, SM_BYTES);
    cudaFuncSetAttribute(tgemm_pair_k<EPI_BIAS, EPI_SP01, false>, cudaFuncAttributeMaxDynamicSharedMemorySize, SM_BYTES);
    cudaFuncSetAttribute(tgemm_pair_k<EPI_GSP, EPI_BIAS, false>, cudaFuncAttributeMaxDynamicSharedMemorySize, SM_BYTES);
    cudaFuncSetAttribute(tgemm_pair_k<EPI_GSP, EPI_BIAS, true>, cudaFuncAttributeMaxDynamicSharedMemorySize, SM_BYTES);
    cudaFuncSetAttribute(tqkv_k<false>, cudaFuncAttributeMaxDynamicSharedMemorySize, SM_BYTES);
    cudaFuncSetAttribute(tqkv_k<true>, cudaFuncAttributeMaxDynamicSharedMemorySize, SM_BYTES);
    cudaFuncSetAttribute(tbank1_k<false>, cudaFuncAttributeMaxDynamicSharedMemorySize, SM_BYTES);
    cudaFuncSetAttribute(tbank1_k<true>, cudaFuncAttributeMaxDynamicSharedMemorySize, SM_BYTES);
    cudaFuncSetAttribute(tbank2_k<0, false>, cudaFuncAttributeMaxDynamicSharedMemorySize, SM_BYTES);
    cudaFuncSetAttribute(tbank2_k<1, false>, cudaFuncAttributeMaxDynamicSharedMemorySize, SM_BYTES);
    cudaFuncSetAttribute(tbank2_k<0, true>, cudaFuncAttributeMaxDynamicSharedMemorySize, SM_BYTES);
    cudaFuncSetAttribute(tbank2_k<1, true>, cudaFuncAttributeMaxDynamicSharedMemorySize, SM_BYTES);

    float* base = nullptr;
    cudaGetSymbolAddress((void**)&base, g_scratch);
    float *whi = nullptr, *wlo = nullptr;
    cudaGetSymbolAddress((void**)&whi, g_whi);
    cudaGetSymbolAddress((void**)&wlo, g_wlo);
    int *cnt, *list, *cnt2, *slot2, *tok2;
    cudaGetSymbolAddress((void**)&cnt, g_cnt);
    cudaGetSymbolAddress((void**)&list, g_list);
    cudaGetSymbolAddress((void**)&cnt2, g_cnt2);
    cudaGetSymbolAddress((void**)&slot2, g_slot2);
    cudaGetSymbolAddress((void**)&tok2, g_tok2);

    float* h     = base + OFF_H;
    float* mu    = base + OFF_MU;
    float* muhat = base + OFF_MUHAT;
    float* mun   = base + OFF_MUN;
    float* mur   = base + OFF_MUR;
    float* so    = base + OFF_SO;
    float* qb    = base + OFF_Q;
    float* lam   = base + OFF_LAM;
    float* msg   = base + OFF_MSG;
    float* dlam  = base + OFF_DLAM;
    float* mhat  = base + OFF_MHAT;
    float* fin   = base + OFF_FIN;
    float* trh   = base + OFF_TRH;
    float* hb    = base + OFF_HB;
    float* pi    = base + OFF_PI;

    const float inv_sqrt_d = 0.03608439182435161f;

    // ---- weight prep: split (and transpose emb) into hi/lo arena ----
    {
        const int DD4 = D * D / 4;
        split_k<<<(DD4 + 255) / 256, 256>>>(mu_w,     whi + W_MU,  wlo + W_MU,  DD4);
        split_k<<<(DD4 + 255) / 256, 256>>>(lam_w,    whi + W_LAM, wlo + W_LAM, DD4);
        split_k<<<(D * 1536 / 4 + 255) / 256, 256>>>(tr_w1, whi + W_TR1, wlo + W_TR1, D * 1536 / 4);
        split_k<<<(DD4 + 255) / 256, 256>>>(rt_q,     whi + W_RTQ, wlo + W_RTQ, DD4);
        split_k<<<(DD4 + 255) / 256, 256>>>(rt_k,     whi + W_RTK, wlo + W_RTK, DD4);
        split_k<<<(DD4 + 255) / 256, 256>>>(rt_v,     whi + W_RTV, wlo + W_RTV, DD4);
        split_k<<<(DD4 + 255) / 256, 256>>>(wr_lam_w, whi + W_WRL, wlo + W_WRL, DD4);
        split_k<<<(DD4 + 255) / 256, 256>>>(wr_mu_w,  whi + W_WRM, wlo + W_WRM, DD4);
        const int B14 = NS * D * FFN / 4;
        split_k<<<(B14 + 255) / 256, 256>>>(bank_w1, whi + W_B1, wlo + W_B1, B14);
        split_k<<<(B14 + 255) / 256, 256>>>(bank_w2, whi + W_B2, wlo + W_B2, B14);
        dim3 gt(VOC / 32, D / 32);
        tsplit_emb_k<<<gt, dim3(32, 8)>>>(emb_w, whi + W_EMBT, wlo + W_EMBT);
    }

    emb_k<<<NTOK, 256>>>(x, emb_w, pos_w, h);
    {
        dim3 g(D / 128, NTOK / 128, 2);
        tgemm_pair_k<EPI_BIAS, EPI_SP01, false><<<g, 256, SM_BYTES>>>(
            h, whi + W_MU, wlo + W_MU, mu_b, lam_b, nullptr, mu);
    }
    pi_init_k<<<(NTOK * NS + 255) / 256, 256>>>(pi);

    for (int step = 0; step < 3; step++) {
        const bool last = (step == 2);
        ln012_k<<<NTOK, 256>>>(mu, muhat, mun, mur, ln_g, ln_b);
        {
            dim3 g(1536 / 128, NTOK / 128);
            tgemm_k<EPI_GELU, false><<<g, 256, SM_BYTES>>>(mu, whi + W_TR1, wlo + W_TR1,
                                                           tr_b1, trh, 1536, D, 1.f, nullptr);
        }
        reset_cnt_k<<<1, 32>>>(cnt, cnt2);
        build_lists_k<<<NTOK / 256, 256>>>(pi, cnt, list, cnt2, slot2, tok2);
        {
            dim3 g1(FFN / 128, NTOK / 128, NS);
            dim3 g2(D / 128, NTOK / 128, NS);
            if (!last) {
                tbank1_k<false><<<g1, 256, SM_BYTES>>>(mun, whi + W_B1, wlo + W_B1, bank_b1, hb, list, cnt);
                tbank2_k<0, false><<<g2, 256, SM_BYTES>>>(hb, whi + W_B2, wlo + W_B2, bank_b2,
                                                          so, cnt2, slot2, tok2, pi);
                tbank2_k<1, false><<<g2, 256, SM_BYTES>>>(hb, whi + W_B2, wlo + W_B2, bank_b2,
                                                          so, cnt2, slot2, tok2, pi);
            } else {
                tbank1_k<true><<<g1, 256, SM_BYTES>>>(mun, whi + W_B1, wlo + W_B1, bank_b1, hb, list, cnt);
                tbank2_k<0, true><<<g2, 256, SM_BYTES>>>(hb, whi + W_B2, wlo + W_B2, bank_b2,
                                                         so, cnt2, slot2, tok2, pi);
                tbank2_k<1, true><<<g2, 256, SM_BYTES>>>(hb, whi + W_B2, wlo + W_B2, bank_b2,
                                                         so, cnt2, slot2, tok2, pi);
            }
        }
        ln_gen_k<<<NTOK, 256>>>(so, so, ln_g + 1 * D, ln_b + 1 * D);
        routing_k<<<NTOK, 128>>>(trh, tr_w2, tr_b2, mun, ev_w, ev_b, pi);
        {
            dim3 g(D / 128, NTOK / 128, 3);
            if (!last) tqkv_k<false><<<g, 256, SM_BYTES>>>(mur, whi + W_RTQ, wlo + W_RTQ, qb);
            else       tqkv_k<true><<<g, 256, SM_BYTES>>>(mur, whi + W_RTQ, wlo + W_RTQ, qb);
        }
        attn_k<<<NTOK, 128>>>(qb, qb + ROW, qb + 2 * ROW, pi, ln_g, ln_b, msg);
        {
            dim3 g(D / 128, NTOK / 128, 2);
            if (!last)
                tgemm_pair_k<EPI_GSP, EPI_BIAS, false><<<g, 256, SM_BYTES>>>(
                    msg, whi + W_WRL, wlo + W_WRL, wr_lam_b, wr_mu_b, pi, dlam);
            else
                tgemm_pair_k<EPI_GSP, EPI_BIAS, true><<<g, 256, SM_BYTES>>>(
                    msg, whi + W_WRL, wlo + W_WRL, wr_lam_b, wr_mu_b, pi, dlam);
        }
        update_k<<<NTOK, 256>>>(muhat, lam, dlam, mhat, so, ln_g, ln_b, mu);
    }

    ln_gen_k<<<NTOK, 256>>>(mu, fin, ln_g + 6 * D, ln_b + 6 * D);
    {
        dim3 g(VOC / 128, NTOK / 128);
        tgemm_k<EPI_SCALE, true><<<g, 256, SM_BYTES>>>(fin, whi + W_EMBT, wlo + W_EMBT,
                                                       nullptr, out, VOC, D, inv_sqrt_d, nullptr);
    }
}

// round 13
// speedup vs baseline: 1.5093x; 1.0720x over previous
#include <cuda_runtime.h>
#include <math.h>
#include <stdint.h>

#define NTOK 2048
#define TSEQ 1024
#define D    768
#define FFN  3072
#define NS   6
#define VOC  32000

// ---------------- scratch ----------------
#define ROW (NTOK*D)
#define OFF_H     0
#define OFF_MU    (1*ROW)
#define OFF_LAM   (2*ROW)
#define OFF_MUHAT (3*ROW)
#define OFF_MUN   (4*ROW)
#define OFF_MUR   (5*ROW)
#define OFF_SO    (6*ROW)
#define OFF_Q     (7*ROW)
#define OFF_K     (8*ROW)
#define OFF_V     (9*ROW)
#define OFF_MSG   (10*ROW)
#define OFF_DLAM  (11*ROW)
#define OFF_MHAT  (12*ROW)
#define OFF_FIN   (13*ROW)
#define OFF_TRH   (14*ROW)
#define OFF_HB    (14*ROW + NTOK*1536)
#define OFF_PI    (OFF_HB + NS*NTOK*FFN)
#define SCRATCH_FLOATS (OFF_PI + NTOK*NS)

__device__ float g_scratch[SCRATCH_FLOATS];
__device__ int   g_cnt[NS];
__device__ int   g_list[NS * NTOK];
__device__ int   g_cnt2[2 * NS];
__device__ int   g_slot2[2 * NS * NTOK];
__device__ int   g_tok2[2 * NS * NTOK];

// ---------------- pre-split weight arena (hi/lo tf32 split) ----------------
#define W_MU   0
#define W_LAM  589824
#define W_TR1  1179648
#define W_RTQ  2359296
#define W_RTK  2949120
#define W_RTV  3538944
#define W_WRL  4128768
#define W_WRM  4718592
#define W_B1   5308416
#define W_B2   19464192
#define W_EMBT 33619968
#define WSPLIT 58195968

__device__ float g_whi[WSPLIT];
__device__ float g_wlo[WSPLIT];

// ---------------- helpers ----------------
__device__ __forceinline__ float gelu_f(float x) {
    float x3 = x * x * x;
    return 0.5f * x * (1.f + tanhf(0.7978845608028654f * (x + 0.044715f * x3)));
}
__device__ __forceinline__ float softplus_f(float x) {
    return fmaxf(x, 0.f) + log1pf(expf(-fabsf(x)));
}
__device__ __forceinline__ float block_sum(float v, float* red) {
    int tid = threadIdx.x;
    __syncthreads();
#pragma unroll
    for (int o = 16; o > 0; o >>= 1) v += __shfl_xor_sync(0xffffffffu, v, o);
    if ((tid & 31) == 0) red[tid >> 5] = v;
    __syncthreads();
    if (tid < 32) {
        float t = (tid < (int)(blockDim.x >> 5)) ? red[tid] : 0.f;
#pragma unroll
        for (int o = 4; o > 0; o >>= 1) t += __shfl_xor_sync(0xffffffffu, t, o);
        if (tid == 0) red[0] = t;
    }
    __syncthreads();
    return red[0];
}

__device__ __forceinline__ void cvt_split(float x, float& hi, float& lo) {
    uint32_t hb; asm("cvt.rna.tf32.f32 %0, %1;" : "=r"(hb) : "f"(x));
    hi = __uint_as_float(hb);
    float lf = x - hi;
    uint32_t lb; asm("cvt.rna.tf32.f32 %0, %1;" : "=r"(lb) : "f"(lf));
    lo = __uint_as_float(lb);
}
__device__ __forceinline__ float cvt_hi(float x) {
    uint32_t hb; asm("cvt.rna.tf32.f32 %0, %1;" : "=r"(hb) : "f"(x));
    return __uint_as_float(hb);
}

// ---------------- weight prep kernels ----------------
__global__ void split_k(const float* __restrict__ src, float* __restrict__ hi,
                        float* __restrict__ lo, int n4)
{
    int i = blockIdx.x * blockDim.x + threadIdx.x;
    if (i >= n4) return;
    float4 v = ((const float4*)src)[i];
    float4 h, l;
    cvt_split(v.x, h.x, l.x); cvt_split(v.y, h.y, l.y);
    cvt_split(v.z, h.z, l.z); cvt_split(v.w, h.w, l.w);
    ((float4*)hi)[i] = h;
    ((float4*)lo)[i] = l;
}

// transpose emb_w [VOC][D] -> [D][VOC] tf32-hi only (logits is pure tf32)
__global__ void tsplit_emb_k(const float* __restrict__ emb, float* __restrict__ hi)
{
    __shared__ float tile[32][33];
    int v0 = blockIdx.x * 32, d0 = blockIdx.y * 32;
    int tx = threadIdx.x, ty = threadIdx.y; // 32 x 8
    for (int r = ty; r < 32; r += 8)
        tile[r][tx] = emb[(long)(v0 + r) * D + d0 + tx];
    __syncthreads();
    for (int r = ty; r < 32; r += 8)
        hi[(long)(d0 + r) * VOC + v0 + tx] = cvt_hi(tile[tx][r]);
}

// ---------------- tf32 mma core ----------------
// smem (float offsets): RAWA[3][128][20] @0 (7680),
// BHI[3][16][136] @7680 (6528), BLO[3][16][136] @14208 (6528)
// total 20736 floats = 82944 B -> 2 CTAs/SM
#define A_ST    2560
#define B_STF   2176
#define SM_RAWA 0
#define SM_BHI  7680
#define SM_BLO  14208
#define SM_BYTES (20736 * 4)

__device__ __forceinline__ void mma8(float* c, const uint32_t* a, uint32_t b0, uint32_t b1) {
    asm volatile(
        "mma.sync.aligned.m16n8k8.row.col.f32.tf32.tf32.f32 "
        "{%0,%1,%2,%3},{%4,%5,%6,%7},{%8,%9},{%0,%1,%2,%3};"
        : "+f"(c[0]), "+f"(c[1]), "+f"(c[2]), "+f"(c[3])
        : "r"(a[0]), "r"(a[1]), "r"(a[2]), "r"(a[3]), "r"(b0), "r"(b1));
}

__device__ __forceinline__ void cp16(uint32_t dst, const float* src) {
    asm volatile("cp.async.ca.shared.global [%0], [%1], 16;" :: "r"(dst), "l"(src) : "memory");
}

// block 128x128, 8 warps (4m x 2n), warp tile 32x64, BK=16.
// Raw A (fp32, read ONCE from gmem) + pre-split B, 3-stage rings, ONE barrier
// per slice. A's hi/lo split happens inline in comp (registers).
// FAST: 2-term split ah*bh + al*bh; Blo is NEVER loaded.
template <bool GATHER, bool FAST>
__device__ __forceinline__ void tf32_loop(
    const float* __restrict__ A, const float* __restrict__ Bhi,
    const float* __restrict__ Blo,
    int K, int N, int bm0, int bn0, const int* __restrict__ rowTok,
    float* __restrict__ sm, float c[2][8][4])
{
    const int tid = threadIdx.x;
    const int lane = tid & 31, warp = tid >> 5;
    const int wm0 = (warp >> 1) * 32, wn0 = (warp & 1) * 64;
    const int g = lane >> 2, tig = lane & 3;

    const int arow0 = tid >> 2, arow1 = arow0 + 64, aq = tid & 3;
    long agr0, agr1;
    if (GATHER) { agr0 = rowTok[arow0]; agr1 = rowTok[arow1]; }
    else        { agr0 = bm0 + arow0;   agr1 = bm0 + arow1;   }
    const int bkr = tid >> 5;
    const int bn4 = (tid & 31) * 4;

    const uint32_t smb = (uint32_t)__cvta_generic_to_shared(sm);

    auto issue = [&](int st, int k0) {
        uint32_t ra = smb + (uint32_t)(SM_RAWA + st * A_ST) * 4u;
        cp16(ra + (uint32_t)(arow0 * 20 + aq * 4) * 4u, A + agr0 * K + k0 + aq * 4);
        cp16(ra + (uint32_t)(arow1 * 20 + aq * 4) * 4u, A + agr1 * K + k0 + aq * 4);
        uint32_t bh = smb + (uint32_t)(SM_BHI + st * B_STF) * 4u;
        cp16(bh + (uint32_t)(bkr * 136 + bn4) * 4u,
             Bhi + (long)(k0 + bkr) * N + bn0 + bn4);
        cp16(bh + (uint32_t)((bkr + 8) * 136 + bn4) * 4u,
             Bhi + (long)(k0 + bkr + 8) * N + bn0 + bn4);
        if (!FAST) {
            uint32_t bl = smb + (uint32_t)(SM_BLO + st * B_STF) * 4u;
            cp16(bl + (uint32_t)(bkr * 136 + bn4) * 4u,
                 Blo + (long)(k0 + bkr) * N + bn0 + bn4);
            cp16(bl + (uint32_t)((bkr + 8) * 136 + bn4) * 4u,
                 Blo + (long)(k0 + bkr + 8) * N + bn0 + bn4);
        }
        asm volatile("cp.async.commit_group;" ::: "memory");
    };

    auto comp = [&](int st) {
        const float* rap = sm + SM_RAWA + st * A_ST;
        const float* bhp = sm + SM_BHI + st * B_STF;
        const float* blp = sm + SM_BLO + st * B_STF;
#pragma unroll
        for (int ks = 0; ks < 16; ks += 8) {
            uint32_t ah[2][4], al[2][4];
#pragma unroll
            for (int mt = 0; mt < 2; mt++) {
                int rb = wm0 + mt * 16 + g;
                float r0 = rap[rb * 20 + ks + tig];
                float r1 = rap[(rb + 8) * 20 + ks + tig];
                float r2 = rap[rb * 20 + ks + tig + 4];
                float r3 = rap[(rb + 8) * 20 + ks + tig + 4];
                float hf, lf;
                cvt_split(r0, hf, lf); ah[mt][0] = __float_as_uint(hf); al[mt][0] = __float_as_uint(lf);
                cvt_split(r1, hf, lf); ah[mt][1] = __float_as_uint(hf); al[mt][1] = __float_as_uint(lf);
                cvt_split(r2, hf, lf); ah[mt][2] = __float_as_uint(hf); al[mt][2] = __float_as_uint(lf);
                cvt_split(r3, hf, lf); ah[mt][3] = __float_as_uint(hf); al[mt][3] = __float_as_uint(lf);
            }
#pragma unroll
            for (int nt = 0; nt < 8; nt++) {
                int cb = wn0 + nt * 8 + g;
                uint32_t bh0 = __float_as_uint(bhp[(ks + tig) * 136 + cb]);
                uint32_t bh1 = __float_as_uint(bhp[(ks + tig + 4) * 136 + cb]);
#pragma unroll
                for (int mt = 0; mt < 2; mt++) {
                    mma8(c[mt][nt], ah[mt], bh0, bh1);
                    mma8(c[mt][nt], al[mt], bh0, bh1);
                }
                if (!FAST) {
                    uint32_t bl0 = __float_as_uint(blp[(ks + tig) * 136 + cb]);
                    uint32_t bl1 = __float_as_uint(blp[(ks + tig + 4) * 136 + cb]);
#pragma unroll
                    for (int mt = 0; mt < 2; mt++)
                        mma8(c[mt][nt], ah[mt], bl0, bl1);
                }
            }
        }
    };

    const int nk = K >> 4;  // >= 48 at all call sites
    issue(0, 0);
    issue(1, 16);
    int st = 0, stn = 2;
    for (int i = 0; i < nk; i++) {
        if (i < nk - 1) asm volatile("cp.async.wait_group 1;" ::: "memory");
        else            asm volatile("cp.async.wait_group 0;" ::: "memory");
        __syncthreads();
        if (i + 2 < nk) {
            issue(stn, (i + 2) << 4);
            stn = (stn == 2) ? 0 : stn + 1;
        }
        comp(st);
        st = (st == 2) ? 0 : st + 1;
    }
}

// ---------------- pure-tf32 logits GEMM ----------------
// A = fin (tf32-rounded at producer), B = embT hi. 1 mma per tile-step.
// smem: AHI[3][128][20] @0, BHI[3][16][136] @7680 -> 14208 fl = 56832 B
#define LG_SM_BYTES (14208 * 4)

__global__ void __launch_bounds__(256, 2) tlogits_k(
    const float* __restrict__ Ahi, const float* __restrict__ Bhi,
    float* __restrict__ C, int N, int K, float alpha)
{
    extern __shared__ float sm[];
    const int tid = threadIdx.x;
    const int lane = tid & 31, warp = tid >> 5;
    const int wm0 = (warp >> 1) * 32, wn0 = (warp & 1) * 64;
    const int g = lane >> 2, tig = lane & 3;
    const int bm0 = blockIdx.y * 128, bn0 = blockIdx.x * 128;

    const int arow0 = tid >> 2, arow1 = arow0 + 64, aq = tid & 3;
    const long agr0 = bm0 + arow0, agr1 = bm0 + arow1;
    const int bkr = tid >> 5;
    const int bn4 = (tid & 31) * 4;
    const uint32_t smb = (uint32_t)__cvta_generic_to_shared(sm);

    float c[2][8][4];
#pragma unroll
    for (int a = 0; a < 2; a++)
#pragma unroll
        for (int b = 0; b < 8; b++)
#pragma unroll
            for (int r = 0; r < 4; r++) c[a][b][r] = 0.f;

    auto issue = [&](int st, int k0) {
        uint32_t ah = smb + (uint32_t)(st * A_ST) * 4u;
        cp16(ah + (uint32_t)(arow0 * 20 + aq * 4) * 4u, Ahi + agr0 * K + k0 + aq * 4);
        cp16(ah + (uint32_t)(arow1 * 20 + aq * 4) * 4u, Ahi + agr1 * K + k0 + aq * 4);
        uint32_t bh = smb + (uint32_t)(SM_BHI + st * B_STF) * 4u;
        cp16(bh + (uint32_t)(bkr * 136 + bn4) * 4u,
             Bhi + (long)(k0 + bkr) * N + bn0 + bn4);
        cp16(bh + (uint32_t)((bkr + 8) * 136 + bn4) * 4u,
             Bhi + (long)(k0 + bkr + 8) * N + bn0 + bn4);
        asm volatile("cp.async.commit_group;" ::: "memory");
    };

    auto comp = [&](int st) {
        const float* ahp = sm + st * A_ST;
        const float* bhp = sm + SM_BHI + st * B_STF;
#pragma unroll
        for (int ks = 0; ks < 16; ks += 8) {
            uint32_t ah[2][4];
#pragma unroll
            for (int mt = 0; mt < 2; mt++) {
                int rb = wm0 + mt * 16 + g;
                ah[mt][0] = __float_as_uint(ahp[rb * 20 + ks + tig]);
                ah[mt][1] = __float_as_uint(ahp[(rb + 8) * 20 + ks + tig]);
                ah[mt][2] = __float_as_uint(ahp[rb * 20 + ks + tig + 4]);
                ah[mt][3] = __float_as_uint(ahp[(rb + 8) * 20 + ks + tig + 4]);
            }
#pragma unroll
            for (int nt = 0; nt < 8; nt++) {
                int cb = wn0 + nt * 8 + g;
                uint32_t bh0 = __float_as_uint(bhp[(ks + tig) * 136 + cb]);
                uint32_t bh1 = __float_as_uint(bhp[(ks + tig + 4) * 136 + cb]);
#pragma unroll
                for (int mt = 0; mt < 2; mt++)
                    mma8(c[mt][nt], ah[mt], bh0, bh1);
            }
        }
    };

    const int nk = K >> 4;  // 48
    issue(0, 0);
    issue(1, 16);
    int st = 0, stn = 2;
    for (int i = 0; i < nk; i++) {
        if (i < nk - 1) asm volatile("cp.async.wait_group 1;" ::: "memory");
        else            asm volatile("cp.async.wait_group 0;" ::: "memory");
        __syncthreads();
        if (i + 2 < nk) {
            issue(stn, (i + 2) << 4);
            stn = (stn == 2) ? 0 : stn + 1;
        }
        comp(st);
        st = (st == 2) ? 0 : st + 1;
    }

    const int colbase = bn0 + wn0;
#pragma unroll
    for (int mt = 0; mt < 2; mt++) {
#pragma unroll
        for (int half = 0; half < 2; half++) {
            int row = bm0 + wm0 + mt * 16 + g + half * 8;
            float* cp = C + (long)row * N + colbase;
#pragma unroll
            for (int nt = 0; nt < 8; nt++) {
                int col = nt * 8 + tig * 2;
                *(float2*)(cp + col) = make_float2(c[mt][nt][half * 2] * alpha,
                                                   c[mt][nt][half * 2 + 1] * alpha);
            }
        }
    }
}

// ---------------- epilogues ----------------
enum { EPI_NONE = 0, EPI_BIAS = 1, EPI_GELU = 2, EPI_GSP = 3, EPI_SP01 = 5 };

template <int EPI>
__device__ __forceinline__ float epi_apply(float v, float b, float rs) {
    if (EPI == EPI_BIAS)  return v + b;
    if (EPI == EPI_GELU)  return gelu_f(v + b);
    if (EPI == EPI_GSP)   return rs * softplus_f(v + b);
    if (EPI == EPI_SP01)  return softplus_f(v + b) + 0.1f;
    return v;
}

template <int EPI>
__device__ __forceinline__ void epi_store_dense(
    float c[2][8][4], float* __restrict__ C, const float* __restrict__ bias,
    int N, int bm0, int bn0, const float* __restrict__ pi)
{
    const int tid = threadIdx.x, lane = tid & 31, warp = tid >> 5;
    const int wm0 = (warp >> 1) * 32, wn0 = (warp & 1) * 64;
    const int g = lane >> 2, tig = lane & 3;
    const int colbase = bn0 + wn0;
#pragma unroll
    for (int mt = 0; mt < 2; mt++) {
#pragma unroll
        for (int half = 0; half < 2; half++) {
            int row = bm0 + wm0 + mt * 16 + g + half * 8;
            float rs = (EPI == EPI_GSP) ? pi[row * NS + 4] : 0.f;
            float* cp = C + (long)row * N + colbase;
#pragma unroll
            for (int nt = 0; nt < 8; nt++) {
                int col = nt * 8 + tig * 2;
                float b0 = 0.f, b1 = 0.f;
                if (EPI != EPI_NONE) {
                    b0 = bias[colbase + col];
                    b1 = bias[colbase + col + 1];
                }
                float v0 = epi_apply<EPI>(c[mt][nt][half * 2], b0, rs);
                float v1 = epi_apply<EPI>(c[mt][nt][half * 2 + 1], b1, rs);
                *(float2*)(cp + col) = make_float2(v0, v1);
            }
        }
    }
}

// ---------------- GEMM kernels ----------------
template <int EPI, bool FAST>
__global__ void __launch_bounds__(256, 2) tgemm_k(
    const float* __restrict__ A, const float* __restrict__ Bhi,
    const float* __restrict__ Blo, const float* __restrict__ bias,
    float* __restrict__ C, int N, int K, const float* __restrict__ pi)
{
    extern __shared__ float sm[];
    const int bm0 = blockIdx.y * 128, bn0 = blockIdx.x * 128;
    float c[2][8][4];
#pragma unroll
    for (int a = 0; a < 2; a++)
#pragma unroll
        for (int b = 0; b < 8; b++)
#pragma unroll
            for (int r = 0; r < 4; r++) c[a][b][r] = 0.f;
    tf32_loop<false, FAST>(A, Bhi, Blo, K, N, bm0, bn0, nullptr, sm, c);
    epi_store_dense<EPI>(c, C, bias, N, bm0, bn0, pi);
}

// z-pair over adjacent arena weights (stride D*D)
template <int EPI0, int EPI1, bool FAST>
__global__ void __launch_bounds__(256, 2) tgemm_pair_k(
    const float* __restrict__ A, const float* __restrict__ Whi,
    const float* __restrict__ Wlo, const float* __restrict__ b0,
    const float* __restrict__ b1, const float* __restrict__ pi,
    float* __restrict__ Cbase)
{
    extern __shared__ float sm[];
    const int z = blockIdx.z;
    const float* Bhi = Whi + (long)z * D * D;
    const float* Blo = Wlo + (long)z * D * D;
    const float* bias = z ? b1 : b0;
    float* C = Cbase + (long)z * ROW;
    const int bm0 = blockIdx.y * 128, bn0 = blockIdx.x * 128;
    float c[2][8][4];
#pragma unroll
    for (int a = 0; a < 2; a++)
#pragma unroll
        for (int b = 0; b < 8; b++)
#pragma unroll
            for (int r = 0; r < 4; r++) c[a][b][r] = 0.f;
    tf32_loop<false, FAST>(A, Bhi, Blo, D, D, bm0, bn0, nullptr, sm, c);
    if (z == 0) epi_store_dense<EPI0>(c, C, bias, D, bm0, bn0, pi);
    else        epi_store_dense<EPI1>(c, C, bias, D, bm0, bn0, pi);
}

template <bool FAST>
__global__ void __launch_bounds__(256, 2) tqkv_k(
    const float* __restrict__ A, const float* __restrict__ Whi,
    const float* __restrict__ Wlo, float* __restrict__ Cbase)
{
    extern __shared__ float sm[];
    const int z = blockIdx.z;
    const float* Bhi = Whi + (long)z * D * D;
    const float* Blo = Wlo + (long)z * D * D;
    float* C = Cbase + (long)z * ROW;
    const int bm0 = blockIdx.y * 128, bn0 = blockIdx.x * 128;
    float c[2][8][4];
#pragma unroll
    for (int a = 0; a < 2; a++)
#pragma unroll
        for (int b = 0; b < 8; b++)
#pragma unroll
            for (int r = 0; r < 4; r++) c[a][b][r] = 0.f;
    tf32_loop<false, FAST>(A, Bhi, Blo, D, D, bm0, bn0, nullptr, sm, c);
    epi_store_dense<EPI_NONE>(c, C, nullptr, D, bm0, bn0, nullptr);
}

template <bool FAST>
__global__ void __launch_bounds__(256, 2) tbank1_k(
    const float* __restrict__ A, const float* __restrict__ Whi,
    const float* __restrict__ Wlo, const float* __restrict__ b1all,
    float* __restrict__ hb, const int* __restrict__ list,
    const int* __restrict__ cnt)
{
    extern __shared__ float sm[];
    __shared__ int rowTok[128];
    const int s = blockIdx.z;
    const int cn = cnt[s];
    const int bm0 = blockIdx.y * 128;
    if (bm0 >= cn) return;
    const int tid = threadIdx.x;
    if (tid < 128) rowTok[tid] = list[s * NTOK + min(bm0 + tid, cn - 1)];
    __syncthreads();

    const float* Bhi = Whi + (long)s * D * FFN;
    const float* Blo = Wlo + (long)s * D * FFN;
    const float* bias = b1all + s * FFN;
    float* C = hb + (long)s * NTOK * FFN;
    const int bn0 = blockIdx.x * 128;

    float c[2][8][4];
#pragma unroll
    for (int a = 0; a < 2; a++)
#pragma unroll
        for (int b = 0; b < 8; b++)
#pragma unroll
            for (int r = 0; r < 4; r++) c[a][b][r] = 0.f;
    tf32_loop<true, FAST>(A, Bhi, Blo, D, FFN, 0, bn0, rowTok, sm, c);

    const int lane = tid & 31, warp = tid >> 5;
    const int wm0 = (warp >> 1) * 32, wn0 = (warp & 1) * 64;
    const int g = lane >> 2, tig = lane & 3;
    const int colbase = bn0 + wn0;
#pragma unroll
    for (int mt = 0; mt < 2; mt++) {
#pragma unroll
        for (int half = 0; half < 2; half++) {
            int slot = bm0 + wm0 + mt * 16 + g + half * 8;
            if (slot >= cn) continue;
            float* cp = C + (long)slot * FFN + colbase;
#pragma unroll
            for (int nt = 0; nt < 8; nt++) {
                int col = nt * 8 + tig * 2;
                float v0 = gelu_f(c[mt][nt][half * 2] + bias[colbase + col]);
                float v1 = gelu_f(c[mt][nt][half * 2 + 1] + bias[colbase + col + 1]);
                *(float2*)(cp + col) = make_float2(v0, v1);
            }
        }
    }
}

template <int RANK, bool FAST>
__global__ void __launch_bounds__(256, 2) tbank2_k(
    const float* __restrict__ hb, const float* __restrict__ Whi,
    const float* __restrict__ Wlo, const float* __restrict__ b2all,
    float* __restrict__ so, const int* __restrict__ cnt2,
    const int* __restrict__ slot2, const int* __restrict__ tok2,
    const float* __restrict__ pi)
{
    extern __shared__ float sm[];
    __shared__ int rowSlot[128];
    const int s = blockIdx.z;
    const int cn = cnt2[RANK * NS + s];
    const int bm0 = blockIdx.y * 128;
    if (bm0 >= cn) return;
    const int tid = threadIdx.x;
    const int lbase = (RANK * NS + s) * NTOK;
    if (tid < 128) rowSlot[tid] = slot2[lbase + min(bm0 + tid, cn - 1)];
    __syncthreads();

    const float* A = hb + (long)s * NTOK * FFN;
    const float* Bhi = Whi + (long)s * FFN * D;
    const float* Blo = Wlo + (long)s * FFN * D;
    const float* bias = b2all + s * D;
    const int bn0 = blockIdx.x * 128;

    float c[2][8][4];
#pragma unroll
    for (int a = 0; a < 2; a++)
#pragma unroll
        for (int b = 0; b < 8; b++)
#pragma unroll
            for (int r = 0; r < 4; r++) c[a][b][r] = 0.f;
    tf32_loop<true, FAST>(A, Bhi, Blo, FFN, D, 0, bn0, rowSlot, sm, c);

    const int lane = tid & 31, warp = tid >> 5;
    const int wm0 = (warp >> 1) * 32, wn0 = (warp & 1) * 64;
    const int g = lane >> 2, tig = lane & 3;
    const int colbase = bn0 + wn0;
#pragma unroll
    for (int mt = 0; mt < 2; mt++) {
#pragma unroll
        for (int half = 0; half < 2; half++) {
            int idx = bm0 + wm0 + mt * 16 + g + half * 8;
            if (idx >= cn) continue;
            int tok = tok2[lbase + idx];
            float rs = pi[tok * NS + s];
            float* cp = so + (long)tok * D + colbase;
#pragma unroll
            for (int nt = 0; nt < 8; nt++) {
                int col = nt * 8 + tig * 2;
                float v0 = rs * (c[mt][nt][half * 2] + bias[colbase + col]);
                float v1 = rs * (c[mt][nt][half * 2 + 1] + bias[colbase + col + 1]);
                if (RANK == 0) {
                    *(float2*)(cp + col) = make_float2(v0, v1);
                } else {
                    float2 old = *(float2*)(cp + col);
                    *(float2*)(cp + col) = make_float2(old.x + v0, old.y + v1);
                }
            }
        }
    }
}

// ---------------- small kernels ----------------
__global__ void emb_k(const int* __restrict__ x, const float* __restrict__ emb,
                      const float* __restrict__ pos, float* __restrict__ h)
{
    int n = blockIdx.x;
    int vx = x[n];
    int t = n % TSEQ;
    const float* e = emb + (long)vx * D;
    const float* p = pos + (long)t * D;
    for (int j = threadIdx.x; j < D; j += blockDim.x)
        h[(long)n * D + j] = e[j] + p[j];
}

__global__ void pi_init_k(float* __restrict__ pi)
{
    int i = blockIdx.x * blockDim.x + threadIdx.x;
    if (i < NTOK * NS) pi[i] = ((i % NS) == 2) ? 1.f : 0.f;
}

__global__ void reset_cnt_k(int* cnt, int* cnt2)
{
    if (threadIdx.x < NS) cnt[threadIdx.x] = 0;
    if (threadIdx.x < 2 * NS) cnt2[threadIdx.x] = 0;
}

__global__ void build_lists_k(const float* __restrict__ pi,
                              int* __restrict__ cnt, int* __restrict__ list,
                              int* __restrict__ cnt2, int* __restrict__ slot2,
                              int* __restrict__ tok2)
{
    int t = blockIdx.x * blockDim.x + threadIdx.x;
    if (t >= NTOK) return;
    int r = 0;
#pragma unroll
    for (int s = 0; s < NS; s++) {
        if (pi[t * NS + s] != 0.f) {
            int p = atomicAdd(&cnt[s], 1);
            list[s * NTOK + p] = t;
            int rr = min(r, 1);
            int q = atomicAdd(&cnt2[rr * NS + s], 1);
            slot2[(rr * NS + s) * NTOK + q] = p;
            tok2[(rr * NS + s) * NTOK + q] = t;
            r++;
        }
    }
}

__global__ void ln012_k(const float* __restrict__ mu, float* __restrict__ muhat,
                        float* __restrict__ mun, float* __restrict__ mur,
                        const float* __restrict__ ln_g, const float* __restrict__ ln_b)
{
    __shared__ float red[8];
    int n = blockIdx.x, tid = threadIdx.x;
    const float* row = mu + (long)n * D;
    float v[3], s = 0.f;
#pragma unroll
    for (int r = 0; r < 3; r++) { v[r] = row[tid + r * 256]; s += v[r]; }
    float mean = block_sum(s, red) / D;
    float qv = 0.f;
#pragma unroll
    for (int r = 0; r < 3; r++) { float d = v[r] - mean; qv += d * d; }
    float var = block_sum(qv, red) / D;
    float inv = rsqrtf(var + 1e-5f);
#pragma unroll
    for (int r = 0; r < 3; r++) {
        int j = tid + r * 256;
        float nh = (v[r] - mean) * inv;
        long idx = (long)n * D + j;
        muhat[idx] = nh;
        mun[idx] = nh * ln_g[j] + ln_b[j];
        mur[idx] = nh * ln_g[2 * D + j] + ln_b[2 * D + j];
    }
}

__global__ void ln_gen_k(const float* __restrict__ in, float* __restrict__ out,
                         const float* __restrict__ g, const float* __restrict__ b)
{
    __shared__ float red[8];
    int n = blockIdx.x, tid = threadIdx.x;
    const float* row = in + (long)n * D;
    float v[3], s = 0.f;
#pragma unroll
    for (int r = 0; r < 3; r++) { v[r] = row[tid + r * 256]; s += v[r]; }
    float mean = block_sum(s, red) / D;
    float qv = 0.f;
#pragma unroll
    for (int r = 0; r < 3; r++) { float d = v[r] - mean; qv += d * d; }
    float var = block_sum(qv, red) / D;
    float inv = rsqrtf(var + 1e-5f);
#pragma unroll
    for (int r = 0; r < 3; r++) {
        int j = tid + r * 256;
        out[(long)n * D + j] = (v[r] - mean) * inv * g[j] + b[j];
    }
}

// LN then tf32-round (rna) — feeds the pure-tf32 logits GEMM
__global__ void ln_cvt_k(const float* __restrict__ in, float* __restrict__ out,
                         const float* __restrict__ g, const float* __restrict__ b)
{
    __shared__ float red[8];
    int n = blockIdx.x, tid = threadIdx.x;
    const float* row = in + (long)n * D;
    float v[3], s = 0.f;
#pragma unroll
    for (int r = 0; r < 3; r++) { v[r] = row[tid + r * 256]; s += v[r]; }
    float mean = block_sum(s, red) / D;
    float qv = 0.f;
#pragma unroll
    for (int r = 0; r < 3; r++) { float d = v[r] - mean; qv += d * d; }
    float var = block_sum(qv, red) / D;
    float inv = rsqrtf(var + 1e-5f);
#pragma unroll
    for (int r = 0; r < 3; r++) {
        int j = tid + r * 256;
        float val = (v[r] - mean) * inv * g[j] + b[j];
        out[(long)n * D + j] = cvt_hi(val);
    }
}

__global__ void routing_k(const float* __restrict__ trh, const float* __restrict__ w2,
                          const float* __restrict__ b2, const float* __restrict__ mun,
                          const float* __restrict__ evw, const float* __restrict__ evb,
                          float* __restrict__ pi)
{
    __shared__ float sh[1536];
    __shared__ float smn[D];
    __shared__ float kz[36];
    __shared__ float ev[6];
    __shared__ float spi[6];
    int n = blockIdx.x, tid = threadIdx.x;
    for (int i = tid; i < 1536; i += 128) sh[i] = trh[(long)n * 1536 + i];
    for (int i = tid; i < D; i += 128)    smn[i] = mun[(long)n * D + i];
    if (tid < NS) spi[tid] = pi[n * NS + tid];
    __syncthreads();
    if (tid < 36) {
        float acc = b2[tid];
        for (int k = 0; k < 1536; k++) acc += sh[k] * w2[k * 36 + tid];
        kz[tid] = acc;
    } else if (tid < 42) {
        int j = tid - 36;
        float acc = evb[j];
        for (int k = 0; k < D; k++) acc += smn[k] * evw[k * NS + j];
        ev[j] = acc;
    }
    __syncthreads();
    if (tid == 0) {
        float Kr[6][6];
        for (int s = 0; s < 6; s++) {
            float mx = kz[s * 6];
            for (int u = 1; u < 6; u++) mx = fmaxf(mx, kz[s * 6 + u]);
            float sum = 0.f;
            for (int u = 0; u < 6; u++) { float e = expf(kz[s * 6 + u] - mx); Kr[s][u] = e; sum += e; }
            float invr = 1.f / sum;
            for (int u = 0; u < 6; u++) Kr[s][u] *= invr;
        }
        float pev[6];
        for (int u = 0; u < 6; u++) {
            float a = 0.f;
            for (int s = 0; s < 6; s++) a += spi[s] * Kr[s][u];
            pev[u] = a;
        }
        float mx = ev[0] * 2.f;
        for (int u = 1; u < 6; u++) mx = fmaxf(mx, ev[u] * 2.f);
        float wv[6], sw = 0.f;
        for (int u = 0; u < 6; u++) { wv[u] = expf(ev[u] * 2.f - mx); sw += wv[u]; }
        float invw = 1.f / sw;
        float pn[6], s1 = 0.f;
        for (int u = 0; u < 6; u++) { pn[u] = pev[u] * wv[u] * invw; s1 += pn[u]; }
        float inv1 = 1.f / fmaxf(s1, 1e-8f);
        for (int u = 0; u < 6; u++) pn[u] *= inv1;
        int i1 = 0;
        for (int u = 1; u < 6; u++) if (pn[u] > pn[i1]) i1 = u;
        int i2 = (i1 == 0) ? 1 : 0;
        for (int u = 0; u < 6; u++) if (u != i1 && pn[u] > pn[i2]) i2 = u;
        float inv2 = 1.f / fmaxf(pn[i1] + pn[i2], 1e-8f);
        for (int u = 0; u < 6; u++)
            pi[n * NS + u] = (u == i1 || u == i2) ? pn[u] * inv2 : 0.f;
    }
}

__global__ void attn_k(const float* __restrict__ q, const float* __restrict__ k,
                       const float* __restrict__ v, const float* __restrict__ pi,
                       const float* __restrict__ ln_g, const float* __restrict__ ln_b,
                       float* __restrict__ msg)
{
    __shared__ float sw[4];
    __shared__ float mb[D];
    __shared__ float red[8];
    int n = blockIdx.x, tid = threadIdx.x;
    int t = n % TSEQ;
    int warp = tid >> 5, lane = tid & 31;
    const int offs[4] = {-2, -1, 1, 2};
    {
        int o = offs[warp];
        int tt = t + o;
        float dot = 0.f;
        if (tt >= 0 && tt < TSEQ) {
            const float* qp = q + (long)n * D;
            const float* kp = k + (long)(n + o) * D;
            for (int j = lane; j < D; j += 32) dot += qp[j] * kp[j];
        }
#pragma unroll
        for (int s = 16; s > 0; s >>= 1) dot += __shfl_xor_sync(0xffffffffu, dot, s);
        if (lane == 0)
            sw[warp] = (tt >= 0 && tt < TSEQ) ? dot / 27.712812921102035f : -1e9f;
    }
    __syncthreads();
    float w0 = sw[0], w1 = sw[1], w2 = sw[2], w3 = sw[3];
    float mx = fmaxf(fmaxf(w0, w1), fmaxf(w2, w3));
    float wt[4] = {expf(w0 - mx), expf(w1 - mx), expf(w2 - mx), expf(w3 - mx)};
    float invs = 1.f / (wt[0] + wt[1] + wt[2] + wt[3]);
#pragma unroll
    for (int w = 0; w < 4; w++) wt[w] *= invs;
    float pi3 = pi[n * NS + 3];
    for (int j = tid; j < D; j += 128) {
        float m = 0.f;
#pragma unroll
        for (int w = 0; w < 4; w++) {
            int tt = t + offs[w];
            if (tt >= 0 && tt < TSEQ) m += wt[w] * v[(long)(n + offs[w]) * D + j];
        }
        mb[j] = m * pi3;
    }
    __syncthreads();
    float loc[6], s = 0.f;
#pragma unroll
    for (int r = 0; r < 6; r++) { loc[r] = mb[tid + r * 128]; s += loc[r]; }
    float mean = block_sum(s, red) / D;
    float qv = 0.f;
#pragma unroll
    for (int r = 0; r < 6; r++) { float d = loc[r] - mean; qv += d * d; }
    float var = block_sum(qv, red) / D;
    float inv = rsqrtf(var + 1e-5f);
#pragma unroll
    for (int r = 0; r < 6; r++) {
        int j = tid + r * 128;
        msg[(long)n * D + j] = (loc[r] - mean) * inv * ln_g[3 * D + j] + ln_b[3 * D + j];
    }
}

__global__ void update_k(const float* __restrict__ muhat, float* __restrict__ lam,
                         const float* __restrict__ dlam, const float* __restrict__ mhat,
                         const float* __restrict__ so,
                         const float* __restrict__ ln_g, const float* __restrict__ ln_b,
                         float* __restrict__ mu)
{
    __shared__ float red[8];
    int n = blockIdx.x, tid = threadIdx.x;
    float mval[3], s = 0.f;
#pragma unroll
    for (int r = 0; r < 3; r++) {
        int j = tid + r * 256;
        long idx = (long)n * D + j;
        float l = lam[idx], dl = dlam[idx];
        float mwn = muhat[idx] * ln_g[4 * D + j] + ln_b[4 * D + j];
        float lnw = l + dl;
        float m = (l * mwn + dl * mhat[idx]) / lnw;
        lam[idx] = lnw;
        mval[r] = m;
        s += m;
    }
    float mean = block_sum(s, red) / D;
    float qv = 0.f;
#pragma unroll
    for (int r = 0; r < 3; r++) { float d = mval[r] - mean; qv += d * d; }
    float var = block_sum(qv, red) / D;
    float inv = rsqrtf(var + 1e-5f);
#pragma unroll
    for (int r = 0; r < 3; r++) {
        int j = tid + r * 256;
        long idx = (long)n * D + j;
        mu[idx] = (mval[r] - mean) * inv * ln_g[5 * D + j] + ln_b[5 * D + j] + so[idx] * 0.1f;
    }
}

// ---------------- launcher ----------------
extern "C" void kernel_launch(void* const* d_in, const int* in_sizes, int n_in,
                              void* d_out, int out_size)
{
    const int*   x        = (const int*)d_in[0];
    const float* emb_w    = (const float*)d_in[1];
    const float* pos_w    = (const float*)d_in[2];
    const float* mu_w     = (const float*)d_in[3];
    const float* mu_b     = (const float*)d_in[4];
    const float* lam_w    = (const float*)d_in[5];
    const float* lam_b    = (const float*)d_in[6];
    const float* tr_w1    = (const float*)d_in[7];
    const float* tr_b1    = (const float*)d_in[8];
    const float* tr_w2    = (const float*)d_in[9];
    const float* tr_b2    = (const float*)d_in[10];
    const float* bank_w1  = (const float*)d_in[11];
    const float* bank_b1  = (const float*)d_in[12];
    const float* bank_w2  = (const float*)d_in[13];
    const float* bank_b2  = (const float*)d_in[14];
    const float* ev_w     = (const float*)d_in[15];
    const float* ev_b     = (const float*)d_in[16];
    const float* rt_q     = (const float*)d_in[17];
    const float* rt_k     = (const float*)d_in[18];
    const float* rt_v     = (const float*)d_in[19];
    const float* wr_lam_w = (const float*)d_in[20];
    const float* wr_lam_b = (const float*)d_in[21];
    const float* wr_mu_w  = (const float*)d_in[22];
    const float* wr_mu_b  = (const float*)d_in[23];
    const float* ln_g     = (const float*)d_in[24];
    const float* ln_b     = (const float*)d_in[25];
    float* out = (float*)d_out;

    cudaFuncSetAttribute(tgemm_k<EPI_GELU, false>, cudaFuncAttributeMaxDynamicSharedMemorySize, SM_BYTES);
    cudaFuncSetAttribute(tgemm_pair_k<EPI_BIAS, EPI_SP01, false>, cudaFuncAttributeMaxDynamicSharedMemorySize, SM_BYTES);
    cudaFuncSetAttribute(tgemm_pair_k<EPI_GSP, EPI_BIAS, false>, cudaFuncAttributeMaxDynamicSharedMemorySize, SM_BYTES);
    cudaFuncSetAttribute(tgemm_pair_k<EPI_GSP, EPI_BIAS, true>, cudaFuncAttributeMaxDynamicSharedMemorySize, SM_BYTES);
    cudaFuncSetAttribute(tqkv_k<false>, cudaFuncAttributeMaxDynamicSharedMemorySize, SM_BYTES);
    cudaFuncSetAttribute(tqkv_k<true>, cudaFuncAttributeMaxDynamicSharedMemorySize, SM_BYTES);
    cudaFuncSetAttribute(tbank1_k<false>, cudaFuncAttributeMaxDynamicSharedMemorySize, SM_BYTES);
    cudaFuncSetAttribute(tbank1_k<true>, cudaFuncAttributeMaxDynamicSharedMemorySize, SM_BYTES);
    cudaFuncSetAttribute(tbank2_k<0, false>, cudaFuncAttributeMaxDynamicSharedMemorySize, SM_BYTES);
    cudaFuncSetAttribute(tbank2_k<1, false>, cudaFuncAttributeMaxDynamicSharedMemorySize, SM_BYTES);
    cudaFuncSetAttribute(tbank2_k<0, true>, cudaFuncAttributeMaxDynamicSharedMemorySize, SM_BYTES);
    cudaFuncSetAttribute(tbank2_k<1, true>, cudaFuncAttributeMaxDynamicSharedMemorySize, SM_BYTES);
    cudaFuncSetAttribute(tlogits_k, cudaFuncAttributeMaxDynamicSharedMemorySize, LG_SM_BYTES);

    float* base = nullptr;
    cudaGetSymbolAddress((void**)&base, g_scratch);
    float *whi = nullptr, *wlo = nullptr;
    cudaGetSymbolAddress((void**)&whi, g_whi);
    cudaGetSymbolAddress((void**)&wlo, g_wlo);
    int *cnt, *list, *cnt2, *slot2, *tok2;
    cudaGetSymbolAddress((void**)&cnt, g_cnt);
    cudaGetSymbolAddress((void**)&list, g_list);
    cudaGetSymbolAddress((void**)&cnt2, g_cnt2);
    cudaGetSymbolAddress((void**)&slot2, g_slot2);
    cudaGetSymbolAddress((void**)&tok2, g_tok2);

    float* h     = base + OFF_H;
    float* mu    = base + OFF_MU;
    float* muhat = base + OFF_MUHAT;
    float* mun   = base + OFF_MUN;
    float* mur   = base + OFF_MUR;
    float* so    = base + OFF_SO;
    float* qb    = base + OFF_Q;
    float* lam   = base + OFF_LAM;
    float* msg   = base + OFF_MSG;
    float* dlam  = base + OFF_DLAM;
    float* mhat  = base + OFF_MHAT;
    float* fin   = base + OFF_FIN;
    float* trh   = base + OFF_TRH;
    float* hb    = base + OFF_HB;
    float* pi    = base + OFF_PI;

    const float inv_sqrt_d = 0.03608439182435161f;

    // ---- weight prep: split (and transpose emb hi) into arena ----
    {
        const int DD4 = D * D / 4;
        split_k<<<(DD4 + 255) / 256, 256>>>(mu_w,     whi + W_MU,  wlo + W_MU,  DD4);
        split_k<<<(DD4 + 255) / 256, 256>>>(lam_w,    whi + W_LAM, wlo + W_LAM, DD4);
        split_k<<<(D * 1536 / 4 + 255) / 256, 256>>>(tr_w1, whi + W_TR1, wlo + W_TR1, D * 1536 / 4);
        split_k<<<(DD4 + 255) / 256, 256>>>(rt_q,     whi + W_RTQ, wlo + W_RTQ, DD4);
        split_k<<<(DD4 + 255) / 256, 256>>>(rt_k,     whi + W_RTK, wlo + W_RTK, DD4);
        split_k<<<(DD4 + 255) / 256, 256>>>(rt_v,     whi + W_RTV, wlo + W_RTV, DD4);
        split_k<<<(DD4 + 255) / 256, 256>>>(wr_lam_w, whi + W_WRL, wlo + W_WRL, DD4);
        split_k<<<(DD4 + 255) / 256, 256>>>(wr_mu_w,  whi + W_WRM, wlo + W_WRM, DD4);
        const int B14 = NS * D * FFN / 4;
        split_k<<<(B14 + 255) / 256, 256>>>(bank_w1, whi + W_B1, wlo + W_B1, B14);
        split_k<<<(B14 + 255) / 256, 256>>>(bank_w2, whi + W_B2, wlo + W_B2, B14);
        dim3 gt(VOC / 32, D / 32);
        tsplit_emb_k<<<gt, dim3(32, 8)>>>(emb_w, whi + W_EMBT);
    }

    emb_k<<<NTOK, 256>>>(x, emb_w, pos_w, h);
    {
        dim3 g(D / 128, NTOK / 128, 2);
        tgemm_pair_k<EPI_BIAS, EPI_SP01, false><<<g, 256, SM_BYTES>>>(
            h, whi + W_MU, wlo + W_MU, mu_b, lam_b, nullptr, mu);
    }
    pi_init_k<<<(NTOK * NS + 255) / 256, 256>>>(pi);

    for (int step = 0; step < 3; step++) {
        const bool last = (step == 2);
        ln012_k<<<NTOK, 256>>>(mu, muhat, mun, mur, ln_g, ln_b);
        {
            dim3 g(1536 / 128, NTOK / 128);
            tgemm_k<EPI_GELU, false><<<g, 256, SM_BYTES>>>(mu, whi + W_TR1, wlo + W_TR1,
                                                           tr_b1, trh, 1536, D, nullptr);
        }
        reset_cnt_k<<<1, 32>>>(cnt, cnt2);
        build_lists_k<<<NTOK / 256, 256>>>(pi, cnt, list, cnt2, slot2, tok2);
        {
            dim3 g1(FFN / 128, NTOK / 128, NS);
            dim3 g2(D / 128, NTOK / 128, NS);
            if (!last) {
                tbank1_k<false><<<g1, 256, SM_BYTES>>>(mun, whi + W_B1, wlo + W_B1, bank_b1, hb, list, cnt);
                tbank2_k<0, false><<<g2, 256, SM_BYTES>>>(hb, whi + W_B2, wlo + W_B2, bank_b2,
                                                          so, cnt2, slot2, tok2, pi);
                tbank2_k<1, false><<<g2, 256, SM_BYTES>>>(hb, whi + W_B2, wlo + W_B2, bank_b2,
                                                          so, cnt2, slot2, tok2, pi);
            } else {
                tbank1_k<true><<<g1, 256, SM_BYTES>>>(mun, whi + W_B1, wlo + W_B1, bank_b1, hb, list, cnt);
                tbank2_k<0, true><<<g2, 256, SM_BYTES>>>(hb, whi + W_B2, wlo + W_B2, bank_b2,
                                                         so, cnt2, slot2, tok2, pi);
                tbank2_k<1, true><<<g2, 256, SM_BYTES>>>(hb, whi + W_B2, wlo + W_B2, bank_b2,
                                                         so, cnt2, slot2, tok2, pi);
            }
        }
        ln_gen_k<<<NTOK, 256>>>(so, so, ln_g + 1 * D, ln_b + 1 * D);
        routing_k<<<NTOK, 128>>>(trh, tr_w2, tr_b2, mun, ev_w, ev_b, pi);
        {
            dim3 g(D / 128, NTOK / 128, 3);
            if (!last) tqkv_k<false><<<g, 256, SM_BYTES>>>(mur, whi + W_RTQ, wlo + W_RTQ, qb);
            else       tqkv_k<true><<<g, 256, SM_BYTES>>>(mur, whi + W_RTQ, wlo + W_RTQ, qb);
        }
        attn_k<<<NTOK, 128>>>(qb, qb + ROW, qb + 2 * ROW, pi, ln_g, ln_b, msg);
        {
            dim3 g(D / 128, NTOK / 128, 2);
            if (!last)
                tgemm_pair_k<EPI_GSP, EPI_BIAS, false><<<g, 256, SM_BYTES>>>(
                    msg, whi + W_WRL, wlo + W_WRL, wr_lam_b, wr_mu_b, pi, dlam);
            else
                tgemm_pair_k<EPI_GSP, EPI_BIAS, true><<<g, 256, SM_BYTES>>>(
                    msg, whi + W_WRL, wlo + W_WRL, wr_lam_b, wr_mu_b, pi, dlam);
        }
        update_k<<<NTOK, 256>>>(muhat, lam, dlam, mhat, so, ln_g, ln_b, mu);
    }

    // final LN with tf32 rounding at producer; pure-tf32 logits GEMM
    ln_cvt_k<<<NTOK, 256>>>(mu, fin, ln_g + 6 * D, ln_b + 6 * D);
    {
        dim3 g(VOC / 128, NTOK / 128);
        tlogits_k<<<g, 256, LG_SM_BYTES>>>(fin, whi + W_EMBT, out, VOC, D, inv_sqrt_d);
    }
}

// round 14
// speedup vs baseline: 1.5383x; 1.0192x over previous
#include <cuda_runtime.h>
#include <math.h>
#include <stdint.h>

#define NTOK 2048
#define TSEQ 1024
#define D    768
#define FFN  3072
#define NS   6
#define VOC  32000

// ---------------- scratch ----------------
#define ROW (NTOK*D)
#define OFF_H     0
#define OFF_MU    (1*ROW)
#define OFF_LAM   (2*ROW)
#define OFF_MUHAT (3*ROW)
#define OFF_MUN   (4*ROW)
#define OFF_MUR   (5*ROW)
#define OFF_SO    (6*ROW)
#define OFF_Q     (7*ROW)
#define OFF_K     (8*ROW)
#define OFF_V     (9*ROW)
#define OFF_MSG   (10*ROW)
#define OFF_DLAM  (11*ROW)
#define OFF_MHAT  (12*ROW)
#define OFF_FIN   (13*ROW)
#define OFF_TRH   (14*ROW)
#define OFF_HB    (14*ROW + NTOK*1536)
#define OFF_PI    (OFF_HB + NS*NTOK*FFN)
#define SCRATCH_FLOATS (OFF_PI + NTOK*NS)

__device__ float g_scratch[SCRATCH_FLOATS];
__device__ int   g_cnt[NS];
__device__ int   g_list[NS * NTOK];
__device__ int   g_cnt2[2 * NS];
__device__ int   g_slot2[2 * NS * NTOK];
__device__ int   g_tok2[2 * NS * NTOK];

// ---------------- pre-split weight arena (hi/lo tf32 split) ----------------
#define W_MU   0
#define W_LAM  589824
#define W_TR1  1179648
#define W_RTQ  2359296
#define W_RTK  2949120
#define W_RTV  3538944
#define W_WRL  4128768
#define W_WRM  4718592
#define W_B1   5308416
#define W_B2   19464192
#define W_EMBT 33619968
#define WSPLIT 58195968

__device__ float g_whi[WSPLIT];
__device__ float g_wlo[WSPLIT];

// ---------------- helpers ----------------
__device__ __forceinline__ float gelu_f(float x) {
    float x3 = x * x * x;
    return 0.5f * x * (1.f + tanhf(0.7978845608028654f * (x + 0.044715f * x3)));
}
__device__ __forceinline__ float softplus_f(float x) {
    return fmaxf(x, 0.f) + log1pf(expf(-fabsf(x)));
}
__device__ __forceinline__ float block_sum(float v, float* red) {
    int tid = threadIdx.x;
    __syncthreads();
#pragma unroll
    for (int o = 16; o > 0; o >>= 1) v += __shfl_xor_sync(0xffffffffu, v, o);
    if ((tid & 31) == 0) red[tid >> 5] = v;
    __syncthreads();
    if (tid < 32) {
        float t = (tid < (int)(blockDim.x >> 5)) ? red[tid] : 0.f;
#pragma unroll
        for (int o = 4; o > 0; o >>= 1) t += __shfl_xor_sync(0xffffffffu, t, o);
        if (tid == 0) red[0] = t;
    }
    __syncthreads();
    return red[0];
}

// hi = tf32-rounded x; lo = exact fp32 remainder (mma truncates lo to tf32
// internally; the induced error ~2^-25|x| is below the 3-term residual).
__device__ __forceinline__ void cvt_split(float x, float& hi, float& lo) {
    uint32_t hb; asm("cvt.rna.tf32.f32 %0, %1;" : "=r"(hb) : "f"(x));
    hi = __uint_as_float(hb);
    lo = x - hi;
}
__device__ __forceinline__ float cvt_hi(float x) {
    uint32_t hb; asm("cvt.rna.tf32.f32 %0, %1;" : "=r"(hb) : "f"(x));
    return __uint_as_float(hb);
}

// ---------------- weight prep kernels ----------------
__global__ void split_k(const float* __restrict__ src, float* __restrict__ hi,
                        float* __restrict__ lo, int n4)
{
    int i = blockIdx.x * blockDim.x + threadIdx.x;
    if (i >= n4) return;
    float4 v = ((const float4*)src)[i];
    float4 h, l;
    cvt_split(v.x, h.x, l.x); cvt_split(v.y, h.y, l.y);
    cvt_split(v.z, h.z, l.z); cvt_split(v.w, h.w, l.w);
    ((float4*)hi)[i] = h;
    ((float4*)lo)[i] = l;
}

// transpose emb_w [VOC][D] -> [D][VOC] tf32-hi only (logits is pure tf32)
__global__ void tsplit_emb_k(const float* __restrict__ emb, float* __restrict__ hi)
{
    __shared__ float tile[32][33];
    int v0 = blockIdx.x * 32, d0 = blockIdx.y * 32;
    int tx = threadIdx.x, ty = threadIdx.y; // 32 x 8
    for (int r = ty; r < 32; r += 8)
        tile[r][tx] = emb[(long)(v0 + r) * D + d0 + tx];
    __syncthreads();
    for (int r = ty; r < 32; r += 8)
        hi[(long)(d0 + r) * VOC + v0 + tx] = cvt_hi(tile[tx][r]);
}

// ---------------- tf32 mma core ----------------
// smem (float offsets): RAWA[3][128][20] @0 (7680),
// BHI[3][16][136] @7680 (6528), BLO[3][16][136] @14208 (6528)
// total 20736 floats = 82944 B -> 2 CTAs/SM
#define A_ST    2560
#define B_STF   2176
#define SM_RAWA 0
#define SM_BHI  7680
#define SM_BLO  14208
#define SM_BYTES (20736 * 4)

__device__ __forceinline__ void mma8(float* c, const uint32_t* a, uint32_t b0, uint32_t b1) {
    asm volatile(
        "mma.sync.aligned.m16n8k8.row.col.f32.tf32.tf32.f32 "
        "{%0,%1,%2,%3},{%4,%5,%6,%7},{%8,%9},{%0,%1,%2,%3};"
        : "+f"(c[0]), "+f"(c[1]), "+f"(c[2]), "+f"(c[3])
        : "r"(a[0]), "r"(a[1]), "r"(a[2]), "r"(a[3]), "r"(b0), "r"(b1));
}

__device__ __forceinline__ void cp16(uint32_t dst, const float* src) {
    asm volatile("cp.async.ca.shared.global [%0], [%1], 16;" :: "r"(dst), "l"(src) : "memory");
}

// block 128x128, 8 warps (4m x 2n), warp tile 32x64, BK=16.
// Raw A (fp32, read ONCE from gmem) + pre-split B, 3-stage rings, ONE barrier
// per slice. A's hi/lo split happens inline in comp (registers).
// FAST: 2-term split ah*bh + al*bh; Blo is NEVER loaded.
template <bool GATHER, bool FAST>
__device__ __forceinline__ void tf32_loop(
    const float* __restrict__ A, const float* __restrict__ Bhi,
    const float* __restrict__ Blo,
    int K, int N, int bm0, int bn0, const int* __restrict__ rowTok,
    float* __restrict__ sm, float c[2][8][4])
{
    const int tid = threadIdx.x;
    const int lane = tid & 31, warp = tid >> 5;
    const int wm0 = (warp >> 1) * 32, wn0 = (warp & 1) * 64;
    const int g = lane >> 2, tig = lane & 3;

    const int arow0 = tid >> 2, arow1 = arow0 + 64, aq = tid & 3;
    long agr0, agr1;
    if (GATHER) { agr0 = rowTok[arow0]; agr1 = rowTok[arow1]; }
    else        { agr0 = bm0 + arow0;   agr1 = bm0 + arow1;   }
    const int bkr = tid >> 5;
    const int bn4 = (tid & 31) * 4;

    const uint32_t smb = (uint32_t)__cvta_generic_to_shared(sm);

    auto issue = [&](int st, int k0) {
        uint32_t ra = smb + (uint32_t)(SM_RAWA + st * A_ST) * 4u;
        cp16(ra + (uint32_t)(arow0 * 20 + aq * 4) * 4u, A + agr0 * K + k0 + aq * 4);
        cp16(ra + (uint32_t)(arow1 * 20 + aq * 4) * 4u, A + agr1 * K + k0 + aq * 4);
        uint32_t bh = smb + (uint32_t)(SM_BHI + st * B_STF) * 4u;
        cp16(bh + (uint32_t)(bkr * 136 + bn4) * 4u,
             Bhi + (long)(k0 + bkr) * N + bn0 + bn4);
        cp16(bh + (uint32_t)((bkr + 8) * 136 + bn4) * 4u,
             Bhi + (long)(k0 + bkr + 8) * N + bn0 + bn4);
        if (!FAST) {
            uint32_t bl = smb + (uint32_t)(SM_BLO + st * B_STF) * 4u;
            cp16(bl + (uint32_t)(bkr * 136 + bn4) * 4u,
                 Blo + (long)(k0 + bkr) * N + bn0 + bn4);
            cp16(bl + (uint32_t)((bkr + 8) * 136 + bn4) * 4u,
                 Blo + (long)(k0 + bkr + 8) * N + bn0 + bn4);
        }
        asm volatile("cp.async.commit_group;" ::: "memory");
    };

    auto comp = [&](int st) {
        const float* rap = sm + SM_RAWA + st * A_ST;
        const float* bhp = sm + SM_BHI + st * B_STF;
        const float* blp = sm + SM_BLO + st * B_STF;
#pragma unroll
        for (int ks = 0; ks < 16; ks += 8) {
            uint32_t ah[2][4], al[2][4];
#pragma unroll
            for (int mt = 0; mt < 2; mt++) {
                int rb = wm0 + mt * 16 + g;
                float r0 = rap[rb * 20 + ks + tig];
                float r1 = rap[(rb + 8) * 20 + ks + tig];
                float r2 = rap[rb * 20 + ks + tig + 4];
                float r3 = rap[(rb + 8) * 20 + ks + tig + 4];
                float hf, lf;
                cvt_split(r0, hf, lf); ah[mt][0] = __float_as_uint(hf); al[mt][0] = __float_as_uint(lf);
                cvt_split(r1, hf, lf); ah[mt][1] = __float_as_uint(hf); al[mt][1] = __float_as_uint(lf);
                cvt_split(r2, hf, lf); ah[mt][2] = __float_as_uint(hf); al[mt][2] = __float_as_uint(lf);
                cvt_split(r3, hf, lf); ah[mt][3] = __float_as_uint(hf); al[mt][3] = __float_as_uint(lf);
            }
#pragma unroll
            for (int nt = 0; nt < 8; nt++) {
                int cb = wn0 + nt * 8 + g;
                uint32_t bh0 = __float_as_uint(bhp[(ks + tig) * 136 + cb]);
                uint32_t bh1 = __float_as_uint(bhp[(ks + tig + 4) * 136 + cb]);
#pragma unroll
                for (int mt = 0; mt < 2; mt++) {
                    mma8(c[mt][nt], ah[mt], bh0, bh1);
                    mma8(c[mt][nt], al[mt], bh0, bh1);
                }
                if (!FAST) {
                    uint32_t bl0 = __float_as_uint(blp[(ks + tig) * 136 + cb]);
                    uint32_t bl1 = __float_as_uint(blp[(ks + tig + 4) * 136 + cb]);
#pragma unroll
                    for (int mt = 0; mt < 2; mt++)
                        mma8(c[mt][nt], ah[mt], bl0, bl1);
                }
            }
        }
    };

    const int nk = K >> 4;  // >= 48 at all call sites
    issue(0, 0);
    issue(1, 16);
    int st = 0, stn = 2;
    for (int i = 0; i < nk; i++) {
        if (i < nk - 1) asm volatile("cp.async.wait_group 1;" ::: "memory");
        else            asm volatile("cp.async.wait_group 0;" ::: "memory");
        __syncthreads();
        if (i + 2 < nk) {
            issue(stn, (i + 2) << 4);
            stn = (stn == 2) ? 0 : stn + 1;
        }
        comp(st);
        st = (st == 2) ? 0 : st + 1;
    }
}

// ---------------- pure-tf32 logits GEMM ----------------
// A = fin (tf32-rounded at producer), B = embT hi. 1 mma per tile-step.
// Grid: (M-tiles, N-tiles) so concurrent CTAs share B columns -> B streamed
// from DRAM once (L2 reuse across all 16 M-tiles).
// smem: AHI[3][128][20] @0, BHI[3][16][136] @7680 -> 14208 fl = 56832 B
#define LG_SM_BYTES (14208 * 4)

__global__ void __launch_bounds__(256, 2) tlogits_k(
    const float* __restrict__ Ahi, const float* __restrict__ Bhi,
    float* __restrict__ C, int N, int K, float alpha)
{
    extern __shared__ float sm[];
    const int tid = threadIdx.x;
    const int lane = tid & 31, warp = tid >> 5;
    const int wm0 = (warp >> 1) * 32, wn0 = (warp & 1) * 64;
    const int g = lane >> 2, tig = lane & 3;
    const int bm0 = blockIdx.x * 128, bn0 = blockIdx.y * 128;

    const int arow0 = tid >> 2, arow1 = arow0 + 64, aq = tid & 3;
    const long agr0 = bm0 + arow0, agr1 = bm0 + arow1;
    const int bkr = tid >> 5;
    const int bn4 = (tid & 31) * 4;
    const uint32_t smb = (uint32_t)__cvta_generic_to_shared(sm);

    float c[2][8][4];
#pragma unroll
    for (int a = 0; a < 2; a++)
#pragma unroll
        for (int b = 0; b < 8; b++)
#pragma unroll
            for (int r = 0; r < 4; r++) c[a][b][r] = 0.f;

    auto issue = [&](int st, int k0) {
        uint32_t ah = smb + (uint32_t)(st * A_ST) * 4u;
        cp16(ah + (uint32_t)(arow0 * 20 + aq * 4) * 4u, Ahi + agr0 * K + k0 + aq * 4);
        cp16(ah + (uint32_t)(arow1 * 20 + aq * 4) * 4u, Ahi + agr1 * K + k0 + aq * 4);
        uint32_t bh = smb + (uint32_t)(SM_BHI + st * B_STF) * 4u;
        cp16(bh + (uint32_t)(bkr * 136 + bn4) * 4u,
             Bhi + (long)(k0 + bkr) * N + bn0 + bn4);
        cp16(bh + (uint32_t)((bkr + 8) * 136 + bn4) * 4u,
             Bhi + (long)(k0 + bkr + 8) * N + bn0 + bn4);
        asm volatile("cp.async.commit_group;" ::: "memory");
    };

    auto comp = [&](int st) {
        const float* ahp = sm + st * A_ST;
        const float* bhp = sm + SM_BHI + st * B_STF;
#pragma unroll
        for (int ks = 0; ks < 16; ks += 8) {
            uint32_t ah[2][4];
#pragma unroll
            for (int mt = 0; mt < 2; mt++) {
                int rb = wm0 + mt * 16 + g;
                ah[mt][0] = __float_as_uint(ahp[rb * 20 + ks + tig]);
                ah[mt][1] = __float_as_uint(ahp[(rb + 8) * 20 + ks + tig]);
                ah[mt][2] = __float_as_uint(ahp[rb * 20 + ks + tig + 4]);
                ah[mt][3] = __float_as_uint(ahp[(rb + 8) * 20 + ks + tig + 4]);
            }
#pragma unroll
            for (int nt = 0; nt < 8; nt++) {
                int cb = wn0 + nt * 8 + g;
                uint32_t bh0 = __float_as_uint(bhp[(ks + tig) * 136 + cb]);
                uint32_t bh1 = __float_as_uint(bhp[(ks + tig + 4) * 136 + cb]);
#pragma unroll
                for (int mt = 0; mt < 2; mt++)
                    mma8(c[mt][nt], ah[mt], bh0, bh1);
            }
        }
    };

    const int nk = K >> 4;  // 48
    issue(0, 0);
    issue(1, 16);
    int st = 0, stn = 2;
    for (int i = 0; i < nk; i++) {
        if (i < nk - 1) asm volatile("cp.async.wait_group 1;" ::: "memory");
        else            asm volatile("cp.async.wait_group 0;" ::: "memory");
        __syncthreads();
        if (i + 2 < nk) {
            issue(stn, (i + 2) << 4);
            stn = (stn == 2) ? 0 : stn + 1;
        }
        comp(st);
        st = (st == 2) ? 0 : st + 1;
    }

    const int colbase = bn0 + wn0;
#pragma unroll
    for (int mt = 0; mt < 2; mt++) {
#pragma unroll
        for (int half = 0; half < 2; half++) {
            int row = bm0 + wm0 + mt * 16 + g + half * 8;
            float* cp = C + (long)row * N + colbase;
#pragma unroll
            for (int nt = 0; nt < 8; nt++) {
                int col = nt * 8 + tig * 2;
                *(float2*)(cp + col) = make_float2(c[mt][nt][half * 2] * alpha,
                                                   c[mt][nt][half * 2 + 1] * alpha);
            }
        }
    }
}

// ---------------- epilogues ----------------
enum { EPI_NONE = 0, EPI_BIAS = 1, EPI_GELU = 2, EPI_GSP = 3, EPI_SP01 = 5 };

template <int EPI>
__device__ __forceinline__ float epi_apply(float v, float b, float rs) {
    if (EPI == EPI_BIAS)  return v + b;
    if (EPI == EPI_GELU)  return gelu_f(v + b);
    if (EPI == EPI_GSP)   return rs * softplus_f(v + b);
    if (EPI == EPI_SP01)  return softplus_f(v + b) + 0.1f;
    return v;
}

template <int EPI>
__device__ __forceinline__ void epi_store_dense(
    float c[2][8][4], float* __restrict__ C, const float* __restrict__ bias,
    int N, int bm0, int bn0, const float* __restrict__ pi)
{
    const int tid = threadIdx.x, lane = tid & 31, warp = tid >> 5;
    const int wm0 = (warp >> 1) * 32, wn0 = (warp & 1) * 64;
    const int g = lane >> 2, tig = lane & 3;
    const int colbase = bn0 + wn0;
#pragma unroll
    for (int mt = 0; mt < 2; mt++) {
#pragma unroll
        for (int half = 0; half < 2; half++) {
            int row = bm0 + wm0 + mt * 16 + g + half * 8;
            float rs = (EPI == EPI_GSP) ? pi[row * NS + 4] : 0.f;
            float* cp = C + (long)row * N + colbase;
#pragma unroll
            for (int nt = 0; nt < 8; nt++) {
                int col = nt * 8 + tig * 2;
                float b0 = 0.f, b1 = 0.f;
                if (EPI != EPI_NONE) {
                    b0 = bias[colbase + col];
                    b1 = bias[colbase + col + 1];
                }
                float v0 = epi_apply<EPI>(c[mt][nt][half * 2], b0, rs);
                float v1 = epi_apply<EPI>(c[mt][nt][half * 2 + 1], b1, rs);
                *(float2*)(cp + col) = make_float2(v0, v1);
            }
        }
    }
}

// ---------------- GEMM kernels ----------------
template <int EPI, bool FAST>
__global__ void __launch_bounds__(256, 2) tgemm_k(
    const float* __restrict__ A, const float* __restrict__ Bhi,
    const float* __restrict__ Blo, const float* __restrict__ bias,
    float* __restrict__ C, int N, int K, const float* __restrict__ pi)
{
    extern __shared__ float sm[];
    const int bm0 = blockIdx.y * 128, bn0 = blockIdx.x * 128;
    float c[2][8][4];
#pragma unroll
    for (int a = 0; a < 2; a++)
#pragma unroll
        for (int b = 0; b < 8; b++)
#pragma unroll
            for (int r = 0; r < 4; r++) c[a][b][r] = 0.f;
    tf32_loop<false, FAST>(A, Bhi, Blo, K, N, bm0, bn0, nullptr, sm, c);
    epi_store_dense<EPI>(c, C, bias, N, bm0, bn0, pi);
}

// z-pair over adjacent arena weights (stride D*D)
template <int EPI0, int EPI1, bool FAST>
__global__ void __launch_bounds__(256, 2) tgemm_pair_k(
    const float* __restrict__ A, const float* __restrict__ Whi,
    const float* __restrict__ Wlo, const float* __restrict__ b0,
    const float* __restrict__ b1, const float* __restrict__ pi,
    float* __restrict__ Cbase)
{
    extern __shared__ float sm[];
    const int z = blockIdx.z;
    const float* Bhi = Whi + (long)z * D * D;
    const float* Blo = Wlo + (long)z * D * D;
    const float* bias = z ? b1 : b0;
    float* C = Cbase + (long)z * ROW;
    const int bm0 = blockIdx.y * 128, bn0 = blockIdx.x * 128;
    float c[2][8][4];
#pragma unroll
    for (int a = 0; a < 2; a++)
#pragma unroll
        for (int b = 0; b < 8; b++)
#pragma unroll
            for (int r = 0; r < 4; r++) c[a][b][r] = 0.f;
    tf32_loop<false, FAST>(A, Bhi, Blo, D, D, bm0, bn0, nullptr, sm, c);
    if (z == 0) epi_store_dense<EPI0>(c, C, bias, D, bm0, bn0, pi);
    else        epi_store_dense<EPI1>(c, C, bias, D, bm0, bn0, pi);
}

template <bool FAST>
__global__ void __launch_bounds__(256, 2) tqkv_k(
    const float* __restrict__ A, const float* __restrict__ Whi,
    const float* __restrict__ Wlo, float* __restrict__ Cbase)
{
    extern __shared__ float sm[];
    const int z = blockIdx.z;
    const float* Bhi = Whi + (long)z * D * D;
    const float* Blo = Wlo + (long)z * D * D;
    float* C = Cbase + (long)z * ROW;
    const int bm0 = blockIdx.y * 128, bn0 = blockIdx.x * 128;
    float c[2][8][4];
#pragma unroll
    for (int a = 0; a < 2; a++)
#pragma unroll
        for (int b = 0; b < 8; b++)
#pragma unroll
            for (int r = 0; r < 4; r++) c[a][b][r] = 0.f;
    tf32_loop<false, FAST>(A, Bhi, Blo, D, D, bm0, bn0, nullptr, sm, c);
    epi_store_dense<EPI_NONE>(c, C, nullptr, D, bm0, bn0, nullptr);
}

template <bool FAST>
__global__ void __launch_bounds__(256, 2) tbank1_k(
    const float* __restrict__ A, const float* __restrict__ Whi,
    const float* __restrict__ Wlo, const float* __restrict__ b1all,
    float* __restrict__ hb, const int* __restrict__ list,
    const int* __restrict__ cnt)
{
    extern __shared__ float sm[];
    __shared__ int rowTok[128];
    const int s = blockIdx.z;
    const int cn = cnt[s];
    const int bm0 = blockIdx.y * 128;
    if (bm0 >= cn) return;
    const int tid = threadIdx.x;
    if (tid < 128) rowTok[tid] = list[s * NTOK + min(bm0 + tid, cn - 1)];
    __syncthreads();

    const float* Bhi = Whi + (long)s * D * FFN;
    const float* Blo = Wlo + (long)s * D * FFN;
    const float* bias = b1all + s * FFN;
    float* C = hb + (long)s * NTOK * FFN;
    const int bn0 = blockIdx.x * 128;

    float c[2][8][4];
#pragma unroll
    for (int a = 0; a < 2; a++)
#pragma unroll
        for (int b = 0; b < 8; b++)
#pragma unroll
            for (int r = 0; r < 4; r++) c[a][b][r] = 0.f;
    tf32_loop<true, FAST>(A, Bhi, Blo, D, FFN, 0, bn0, rowTok, sm, c);

    const int lane = tid & 31, warp = tid >> 5;
    const int wm0 = (warp >> 1) * 32, wn0 = (warp & 1) * 64;
    const int g = lane >> 2, tig = lane & 3;
    const int colbase = bn0 + wn0;
#pragma unroll
    for (int mt = 0; mt < 2; mt++) {
#pragma unroll
        for (int half = 0; half < 2; half++) {
            int slot = bm0 + wm0 + mt * 16 + g + half * 8;
            if (slot >= cn) continue;
            float* cp = C + (long)slot * FFN + colbase;
#pragma unroll
            for (int nt = 0; nt < 8; nt++) {
                int col = nt * 8 + tig * 2;
                float v0 = gelu_f(c[mt][nt][half * 2] + bias[colbase + col]);
                float v1 = gelu_f(c[mt][nt][half * 2 + 1] + bias[colbase + col + 1]);
                *(float2*)(cp + col) = make_float2(v0, v1);
            }
        }
    }
}

template <int RANK, bool FAST>
__global__ void __launch_bounds__(256, 2) tbank2_k(
    const float* __restrict__ hb, const float* __restrict__ Whi,
    const float* __restrict__ Wlo, const float* __restrict__ b2all,
    float* __restrict__ so, const int* __restrict__ cnt2,
    const int* __restrict__ slot2, const int* __restrict__ tok2,
    const float* __restrict__ pi)
{
    extern __shared__ float sm[];
    __shared__ int rowSlot[128];
    const int s = blockIdx.z;
    const int cn = cnt2[RANK * NS + s];
    const int bm0 = blockIdx.y * 128;
    if (bm0 >= cn) return;
    const int tid = threadIdx.x;
    const int lbase = (RANK * NS + s) * NTOK;
    if (tid < 128) rowSlot[tid] = slot2[lbase + min(bm0 + tid, cn - 1)];
    __syncthreads();

    const float* A = hb + (long)s * NTOK * FFN;
    const float* Bhi = Whi + (long)s * FFN * D;
    const float* Blo = Wlo + (long)s * FFN * D;
    const float* bias = b2all + s * D;
    const int bn0 = blockIdx.x * 128;

    float c[2][8][4];
#pragma unroll
    for (int a = 0; a < 2; a++)
#pragma unroll
        for (int b = 0; b < 8; b++)
#pragma unroll
            for (int r = 0; r < 4; r++) c[a][b][r] = 0.f;
    tf32_loop<true, FAST>(A, Bhi, Blo, FFN, D, 0, bn0, rowSlot, sm, c);

    const int lane = tid & 31, warp = tid >> 5;
    const int wm0 = (warp >> 1) * 32, wn0 = (warp & 1) * 64;
    const int g = lane >> 2, tig = lane & 3;
    const int colbase = bn0 + wn0;
#pragma unroll
    for (int mt = 0; mt < 2; mt++) {
#pragma unroll
        for (int half = 0; half < 2; half++) {
            int idx = bm0 + wm0 + mt * 16 + g + half * 8;
            if (idx >= cn) continue;
            int tok = tok2[lbase + idx];
            float rs = pi[tok * NS + s];
            float* cp = so + (long)tok * D + colbase;
#pragma unroll
            for (int nt = 0; nt < 8; nt++) {
                int col = nt * 8 + tig * 2;
                float v0 = rs * (c[mt][nt][half * 2] + bias[colbase + col]);
                float v1 = rs * (c[mt][nt][half * 2 + 1] + bias[colbase + col + 1]);
                if (RANK == 0) {
                    *(float2*)(cp + col) = make_float2(v0, v1);
                } else {
                    float2 old = *(float2*)(cp + col);
                    *(float2*)(cp + col) = make_float2(old.x + v0, old.y + v1);
                }
            }
        }
    }
}

// ---------------- small kernels ----------------
__global__ void emb_k(const int* __restrict__ x, const float* __restrict__ emb,
                      const float* __restrict__ pos, float* __restrict__ h)
{
    int n = blockIdx.x;
    int vx = x[n];
    int t = n % TSEQ;
    const float* e = emb + (long)vx * D;
    const float* p = pos + (long)t * D;
    for (int j = threadIdx.x; j < D; j += blockDim.x)
        h[(long)n * D + j] = e[j] + p[j];
}

__global__ void pi_init_k(float* __restrict__ pi)
{
    int i = blockIdx.x * blockDim.x + threadIdx.x;
    if (i < NTOK * NS) pi[i] = ((i % NS) == 2) ? 1.f : 0.f;
}

__global__ void reset_cnt_k(int* cnt, int* cnt2)
{
    if (threadIdx.x < NS) cnt[threadIdx.x] = 0;
    if (threadIdx.x < 2 * NS) cnt2[threadIdx.x] = 0;
}

__global__ void build_lists_k(const float* __restrict__ pi,
                              int* __restrict__ cnt, int* __restrict__ list,
                              int* __restrict__ cnt2, int* __restrict__ slot2,
                              int* __restrict__ tok2)
{
    int t = blockIdx.x * blockDim.x + threadIdx.x;
    if (t >= NTOK) return;
    int r = 0;
#pragma unroll
    for (int s = 0; s < NS; s++) {
        if (pi[t * NS + s] != 0.f) {
            int p = atomicAdd(&cnt[s], 1);
            list[s * NTOK + p] = t;
            int rr = min(r, 1);
            int q = atomicAdd(&cnt2[rr * NS + s], 1);
            slot2[(rr * NS + s) * NTOK + q] = p;
            tok2[(rr * NS + s) * NTOK + q] = t;
            r++;
        }
    }
}

__global__ void ln012_k(const float* __restrict__ mu, float* __restrict__ muhat,
                        float* __restrict__ mun, float* __restrict__ mur,
                        const float* __restrict__ ln_g, const float* __restrict__ ln_b)
{
    __shared__ float red[8];
    int n = blockIdx.x, tid = threadIdx.x;
    const float* row = mu + (long)n * D;
    float v[3], s = 0.f;
#pragma unroll
    for (int r = 0; r < 3; r++) { v[r] = row[tid + r * 256]; s += v[r]; }
    float mean = block_sum(s, red) / D;
    float qv = 0.f;
#pragma unroll
    for (int r = 0; r < 3; r++) { float d = v[r] - mean; qv += d * d; }
    float var = block_sum(qv, red) / D;
    float inv = rsqrtf(var + 1e-5f);
#pragma unroll
    for (int r = 0; r < 3; r++) {
        int j = tid + r * 256;
        float nh = (v[r] - mean) * inv;
        long idx = (long)n * D + j;
        muhat[idx] = nh;
        mun[idx] = nh * ln_g[j] + ln_b[j];
        mur[idx] = nh * ln_g[2 * D + j] + ln_b[2 * D + j];
    }
}

__global__ void ln_gen_k(const float* __restrict__ in, float* __restrict__ out,
                         const float* __restrict__ g, const float* __restrict__ b)
{
    __shared__ float red[8];
    int n = blockIdx.x, tid = threadIdx.x;
    const float* row = in + (long)n * D;
    float v[3], s = 0.f;
#pragma unroll
    for (int r = 0; r < 3; r++) { v[r] = row[tid + r * 256]; s += v[r]; }
    float mean = block_sum(s, red) / D;
    float qv = 0.f;
#pragma unroll
    for (int r = 0; r < 3; r++) { float d = v[r] - mean; qv += d * d; }
    float var = block_sum(qv, red) / D;
    float inv = rsqrtf(var + 1e-5f);
#pragma unroll
    for (int r = 0; r < 3; r++) {
        int j = tid + r * 256;
        out[(long)n * D + j] = (v[r] - mean) * inv * g[j] + b[j];
    }
}

// LN then tf32-round (rna) — feeds the pure-tf32 logits GEMM
__global__ void ln_cvt_k(const float* __restrict__ in, float* __restrict__ out,
                         const float* __restrict__ g, const float* __restrict__ b)
{
    __shared__ float red[8];
    int n = blockIdx.x, tid = threadIdx.x;
    const float* row = in + (long)n * D;
    float v[3], s = 0.f;
#pragma unroll
    for (int r = 0; r < 3; r++) { v[r] = row[tid + r * 256]; s += v[r]; }
    float mean = block_sum(s, red) / D;
    float qv = 0.f;
#pragma unroll
    for (int r = 0; r < 3; r++) { float d = v[r] - mean; qv += d * d; }
    float var = block_sum(qv, red) / D;
    float inv = rsqrtf(var + 1e-5f);
#pragma unroll
    for (int r = 0; r < 3; r++) {
        int j = tid + r * 256;
        float val = (v[r] - mean) * inv * g[j] + b[j];
        out[(long)n * D + j] = cvt_hi(val);
    }
}

__global__ void routing_k(const float* __restrict__ trh, const float* __restrict__ w2,
                          const float* __restrict__ b2, const float* __restrict__ mun,
                          const float* __restrict__ evw, const float* __restrict__ evb,
                          float* __restrict__ pi)
{
    __shared__ float sh[1536];
    __shared__ float smn[D];
    __shared__ float kz[36];
    __shared__ float ev[6];
    __shared__ float spi[6];
    int n = blockIdx.x, tid = threadIdx.x;
    for (int i = tid; i < 1536; i += 128) sh[i] = trh[(long)n * 1536 + i];
    for (int i = tid; i < D; i += 128)    smn[i] = mun[(long)n * D + i];
    if (tid < NS) spi[tid] = pi[n * NS + tid];
    __syncthreads();
    if (tid < 36) {
        float acc = b2[tid];
        for (int k = 0; k < 1536; k++) acc += sh[k] * w2[k * 36 + tid];
        kz[tid] = acc;
    } else if (tid < 42) {
        int j = tid - 36;
        float acc = evb[j];
        for (int k = 0; k < D; k++) acc += smn[k] * evw[k * NS + j];
        ev[j] = acc;
    }
    __syncthreads();
    if (tid == 0) {
        float Kr[6][6];
        for (int s = 0; s < 6; s++) {
            float mx = kz[s * 6];
            for (int u = 1; u < 6; u++) mx = fmaxf(mx, kz[s * 6 + u]);
            float sum = 0.f;
            for (int u = 0; u < 6; u++) { float e = expf(kz[s * 6 + u] - mx); Kr[s][u] = e; sum += e; }
            float invr = 1.f / sum;
            for (int u = 0; u < 6; u++) Kr[s][u] *= invr;
        }
        float pev[6];
        for (int u = 0; u < 6; u++) {
            float a = 0.f;
            for (int s = 0; s < 6; s++) a += spi[s] * Kr[s][u];
            pev[u] = a;
        }
        float mx = ev[0] * 2.f;
        for (int u = 1; u < 6; u++) mx = fmaxf(mx, ev[u] * 2.f);
        float wv[6], sw = 0.f;
        for (int u = 0; u < 6; u++) { wv[u] = expf(ev[u] * 2.f - mx); sw += wv[u]; }
        float invw = 1.f / sw;
        float pn[6], s1 = 0.f;
        for (int u = 0; u < 6; u++) { pn[u] = pev[u] * wv[u] * invw; s1 += pn[u]; }
        float inv1 = 1.f / fmaxf(s1, 1e-8f);
        for (int u = 0; u < 6; u++) pn[u] *= inv1;
        int i1 = 0;
        for (int u = 1; u < 6; u++) if (pn[u] > pn[i1]) i1 = u;
        int i2 = (i1 == 0) ? 1 : 0;
        for (int u = 0; u < 6; u++) if (u != i1 && pn[u] > pn[i2]) i2 = u;
        float inv2 = 1.f / fmaxf(pn[i1] + pn[i2], 1e-8f);
        for (int u = 0; u < 6; u++)
            pi[n * NS + u] = (u == i1 || u == i2) ? pn[u] * inv2 : 0.f;
    }
}

__global__ void attn_k(const float* __restrict__ q, const float* __restrict__ k,
                       const float* __restrict__ v, const float* __restrict__ pi,
                       const float* __restrict__ ln_g, const float* __restrict__ ln_b,
                       float* __restrict__ msg)
{
    __shared__ float sw[4];
    __shared__ float mb[D];
    __shared__ float red[8];
    int n = blockIdx.x, tid = threadIdx.x;
    int t = n % TSEQ;
    int warp = tid >> 5, lane = tid & 31;
    const int offs[4] = {-2, -1, 1, 2};
    {
        int o = offs[warp];
        int tt = t + o;
        float dot = 0.f;
        if (tt >= 0 && tt < TSEQ) {
            const float* qp = q + (long)n * D;
            const float* kp = k + (long)(n + o) * D;
            for (int j = lane; j < D; j += 32) dot += qp[j] * kp[j];
        }
#pragma unroll
        for (int s = 16; s > 0; s >>= 1) dot += __shfl_xor_sync(0xffffffffu, dot, s);
        if (lane == 0)
            sw[warp] = (tt >= 0 && tt < TSEQ) ? dot / 27.712812921102035f : -1e9f;
    }
    __syncthreads();
    float w0 = sw[0], w1 = sw[1], w2 = sw[2], w3 = sw[3];
    float mx = fmaxf(fmaxf(w0, w1), fmaxf(w2, w3));
    float wt[4] = {expf(w0 - mx), expf(w1 - mx), expf(w2 - mx), expf(w3 - mx)};
    float invs = 1.f / (wt[0] + wt[1] + wt[2] + wt[3]);
#pragma unroll
    for (int w = 0; w < 4; w++) wt[w] *= invs;
    float pi3 = pi[n * NS + 3];
    for (int j = tid; j < D; j += 128) {
        float m = 0.f;
#pragma unroll
        for (int w = 0; w < 4; w++) {
            int tt = t + offs[w];
            if (tt >= 0 && tt < TSEQ) m += wt[w] * v[(long)(n + offs[w]) * D + j];
        }
        mb[j] = m * pi3;
    }
    __syncthreads();
    float loc[6], s = 0.f;
#pragma unroll
    for (int r = 0; r < 6; r++) { loc[r] = mb[tid + r * 128]; s += loc[r]; }
    float mean = block_sum(s, red) / D;
    float qv = 0.f;
#pragma unroll
    for (int r = 0; r < 6; r++) { float d = loc[r] - mean; qv += d * d; }
    float var = block_sum(qv, red) / D;
    float inv = rsqrtf(var + 1e-5f);
#pragma unroll
    for (int r = 0; r < 6; r++) {
        int j = tid + r * 128;
        msg[(long)n * D + j] = (loc[r] - mean) * inv * ln_g[3 * D + j] + ln_b[3 * D + j];
    }
}

__global__ void update_k(const float* __restrict__ muhat, float* __restrict__ lam,
                         const float* __restrict__ dlam, const float* __restrict__ mhat,
                         const float* __restrict__ so,
                         const float* __restrict__ ln_g, const float* __restrict__ ln_b,
                         float* __restrict__ mu)
{
    __shared__ float red[8];
    int n = blockIdx.x, tid = threadIdx.x;
    float mval[3], s = 0.f;
#pragma unroll
    for (int r = 0; r < 3; r++) {
        int j = tid + r * 256;
        long idx = (long)n * D + j;
        float l = lam[idx], dl = dlam[idx];
        float mwn = muhat[idx] * ln_g[4 * D + j] + ln_b[4 * D + j];
        float lnw = l + dl;
        float m = (l * mwn + dl * mhat[idx]) / lnw;
        lam[idx] = lnw;
        mval[r] = m;
        s += m;
    }
    float mean = block_sum(s, red) / D;
    float qv = 0.f;
#pragma unroll
    for (int r = 0; r < 3; r++) { float d = mval[r] - mean; qv += d * d; }
    float var = block_sum(qv, red) / D;
    float inv = rsqrtf(var + 1e-5f);
#pragma unroll
    for (int r = 0; r < 3; r++) {
        int j = tid + r * 256;
        long idx = (long)n * D + j;
        mu[idx] = (mval[r] - mean) * inv * ln_g[5 * D + j] + ln_b[5 * D + j] + so[idx] * 0.1f;
    }
}

// ---------------- launcher ----------------
extern "C" void kernel_launch(void* const* d_in, const int* in_sizes, int n_in,
                              void* d_out, int out_size)
{
    const int*   x        = (const int*)d_in[0];
    const float* emb_w    = (const float*)d_in[1];
    const float* pos_w    = (const float*)d_in[2];
    const float* mu_w     = (const float*)d_in[3];
    const float* mu_b     = (const float*)d_in[4];
    const float* lam_w    = (const float*)d_in[5];
    const float* lam_b    = (const float*)d_in[6];
    const float* tr_w1    = (const float*)d_in[7];
    const float* tr_b1    = (const float*)d_in[8];
    const float* tr_w2    = (const float*)d_in[9];
    const float* tr_b2    = (const float*)d_in[10];
    const float* bank_w1  = (const float*)d_in[11];
    const float* bank_b1  = (const float*)d_in[12];
    const float* bank_w2  = (const float*)d_in[13];
    const float* bank_b2  = (const float*)d_in[14];
    const float* ev_w     = (const float*)d_in[15];
    const float* ev_b     = (const float*)d_in[16];
    const float* rt_q     = (const float*)d_in[17];
    const float* rt_k     = (const float*)d_in[18];
    const float* rt_v     = (const float*)d_in[19];
    const float* wr_lam_w = (const float*)d_in[20];
    const float* wr_lam_b = (const float*)d_in[21];
    const float* wr_mu_w  = (const float*)d_in[22];
    const float* wr_mu_b  = (const float*)d_in[23];
    const float* ln_g     = (const float*)d_in[24];
    const float* ln_b     = (const float*)d_in[25];
    float* out = (float*)d_out;

    cudaFuncSetAttribute(tgemm_k<EPI_GELU, false>, cudaFuncAttributeMaxDynamicSharedMemorySize, SM_BYTES);
    cudaFuncSetAttribute(tgemm_pair_k<EPI_BIAS, EPI_SP01, false>, cudaFuncAttributeMaxDynamicSharedMemorySize, SM_BYTES);
    cudaFuncSetAttribute(tgemm_pair_k<EPI_GSP, EPI_BIAS, false>, cudaFuncAttributeMaxDynamicSharedMemorySize, SM_BYTES);
    cudaFuncSetAttribute(tgemm_pair_k<EPI_GSP, EPI_BIAS, true>, cudaFuncAttributeMaxDynamicSharedMemorySize, SM_BYTES);
    cudaFuncSetAttribute(tqkv_k<false>, cudaFuncAttributeMaxDynamicSharedMemorySize, SM_BYTES);
    cudaFuncSetAttribute(tqkv_k<true>, cudaFuncAttributeMaxDynamicSharedMemorySize, SM_BYTES);
    cudaFuncSetAttribute(tbank1_k<false>, cudaFuncAttributeMaxDynamicSharedMemorySize, SM_BYTES);
    cudaFuncSetAttribute(tbank1_k<true>, cudaFuncAttributeMaxDynamicSharedMemorySize, SM_BYTES);
    cudaFuncSetAttribute(tbank2_k<0, false>, cudaFuncAttributeMaxDynamicSharedMemorySize, SM_BYTES);
    cudaFuncSetAttribute(tbank2_k<1, false>, cudaFuncAttributeMaxDynamicSharedMemorySize, SM_BYTES);
    cudaFuncSetAttribute(tbank2_k<0, true>, cudaFuncAttributeMaxDynamicSharedMemorySize, SM_BYTES);
    cudaFuncSetAttribute(tbank2_k<1, true>, cudaFuncAttributeMaxDynamicSharedMemorySize, SM_BYTES);
    cudaFuncSetAttribute(tlogits_k, cudaFuncAttributeMaxDynamicSharedMemorySize, LG_SM_BYTES);

    float* base = nullptr;
    cudaGetSymbolAddress((void**)&base, g_scratch);
    float *whi = nullptr, *wlo = nullptr;
    cudaGetSymbolAddress((void**)&whi, g_whi);
    cudaGetSymbolAddress((void**)&wlo, g_wlo);
    int *cnt, *list, *cnt2, *slot2, *tok2;
    cudaGetSymbolAddress((void**)&cnt, g_cnt);
    cudaGetSymbolAddress((void**)&list, g_list);
    cudaGetSymbolAddress((void**)&cnt2, g_cnt2);
    cudaGetSymbolAddress((void**)&slot2, g_slot2);
    cudaGetSymbolAddress((void**)&tok2, g_tok2);

    float* h     = base + OFF_H;
    float* mu    = base + OFF_MU;
    float* muhat = base + OFF_MUHAT;
    float* mun   = base + OFF_MUN;
    float* mur   = base + OFF_MUR;
    float* so    = base + OFF_SO;
    float* qb    = base + OFF_Q;
    float* lam   = base + OFF_LAM;
    float* msg   = base + OFF_MSG;
    float* dlam  = base + OFF_DLAM;
    float* mhat  = base + OFF_MHAT;
    float* fin   = base + OFF_FIN;
    float* trh   = base + OFF_TRH;
    float* hb    = base + OFF_HB;
    float* pi    = base + OFF_PI;

    const float inv_sqrt_d = 0.03608439182435161f;

    // ---- weight prep: split (and transpose emb hi) into arena ----
    {
        const int DD4 = D * D / 4;
        split_k<<<(DD4 + 255) / 256, 256>>>(mu_w,     whi + W_MU,  wlo + W_MU,  DD4);
        split_k<<<(DD4 + 255) / 256, 256>>>(lam_w,    whi + W_LAM, wlo + W_LAM, DD4);
        split_k<<<(D * 1536 / 4 + 255) / 256, 256>>>(tr_w1, whi + W_TR1, wlo + W_TR1, D * 1536 / 4);
        split_k<<<(DD4 + 255) / 256, 256>>>(rt_q,     whi + W_RTQ, wlo + W_RTQ, DD4);
        split_k<<<(DD4 + 255) / 256, 256>>>(rt_k,     whi + W_RTK, wlo + W_RTK, DD4);
        split_k<<<(DD4 + 255) / 256, 256>>>(rt_v,     whi + W_RTV, wlo + W_RTV, DD4);
        split_k<<<(DD4 + 255) / 256, 256>>>(wr_lam_w, whi + W_WRL, wlo + W_WRL, DD4);
        split_k<<<(DD4 + 255) / 256, 256>>>(wr_mu_w,  whi + W_WRM, wlo + W_WRM, DD4);
        const int B14 = NS * D * FFN / 4;
        split_k<<<(B14 + 255) / 256, 256>>>(bank_w1, whi + W_B1, wlo + W_B1, B14);
        split_k<<<(B14 + 255) / 256, 256>>>(bank_w2, whi + W_B2, wlo + W_B2, B14);
        dim3 gt(VOC / 32, D / 32);
        tsplit_emb_k<<<gt, dim3(32, 8)>>>(emb_w, whi + W_EMBT);
    }

    emb_k<<<NTOK, 256>>>(x, emb_w, pos_w, h);
    {
        dim3 g(D / 128, NTOK / 128, 2);
        tgemm_pair_k<EPI_BIAS, EPI_SP01, false><<<g, 256, SM_BYTES>>>(
            h, whi + W_MU, wlo + W_MU, mu_b, lam_b, nullptr, mu);
    }
    pi_init_k<<<(NTOK * NS + 255) / 256, 256>>>(pi);

    for (int step = 0; step < 3; step++) {
        const bool last = (step == 2);
        ln012_k<<<NTOK, 256>>>(mu, muhat, mun, mur, ln_g, ln_b);
        {
            dim3 g(1536 / 128, NTOK / 128);
            tgemm_k<EPI_GELU, false><<<g, 256, SM_BYTES>>>(mu, whi + W_TR1, wlo + W_TR1,
                                                           tr_b1, trh, 1536, D, nullptr);
        }
        reset_cnt_k<<<1, 32>>>(cnt, cnt2);
        build_lists_k<<<NTOK / 256, 256>>>(pi, cnt, list, cnt2, slot2, tok2);
        {
            dim3 g1(FFN / 128, NTOK / 128, NS);
            dim3 g2(D / 128, NTOK / 128, NS);
            if (!last) {
                tbank1_k<false><<<g1, 256, SM_BYTES>>>(mun, whi + W_B1, wlo + W_B1, bank_b1, hb, list, cnt);
                tbank2_k<0, false><<<g2, 256, SM_BYTES>>>(hb, whi + W_B2, wlo + W_B2, bank_b2,
                                                          so, cnt2, slot2, tok2, pi);
                tbank2_k<1, false><<<g2, 256, SM_BYTES>>>(hb, whi + W_B2, wlo + W_B2, bank_b2,
                                                          so, cnt2, slot2, tok2, pi);
            } else {
                tbank1_k<true><<<g1, 256, SM_BYTES>>>(mun, whi + W_B1, wlo + W_B1, bank_b1, hb, list, cnt);
                tbank2_k<0, true><<<g2, 256, SM_BYTES>>>(hb, whi + W_B2, wlo + W_B2, bank_b2,
                                                         so, cnt2, slot2, tok2, pi);
                tbank2_k<1, true><<<g2, 256, SM_BYTES>>>(hb, whi + W_B2, wlo + W_B2, bank_b2,
                                                         so, cnt2, slot2, tok2, pi);
            }
        }
        ln_gen_k<<<NTOK, 256>>>(so, so, ln_g + 1 * D, ln_b + 1 * D);
        routing_k<<<NTOK, 128>>>(trh, tr_w2, tr_b2, mun, ev_w, ev_b, pi);
        {
            dim3 g(D / 128, NTOK / 128, 3);
            if (!last) tqkv_k<false><<<g, 256, SM_BYTES>>>(mur, whi + W_RTQ, wlo + W_RTQ, qb);
            else       tqkv_k<true><<<g, 256, SM_BYTES>>>(mur, whi + W_RTQ, wlo + W_RTQ, qb);
        }
        attn_k<<<NTOK, 128>>>(qb, qb + ROW, qb + 2 * ROW, pi, ln_g, ln_b, msg);
        {
            dim3 g(D / 128, NTOK / 128, 2);
            if (!last)
                tgemm_pair_k<EPI_GSP, EPI_BIAS, false><<<g, 256, SM_BYTES>>>(
                    msg, whi + W_WRL, wlo + W_WRL, wr_lam_b, wr_mu_b, pi, dlam);
            else
                tgemm_pair_k<EPI_GSP, EPI_BIAS, true><<<g, 256, SM_BYTES>>>(
                    msg, whi + W_WRL, wlo + W_WRL, wr_lam_b, wr_mu_b, pi, dlam);
        }
        update_k<<<NTOK, 256>>>(muhat, lam, dlam, mhat, so, ln_g, ln_b, mu);
    }

    // final LN with tf32 rounding at producer; pure-tf32 logits GEMM
    ln_cvt_k<<<NTOK, 256>>>(mu, fin, ln_g + 6 * D, ln_b + 6 * D);
    {
        dim3 g(NTOK / 128, VOC / 128);  // x = M-tiles: concurrent CTAs share B
        tlogits_k<<<g, 256, LG_SM_BYTES>>>(fin, whi + W_EMBT, out, VOC, D, inv_sqrt_d);
    }
}

// round 15
// speedup vs baseline: 1.6297x; 1.0594x over previous
#include <cuda_runtime.h>
#include <math.h>
#include <stdint.h>

#define NTOK 2048
#define TSEQ 1024
#define D    768
#define FFN  3072
#define NS   6
#define VOC  32000

// ---------------- scratch ----------------
#define ROW (NTOK*D)
#define OFF_H     0
#define OFF_MU    (1*ROW)
#define OFF_LAM   (2*ROW)
#define OFF_MUHAT (3*ROW)
#define OFF_MUN   (4*ROW)
#define OFF_MUR   (5*ROW)
#define OFF_SO    (6*ROW)
#define OFF_Q     (7*ROW)
#define OFF_K     (8*ROW)
#define OFF_V     (9*ROW)
#define OFF_MSG   (10*ROW)
#define OFF_DLAM  (11*ROW)
#define OFF_MHAT  (12*ROW)
#define OFF_FIN   (13*ROW)
#define OFF_TRH   (14*ROW)
#define OFF_HB    (14*ROW + NTOK*1536)
#define OFF_PI    (OFF_HB + NS*NTOK*FFN)
#define SCRATCH_FLOATS (OFF_PI + NTOK*NS)

__device__ float g_scratch[SCRATCH_FLOATS];
__device__ int   g_cnt[NS];
__device__ int   g_list[NS * NTOK];
__device__ int   g_cnt2[2 * NS];
__device__ int   g_slot2[2 * NS * NTOK];
__device__ int   g_tok2[2 * NS * NTOK];

// ---------------- pre-split weight arena (hi/lo tf32 split) ----------------
#define W_MU   0
#define W_LAM  589824
#define W_TR1  1179648
#define W_RTQ  2359296
#define W_RTK  2949120
#define W_RTV  3538944
#define W_WRL  4128768
#define W_WRM  4718592
#define W_B1   5308416
#define W_B2   19464192
#define W_EMBT 33619968
#define WSPLIT 58195968

__device__ float g_whi[WSPLIT];
__device__ float g_wlo[WSPLIT];

// ---------------- helpers ----------------
__device__ __forceinline__ float gelu_f(float x) {
    float x3 = x * x * x;
    return 0.5f * x * (1.f + tanhf(0.7978845608028654f * (x + 0.044715f * x3)));
}
__device__ __forceinline__ float softplus_f(float x) {
    return fmaxf(x, 0.f) + log1pf(expf(-fabsf(x)));
}
__device__ __forceinline__ float block_sum(float v, float* red) {
    int tid = threadIdx.x;
    __syncthreads();
#pragma unroll
    for (int o = 16; o > 0; o >>= 1) v += __shfl_xor_sync(0xffffffffu, v, o);
    if ((tid & 31) == 0) red[tid >> 5] = v;
    __syncthreads();
    if (tid < 32) {
        float t = (tid < (int)(blockDim.x >> 5)) ? red[tid] : 0.f;
#pragma unroll
        for (int o = 4; o > 0; o >>= 1) t += __shfl_xor_sync(0xffffffffu, t, o);
        if (tid == 0) red[0] = t;
    }
    __syncthreads();
    return red[0];
}

// hi = tf32-rounded x; lo = exact fp32 remainder (mma truncates lo internally)
__device__ __forceinline__ void cvt_split(float x, float& hi, float& lo) {
    uint32_t hb; asm("cvt.rna.tf32.f32 %0, %1;" : "=r"(hb) : "f"(x));
    hi = __uint_as_float(hb);
    lo = x - hi;
}
__device__ __forceinline__ float cvt_hi(float x) {
    uint32_t hb; asm("cvt.rna.tf32.f32 %0, %1;" : "=r"(hb) : "f"(x));
    return __uint_as_float(hb);
}

// ---------------- weight prep kernels ----------------
__global__ void split_k(const float* __restrict__ src, float* __restrict__ hi,
                        float* __restrict__ lo, int n4)
{
    int i = blockIdx.x * blockDim.x + threadIdx.x;
    if (i >= n4) return;
    float4 v = ((const float4*)src)[i];
    float4 h, l;
    cvt_split(v.x, h.x, l.x); cvt_split(v.y, h.y, l.y);
    cvt_split(v.z, h.z, l.z); cvt_split(v.w, h.w, l.w);
    ((float4*)hi)[i] = h;
    ((float4*)lo)[i] = l;
}

// transpose emb_w [VOC][D] -> [D][VOC] tf32-hi only (logits is pure tf32)
__global__ void tsplit_emb_k(const float* __restrict__ emb, float* __restrict__ hi)
{
    __shared__ float tile[32][33];
    int v0 = blockIdx.x * 32, d0 = blockIdx.y * 32;
    int tx = threadIdx.x, ty = threadIdx.y; // 32 x 8
    for (int r = ty; r < 32; r += 8)
        tile[r][tx] = emb[(long)(v0 + r) * D + d0 + tx];
    __syncthreads();
    for (int r = ty; r < 32; r += 8)
        hi[(long)(d0 + r) * VOC + v0 + tx] = cvt_hi(tile[tx][r]);
}

// ---------------- tf32 mma core ----------------
// smem (float offsets): RAWA[3][128][20] @0 (7680),
// BHI[3][16][136] @7680 (6528), BLO[3][16][136] @14208 (6528)
// total 20736 floats = 82944 B -> 2 CTAs/SM
#define A_ST    2560
#define B_STF   2176
#define SM_RAWA 0
#define SM_BHI  7680
#define SM_BLO  14208
#define SM_BYTES (20736 * 4)

__device__ __forceinline__ void mma8(float* c, const uint32_t* a, uint32_t b0, uint32_t b1) {
    asm volatile(
        "mma.sync.aligned.m16n8k8.row.col.f32.tf32.tf32.f32 "
        "{%0,%1,%2,%3},{%4,%5,%6,%7},{%8,%9},{%0,%1,%2,%3};"
        : "+f"(c[0]), "+f"(c[1]), "+f"(c[2]), "+f"(c[3])
        : "r"(a[0]), "r"(a[1]), "r"(a[2]), "r"(a[3]), "r"(b0), "r"(b1));
}

__device__ __forceinline__ void cp16(uint32_t dst, const float* src) {
    asm volatile("cp.async.ca.shared.global [%0], [%1], 16;" :: "r"(dst), "l"(src) : "memory");
}

// block 128x128, 8 warps (4m x 2n), warp tile 32x64, BK=16.
// MODE 0: 3-term split (ah*bh + al*bh + ah*bl) — routing-relevant GEMMs.
// MODE 1: 2-term (ah*bh + al*bh), Blo never loaded.
// MODE 2: pure tf32 (ah*bh only) — ONLY where error cannot reach a top-k
//         routing decision (last-step bank/qkv/wr; logits kernel separate).
template <bool GATHER, int MODE>
__device__ __forceinline__ void tf32_loop(
    const float* __restrict__ A, const float* __restrict__ Bhi,
    const float* __restrict__ Blo,
    int K, int N, int bm0, int bn0, const int* __restrict__ rowTok,
    float* __restrict__ sm, float c[2][8][4])
{
    const int tid = threadIdx.x;
    const int lane = tid & 31, warp = tid >> 5;
    const int wm0 = (warp >> 1) * 32, wn0 = (warp & 1) * 64;
    const int g = lane >> 2, tig = lane & 3;

    const int arow0 = tid >> 2, arow1 = arow0 + 64, aq = tid & 3;
    long agr0, agr1;
    if (GATHER) { agr0 = rowTok[arow0]; agr1 = rowTok[arow1]; }
    else        { agr0 = bm0 + arow0;   agr1 = bm0 + arow1;   }
    const int bkr = tid >> 5;
    const int bn4 = (tid & 31) * 4;

    const uint32_t smb = (uint32_t)__cvta_generic_to_shared(sm);

    auto issue = [&](int st, int k0) {
        uint32_t ra = smb + (uint32_t)(SM_RAWA + st * A_ST) * 4u;
        cp16(ra + (uint32_t)(arow0 * 20 + aq * 4) * 4u, A + agr0 * K + k0 + aq * 4);
        cp16(ra + (uint32_t)(arow1 * 20 + aq * 4) * 4u, A + agr1 * K + k0 + aq * 4);
        uint32_t bh = smb + (uint32_t)(SM_BHI + st * B_STF) * 4u;
        cp16(bh + (uint32_t)(bkr * 136 + bn4) * 4u,
             Bhi + (long)(k0 + bkr) * N + bn0 + bn4);
        cp16(bh + (uint32_t)((bkr + 8) * 136 + bn4) * 4u,
             Bhi + (long)(k0 + bkr + 8) * N + bn0 + bn4);
        if (MODE == 0) {
            uint32_t bl = smb + (uint32_t)(SM_BLO + st * B_STF) * 4u;
            cp16(bl + (uint32_t)(bkr * 136 + bn4) * 4u,
                 Blo + (long)(k0 + bkr) * N + bn0 + bn4);
            cp16(bl + (uint32_t)((bkr + 8) * 136 + bn4) * 4u,
                 Blo + (long)(k0 + bkr + 8) * N + bn0 + bn4);
        }
        asm volatile("cp.async.commit_group;" ::: "memory");
    };

    auto comp = [&](int st) {
        const float* rap = sm + SM_RAWA + st * A_ST;
        const float* bhp = sm + SM_BHI + st * B_STF;
        const float* blp = sm + SM_BLO + st * B_STF;
#pragma unroll
        for (int ks = 0; ks < 16; ks += 8) {
            uint32_t ah[2][4], al[2][4];
#pragma unroll
            for (int mt = 0; mt < 2; mt++) {
                int rb = wm0 + mt * 16 + g;
                float r0 = rap[rb * 20 + ks + tig];
                float r1 = rap[(rb + 8) * 20 + ks + tig];
                float r2 = rap[rb * 20 + ks + tig + 4];
                float r3 = rap[(rb + 8) * 20 + ks + tig + 4];
                if (MODE == 2) {
                    ah[mt][0] = __float_as_uint(cvt_hi(r0));
                    ah[mt][1] = __float_as_uint(cvt_hi(r1));
                    ah[mt][2] = __float_as_uint(cvt_hi(r2));
                    ah[mt][3] = __float_as_uint(cvt_hi(r3));
                } else {
                    float hf, lf;
                    cvt_split(r0, hf, lf); ah[mt][0] = __float_as_uint(hf); al[mt][0] = __float_as_uint(lf);
                    cvt_split(r1, hf, lf); ah[mt][1] = __float_as_uint(hf); al[mt][1] = __float_as_uint(lf);
                    cvt_split(r2, hf, lf); ah[mt][2] = __float_as_uint(hf); al[mt][2] = __float_as_uint(lf);
                    cvt_split(r3, hf, lf); ah[mt][3] = __float_as_uint(hf); al[mt][3] = __float_as_uint(lf);
                }
            }
#pragma unroll
            for (int nt = 0; nt < 8; nt++) {
                int cb = wn0 + nt * 8 + g;
                uint32_t bh0 = __float_as_uint(bhp[(ks + tig) * 136 + cb]);
                uint32_t bh1 = __float_as_uint(bhp[(ks + tig + 4) * 136 + cb]);
#pragma unroll
                for (int mt = 0; mt < 2; mt++) {
                    mma8(c[mt][nt], ah[mt], bh0, bh1);
                    if (MODE <= 1) mma8(c[mt][nt], al[mt], bh0, bh1);
                }
                if (MODE == 0) {
                    uint32_t bl0 = __float_as_uint(blp[(ks + tig) * 136 + cb]);
                    uint32_t bl1 = __float_as_uint(blp[(ks + tig + 4) * 136 + cb]);
#pragma unroll
                    for (int mt = 0; mt < 2; mt++)
                        mma8(c[mt][nt], ah[mt], bl0, bl1);
                }
            }
        }
    };

    const int nk = K >> 4;  // >= 48 at all call sites
    issue(0, 0);
    issue(1, 16);
    int st = 0, stn = 2;
    for (int i = 0; i < nk; i++) {
        if (i < nk - 1) asm volatile("cp.async.wait_group 1;" ::: "memory");
        else            asm volatile("cp.async.wait_group 0;" ::: "memory");
        __syncthreads();
        if (i + 2 < nk) {
            issue(stn, (i + 2) << 4);
            stn = (stn == 2) ? 0 : stn + 1;
        }
        comp(st);
        st = (st == 2) ? 0 : st + 1;
    }
}

// ---------------- pure-tf32 logits GEMM ----------------
// Grid: (M-tiles, N-tiles) so concurrent CTAs share B columns.
// smem: AHI[3][128][20] @0, BHI[3][16][136] @7680 -> 14208 fl = 56832 B
#define LG_SM_BYTES (14208 * 4)

__global__ void __launch_bounds__(256, 2) tlogits_k(
    const float* __restrict__ Ahi, const float* __restrict__ Bhi,
    float* __restrict__ C, int N, int K, float alpha)
{
    extern __shared__ float sm[];
    const int tid = threadIdx.x;
    const int lane = tid & 31, warp = tid >> 5;
    const int wm0 = (warp >> 1) * 32, wn0 = (warp & 1) * 64;
    const int g = lane >> 2, tig = lane & 3;
    const int bm0 = blockIdx.x * 128, bn0 = blockIdx.y * 128;

    const int arow0 = tid >> 2, arow1 = arow0 + 64, aq = tid & 3;
    const long agr0 = bm0 + arow0, agr1 = bm0 + arow1;
    const int bkr = tid >> 5;
    const int bn4 = (tid & 31) * 4;
    const uint32_t smb = (uint32_t)__cvta_generic_to_shared(sm);

    float c[2][8][4];
#pragma unroll
    for (int a = 0; a < 2; a++)
#pragma unroll
        for (int b = 0; b < 8; b++)
#pragma unroll
            for (int r = 0; r < 4; r++) c[a][b][r] = 0.f;

    auto issue = [&](int st, int k0) {
        uint32_t ah = smb + (uint32_t)(st * A_ST) * 4u;
        cp16(ah + (uint32_t)(arow0 * 20 + aq * 4) * 4u, Ahi + agr0 * K + k0 + aq * 4);
        cp16(ah + (uint32_t)(arow1 * 20 + aq * 4) * 4u, Ahi + agr1 * K + k0 + aq * 4);
        uint32_t bh = smb + (uint32_t)(SM_BHI + st * B_STF) * 4u;
        cp16(bh + (uint32_t)(bkr * 136 + bn4) * 4u,
             Bhi + (long)(k0 + bkr) * N + bn0 + bn4);
        cp16(bh + (uint32_t)((bkr + 8) * 136 + bn4) * 4u,
             Bhi + (long)(k0 + bkr + 8) * N + bn0 + bn4);
        asm volatile("cp.async.commit_group;" ::: "memory");
    };

    auto comp = [&](int st) {
        const float* ahp = sm + st * A_ST;
        const float* bhp = sm + SM_BHI + st * B_STF;
#pragma unroll
        for (int ks = 0; ks < 16; ks += 8) {
            uint32_t ah[2][4];
#pragma unroll
            for (int mt = 0; mt < 2; mt++) {
                int rb = wm0 + mt * 16 + g;
                ah[mt][0] = __float_as_uint(ahp[rb * 20 + ks + tig]);
                ah[mt][1] = __float_as_uint(ahp[(rb + 8) * 20 + ks + tig]);
                ah[mt][2] = __float_as_uint(ahp[rb * 20 + ks + tig + 4]);
                ah[mt][3] = __float_as_uint(ahp[(rb + 8) * 20 + ks + tig + 4]);
            }
#pragma unroll
            for (int nt = 0; nt < 8; nt++) {
                int cb = wn0 + nt * 8 + g;
                uint32_t bh0 = __float_as_uint(bhp[(ks + tig) * 136 + cb]);
                uint32_t bh1 = __float_as_uint(bhp[(ks + tig + 4) * 136 + cb]);
#pragma unroll
                for (int mt = 0; mt < 2; mt++)
                    mma8(c[mt][nt], ah[mt], bh0, bh1);
            }
        }
    };

    const int nk = K >> 4;  // 48
    issue(0, 0);
    issue(1, 16);
    int st = 0, stn = 2;
    for (int i = 0; i < nk; i++) {
        if (i < nk - 1) asm volatile("cp.async.wait_group 1;" ::: "memory");
        else            asm volatile("cp.async.wait_group 0;" ::: "memory");
        __syncthreads();
        if (i + 2 < nk) {
            issue(stn, (i + 2) << 4);
            stn = (stn == 2) ? 0 : stn + 1;
        }
        comp(st);
        st = (st == 2) ? 0 : st + 1;
    }

    const int colbase = bn0 + wn0;
#pragma unroll
    for (int mt = 0; mt < 2; mt++) {
#pragma unroll
        for (int half = 0; half < 2; half++) {
            int row = bm0 + wm0 + mt * 16 + g + half * 8;
            float* cp = C + (long)row * N + colbase;
#pragma unroll
            for (int nt = 0; nt < 8; nt++) {
                int col = nt * 8 + tig * 2;
                *(float2*)(cp + col) = make_float2(c[mt][nt][half * 2] * alpha,
                                                   c[mt][nt][half * 2 + 1] * alpha);
            }
        }
    }
}

// ---------------- epilogues ----------------
enum { EPI_NONE = 0, EPI_BIAS = 1, EPI_GELU = 2, EPI_GSP = 3, EPI_SP01 = 5 };

template <int EPI>
__device__ __forceinline__ float epi_apply(float v, float b, float rs) {
    if (EPI == EPI_BIAS)  return v + b;
    if (EPI == EPI_GELU)  return gelu_f(v + b);
    if (EPI == EPI_GSP)   return rs * softplus_f(v + b);
    if (EPI == EPI_SP01)  return softplus_f(v + b) + 0.1f;
    return v;
}

template <int EPI>
__device__ __forceinline__ void epi_store_dense(
    float c[2][8][4], float* __restrict__ C, const float* __restrict__ bias,
    int N, int bm0, int bn0, const float* __restrict__ pi)
{
    const int tid = threadIdx.x, lane = tid & 31, warp = tid >> 5;
    const int wm0 = (warp >> 1) * 32, wn0 = (warp & 1) * 64;
    const int g = lane >> 2, tig = lane & 3;
    const int colbase = bn0 + wn0;
#pragma unroll
    for (int mt = 0; mt < 2; mt++) {
#pragma unroll
        for (int half = 0; half < 2; half++) {
            int row = bm0 + wm0 + mt * 16 + g + half * 8;
            float rs = (EPI == EPI_GSP) ? pi[row * NS + 4] : 0.f;
            float* cp = C + (long)row * N + colbase;
#pragma unroll
            for (int nt = 0; nt < 8; nt++) {
                int col = nt * 8 + tig * 2;
                float b0 = 0.f, b1 = 0.f;
                if (EPI != EPI_NONE) {
                    b0 = bias[colbase + col];
                    b1 = bias[colbase + col + 1];
                }
                float v0 = epi_apply<EPI>(c[mt][nt][half * 2], b0, rs);
                float v1 = epi_apply<EPI>(c[mt][nt][half * 2 + 1], b1, rs);
                *(float2*)(cp + col) = make_float2(v0, v1);
            }
        }
    }
}

// ---------------- GEMM kernels ----------------
template <int EPI, int MODE>
__global__ void __launch_bounds__(256, 2) tgemm_k(
    const float* __restrict__ A, const float* __restrict__ Bhi,
    const float* __restrict__ Blo, const float* __restrict__ bias,
    float* __restrict__ C, int N, int K, const float* __restrict__ pi)
{
    extern __shared__ float sm[];
    const int bm0 = blockIdx.y * 128, bn0 = blockIdx.x * 128;
    float c[2][8][4];
#pragma unroll
    for (int a = 0; a < 2; a++)
#pragma unroll
        for (int b = 0; b < 8; b++)
#pragma unroll
            for (int r = 0; r < 4; r++) c[a][b][r] = 0.f;
    tf32_loop<false, MODE>(A, Bhi, Blo, K, N, bm0, bn0, nullptr, sm, c);
    epi_store_dense<EPI>(c, C, bias, N, bm0, bn0, pi);
}

// z-pair over adjacent arena weights (stride D*D)
template <int EPI0, int EPI1, int MODE>
__global__ void __launch_bounds__(256, 2) tgemm_pair_k(
    const float* __restrict__ A, const float* __restrict__ Whi,
    const float* __restrict__ Wlo, const float* __restrict__ b0,
    const float* __restrict__ b1, const float* __restrict__ pi,
    float* __restrict__ Cbase)
{
    extern __shared__ float sm[];
    const int z = blockIdx.z;
    const float* Bhi = Whi + (long)z * D * D;
    const float* Blo = Wlo + (long)z * D * D;
    const float* bias = z ? b1 : b0;
    float* C = Cbase + (long)z * ROW;
    const int bm0 = blockIdx.y * 128, bn0 = blockIdx.x * 128;
    float c[2][8][4];
#pragma unroll
    for (int a = 0; a < 2; a++)
#pragma unroll
        for (int b = 0; b < 8; b++)
#pragma unroll
            for (int r = 0; r < 4; r++) c[a][b][r] = 0.f;
    tf32_loop<false, MODE>(A, Bhi, Blo, D, D, bm0, bn0, nullptr, sm, c);
    if (z == 0) epi_store_dense<EPI0>(c, C, bias, D, bm0, bn0, pi);
    else        epi_store_dense<EPI1>(c, C, bias, D, bm0, bn0, pi);
}

template <int MODE>
__global__ void __launch_bounds__(256, 2) tqkv_k(
    const float* __restrict__ A, const float* __restrict__ Whi,
    const float* __restrict__ Wlo, float* __restrict__ Cbase)
{
    extern __shared__ float sm[];
    const int z = blockIdx.z;
    const float* Bhi = Whi + (long)z * D * D;
    const float* Blo = Wlo + (long)z * D * D;
    float* C = Cbase + (long)z * ROW;
    const int bm0 = blockIdx.y * 128, bn0 = blockIdx.x * 128;
    float c[2][8][4];
#pragma unroll
    for (int a = 0; a < 2; a++)
#pragma unroll
        for (int b = 0; b < 8; b++)
#pragma unroll
            for (int r = 0; r < 4; r++) c[a][b][r] = 0.f;
    tf32_loop<false, MODE>(A, Bhi, Blo, D, D, bm0, bn0, nullptr, sm, c);
    epi_store_dense<EPI_NONE>(c, C, nullptr, D, bm0, bn0, nullptr);
}

template <int MODE>
__global__ void __launch_bounds__(256, 2) tbank1_k(
    const float* __restrict__ A, const float* __restrict__ Whi,
    const float* __restrict__ Wlo, const float* __restrict__ b1all,
    float* __restrict__ hb, const int* __restrict__ list,
    const int* __restrict__ cnt)
{
    extern __shared__ float sm[];
    __shared__ int rowTok[128];
    const int s = blockIdx.z;
    const int cn = cnt[s];
    const int bm0 = blockIdx.y * 128;
    if (bm0 >= cn) return;
    const int tid = threadIdx.x;
    if (tid < 128) rowTok[tid] = list[s * NTOK + min(bm0 + tid, cn - 1)];
    __syncthreads();

    const float* Bhi = Whi + (long)s * D * FFN;
    const float* Blo = Wlo + (long)s * D * FFN;
    const float* bias = b1all + s * FFN;
    float* C = hb + (long)s * NTOK * FFN;
    const int bn0 = blockIdx.x * 128;

    float c[2][8][4];
#pragma unroll
    for (int a = 0; a < 2; a++)
#pragma unroll
        for (int b = 0; b < 8; b++)
#pragma unroll
            for (int r = 0; r < 4; r++) c[a][b][r] = 0.f;
    tf32_loop<true, MODE>(A, Bhi, Blo, D, FFN, 0, bn0, rowTok, sm, c);

    const int lane = tid & 31, warp = tid >> 5;
    const int wm0 = (warp >> 1) * 32, wn0 = (warp & 1) * 64;
    const int g = lane >> 2, tig = lane & 3;
    const int colbase = bn0 + wn0;
#pragma unroll
    for (int mt = 0; mt < 2; mt++) {
#pragma unroll
        for (int half = 0; half < 2; half++) {
            int slot = bm0 + wm0 + mt * 16 + g + half * 8;
            if (slot >= cn) continue;
            float* cp = C + (long)slot * FFN + colbase;
#pragma unroll
            for (int nt = 0; nt < 8; nt++) {
                int col = nt * 8 + tig * 2;
                float v0 = gelu_f(c[mt][nt][half * 2] + bias[colbase + col]);
                float v1 = gelu_f(c[mt][nt][half * 2 + 1] + bias[colbase + col + 1]);
                *(float2*)(cp + col) = make_float2(v0, v1);
            }
        }
    }
}

template <int RANK, int MODE>
__global__ void __launch_bounds__(256, 2) tbank2_k(
    const float* __restrict__ hb, const float* __restrict__ Whi,
    const float* __restrict__ Wlo, const float* __restrict__ b2all,
    float* __restrict__ so, const int* __restrict__ cnt2,
    const int* __restrict__ slot2, const int* __restrict__ tok2,
    const float* __restrict__ pi)
{
    extern __shared__ float sm[];
    __shared__ int rowSlot[128];
    const int s = blockIdx.z;
    const int cn = cnt2[RANK * NS + s];
    const int bm0 = blockIdx.y * 128;
    if (bm0 >= cn) return;
    const int tid = threadIdx.x;
    const int lbase = (RANK * NS + s) * NTOK;
    if (tid < 128) rowSlot[tid] = slot2[lbase + min(bm0 + tid, cn - 1)];
    __syncthreads();

    const float* A = hb + (long)s * NTOK * FFN;
    const float* Bhi = Whi + (long)s * FFN * D;
    const float* Blo = Wlo + (long)s * FFN * D;
    const float* bias = b2all + s * D;
    const int bn0 = blockIdx.x * 128;

    float c[2][8][4];
#pragma unroll
    for (int a = 0; a < 2; a++)
#pragma unroll
        for (int b = 0; b < 8; b++)
#pragma unroll
            for (int r = 0; r < 4; r++) c[a][b][r] = 0.f;
    tf32_loop<true, MODE>(A, Bhi, Blo, FFN, D, 0, bn0, rowSlot, sm, c);

    const int lane = tid & 31, warp = tid >> 5;
    const int wm0 = (warp >> 1) * 32, wn0 = (warp & 1) * 64;
    const int g = lane >> 2, tig = lane & 3;
    const int colbase = bn0 + wn0;
#pragma unroll
    for (int mt = 0; mt < 2; mt++) {
#pragma unroll
        for (int half = 0; half < 2; half++) {
            int idx = bm0 + wm0 + mt * 16 + g + half * 8;
            if (idx >= cn) continue;
            int tok = tok2[lbase + idx];
            float rs = pi[tok * NS + s];
            float* cp = so + (long)tok * D + colbase;
#pragma unroll
            for (int nt = 0; nt < 8; nt++) {
                int col = nt * 8 + tig * 2;
                float v0 = rs * (c[mt][nt][half * 2] + bias[colbase + col]);
                float v1 = rs * (c[mt][nt][half * 2 + 1] + bias[colbase + col + 1]);
                if (RANK == 0) {
                    *(float2*)(cp + col) = make_float2(v0, v1);
                } else {
                    float2 old = *(float2*)(cp + col);
                    *(float2*)(cp + col) = make_float2(old.x + v0, old.y + v1);
                }
            }
        }
    }
}

// ---------------- small kernels ----------------
__global__ void emb_k(const int* __restrict__ x, const float* __restrict__ emb,
                      const float* __restrict__ pos, float* __restrict__ h)
{
    int n = blockIdx.x;
    int vx = x[n];
    int t = n % TSEQ;
    const float* e = emb + (long)vx * D;
    const float* p = pos + (long)t * D;
    for (int j = threadIdx.x; j < D; j += blockDim.x)
        h[(long)n * D + j] = e[j] + p[j];
}

// pi init + counter zeroing (counters must be clean at every graph replay)
__global__ void pi_init_k(float* __restrict__ pi, int* __restrict__ cnt,
                          int* __restrict__ cnt2)
{
    int i = blockIdx.x * blockDim.x + threadIdx.x;
    if (i < NTOK * NS) pi[i] = ((i % NS) == 2) ? 1.f : 0.f;
    if (i < NS) cnt[i] = 0;
    if (i < 2 * NS) cnt2[i] = 0;
}

__global__ void build_lists_k(const float* __restrict__ pi,
                              int* __restrict__ cnt, int* __restrict__ list,
                              int* __restrict__ cnt2, int* __restrict__ slot2,
                              int* __restrict__ tok2)
{
    int t = blockIdx.x * blockDim.x + threadIdx.x;
    if (t >= NTOK) return;
    int r = 0;
#pragma unroll
    for (int s = 0; s < NS; s++) {
        if (pi[t * NS + s] != 0.f) {
            int p = atomicAdd(&cnt[s], 1);
            list[s * NTOK + p] = t;
            int rr = min(r, 1);
            int q = atomicAdd(&cnt2[rr * NS + s], 1);
            slot2[(rr * NS + s) * NTOK + q] = p;
            tok2[(rr * NS + s) * NTOK + q] = t;
            r++;
        }
    }
}

__global__ void ln012_k(const float* __restrict__ mu, float* __restrict__ muhat,
                        float* __restrict__ mun, float* __restrict__ mur,
                        const float* __restrict__ ln_g, const float* __restrict__ ln_b)
{
    __shared__ float red[8];
    int n = blockIdx.x, tid = threadIdx.x;
    const float* row = mu + (long)n * D;
    float v[3], s = 0.f;
#pragma unroll
    for (int r = 0; r < 3; r++) { v[r] = row[tid + r * 256]; s += v[r]; }
    float mean = block_sum(s, red) / D;
    float qv = 0.f;
#pragma unroll
    for (int r = 0; r < 3; r++) { float d = v[r] - mean; qv += d * d; }
    float var = block_sum(qv, red) / D;
    float inv = rsqrtf(var + 1e-5f);
#pragma unroll
    for (int r = 0; r < 3; r++) {
        int j = tid + r * 256;
        float nh = (v[r] - mean) * inv;
        long idx = (long)n * D + j;
        muhat[idx] = nh;
        mun[idx] = nh * ln_g[j] + ln_b[j];
        mur[idx] = nh * ln_g[2 * D + j] + ln_b[2 * D + j];
    }
}

__global__ void ln_gen_k(const float* __restrict__ in, float* __restrict__ out,
                         const float* __restrict__ g, const float* __restrict__ b)
{
    __shared__ float red[8];
    int n = blockIdx.x, tid = threadIdx.x;
    const float* row = in + (long)n * D;
    float v[3], s = 0.f;
#pragma unroll
    for (int r = 0; r < 3; r++) { v[r] = row[tid + r * 256]; s += v[r]; }
    float mean = block_sum(s, red) / D;
    float qv = 0.f;
#pragma unroll
    for (int r = 0; r < 3; r++) { float d = v[r] - mean; qv += d * d; }
    float var = block_sum(qv, red) / D;
    float inv = rsqrtf(var + 1e-5f);
#pragma unroll
    for (int r = 0; r < 3; r++) {
        int j = tid + r * 256;
        out[(long)n * D + j] = (v[r] - mean) * inv * g[j] + b[j];
    }
}

// LN then tf32-round (rna) — feeds the pure-tf32 logits GEMM
__global__ void ln_cvt_k(const float* __restrict__ in, float* __restrict__ out,
                         const float* __restrict__ g, const float* __restrict__ b)
{
    __shared__ float red[8];
    int n = blockIdx.x, tid = threadIdx.x;
    const float* row = in + (long)n * D;
    float v[3], s = 0.f;
#pragma unroll
    for (int r = 0; r < 3; r++) { v[r] = row[tid + r * 256]; s += v[r]; }
    float mean = block_sum(s, red) / D;
    float qv = 0.f;
#pragma unroll
    for (int r = 0; r < 3; r++) { float d = v[r] - mean; qv += d * d; }
    float var = block_sum(qv, red) / D;
    float inv = rsqrtf(var + 1e-5f);
#pragma unroll
    for (int r = 0; r < 3; r++) {
        int j = tid + r * 256;
        float val = (v[r] - mean) * inv * g[j] + b[j];
        out[(long)n * D + j] = cvt_hi(val);
    }
}

// routing; block 0 also re-zeroes the compaction counters for the NEXT step's
// build (this step's bank kernels have already consumed them — stream order).
__global__ void routing_k(const float* __restrict__ trh, const float* __restrict__ w2,
                          const float* __restrict__ b2, const float* __restrict__ mun,
                          const float* __restrict__ evw, const float* __restrict__ evb,
                          float* __restrict__ pi, int* __restrict__ cnt,
                          int* __restrict__ cnt2)
{
    __shared__ float sh[1536];
    __shared__ float smn[D];
    __shared__ float kz[36];
    __shared__ float ev[6];
    __shared__ float spi[6];
    int n = blockIdx.x, tid = threadIdx.x;
    if (n == 0) {
        if (tid < NS) cnt[tid] = 0;
        if (tid < 2 * NS) cnt2[tid] = 0;
    }
    for (int i = tid; i < 1536; i += 128) sh[i] = trh[(long)n * 1536 + i];
    for (int i = tid; i < D; i += 128)    smn[i] = mun[(long)n * D + i];
    if (tid < NS) spi[tid] = pi[n * NS + tid];
    __syncthreads();
    if (tid < 36) {
        float acc = b2[tid];
        for (int k = 0; k < 1536; k++) acc += sh[k] * w2[k * 36 + tid];
        kz[tid] = acc;
    } else if (tid < 42) {
        int j = tid - 36;
        float acc = evb[j];
        for (int k = 0; k < D; k++) acc += smn[k] * evw[k * NS + j];
        ev[j] = acc;
    }
    __syncthreads();
    if (tid == 0) {
        float Kr[6][6];
        for (int s = 0; s < 6; s++) {
            float mx = kz[s * 6];
            for (int u = 1; u < 6; u++) mx = fmaxf(mx, kz[s * 6 + u]);
            float sum = 0.f;
            for (int u = 0; u < 6; u++) { float e = expf(kz[s * 6 + u] - mx); Kr[s][u] = e; sum += e; }
            float invr = 1.f / sum;
            for (int u = 0; u < 6; u++) Kr[s][u] *= invr;
        }
        float pev[6];
        for (int u = 0; u < 6; u++) {
            float a = 0.f;
            for (int s = 0; s < 6; s++) a += spi[s] * Kr[s][u];
            pev[u] = a;
        }
        float mx = ev[0] * 2.f;
        for (int u = 1; u < 6; u++) mx = fmaxf(mx, ev[u] * 2.f);
        float wv[6], sw = 0.f;
        for (int u = 0; u < 6; u++) { wv[u] = expf(ev[u] * 2.f - mx); sw += wv[u]; }
        float invw = 1.f / sw;
        float pn[6], s1 = 0.f;
        for (int u = 0; u < 6; u++) { pn[u] = pev[u] * wv[u] * invw; s1 += pn[u]; }
        float inv1 = 1.f / fmaxf(s1, 1e-8f);
        for (int u = 0; u < 6; u++) pn[u] *= inv1;
        int i1 = 0;
        for (int u = 1; u < 6; u++) if (pn[u] > pn[i1]) i1 = u;
        int i2 = (i1 == 0) ? 1 : 0;
        for (int u = 0; u < 6; u++) if (u != i1 && pn[u] > pn[i2]) i2 = u;
        float inv2 = 1.f / fmaxf(pn[i1] + pn[i2], 1e-8f);
        for (int u = 0; u < 6; u++)
            pi[n * NS + u] = (u == i1 || u == i2) ? pn[u] * inv2 : 0.f;
    }
}

__global__ void attn_k(const float* __restrict__ q, const float* __restrict__ k,
                       const float* __restrict__ v, const float* __restrict__ pi,
                       const float* __restrict__ ln_g, const float* __restrict__ ln_b,
                       float* __restrict__ msg)
{
    __shared__ float sw[4];
    __shared__ float mb[D];
    __shared__ float red[8];
    int n = blockIdx.x, tid = threadIdx.x;
    int t = n % TSEQ;
    int warp = tid >> 5, lane = tid & 31;
    const int offs[4] = {-2, -1, 1, 2};
    {
        int o = offs[warp];
        int tt = t + o;
        float dot = 0.f;
        if (tt >= 0 && tt < TSEQ) {
            const float* qp = q + (long)n * D;
            const float* kp = k + (long)(n + o) * D;
            for (int j = lane; j < D; j += 32) dot += qp[j] * kp[j];
        }
#pragma unroll
        for (int s = 16; s > 0; s >>= 1) dot += __shfl_xor_sync(0xffffffffu, dot, s);
        if (lane == 0)
            sw[warp] = (tt >= 0 && tt < TSEQ) ? dot / 27.712812921102035f : -1e9f;
    }
    __syncthreads();
    float w0 = sw[0], w1 = sw[1], w2 = sw[2], w3 = sw[3];
    float mx = fmaxf(fmaxf(w0, w1), fmaxf(w2, w3));
    float wt[4] = {expf(w0 - mx), expf(w1 - mx), expf(w2 - mx), expf(w3 - mx)};
    float invs = 1.f / (wt[0] + wt[1] + wt[2] + wt[3]);
#pragma unroll
    for (int w = 0; w < 4; w++) wt[w] *= invs;
    float pi3 = pi[n * NS + 3];
    for (int j = tid; j < D; j += 128) {
        float m = 0.f;
#pragma unroll
        for (int w = 0; w < 4; w++) {
            int tt = t + offs[w];
            if (tt >= 0 && tt < TSEQ) m += wt[w] * v[(long)(n + offs[w]) * D + j];
        }
        mb[j] = m * pi3;
    }
    __syncthreads();
    float loc[6], s = 0.f;
#pragma unroll
    for (int r = 0; r < 6; r++) { loc[r] = mb[tid + r * 128]; s += loc[r]; }
    float mean = block_sum(s, red) / D;
    float qv = 0.f;
#pragma unroll
    for (int r = 0; r < 6; r++) { float d = loc[r] - mean; qv += d * d; }
    float var = block_sum(qv, red) / D;
    float inv = rsqrtf(var + 1e-5f);
#pragma unroll
    for (int r = 0; r < 6; r++) {
        int j = tid + r * 128;
        msg[(long)n * D + j] = (loc[r] - mean) * inv * ln_g[3 * D + j] + ln_b[3 * D + j];
    }
}

__global__ void update_k(const float* __restrict__ muhat, float* __restrict__ lam,
                         const float* __restrict__ dlam, const float* __restrict__ mhat,
                         const float* __restrict__ so,
                         const float* __restrict__ ln_g, const float* __restrict__ ln_b,
                         float* __restrict__ mu)
{
    __shared__ float red[8];
    int n = blockIdx.x, tid = threadIdx.x;
    float mval[3], s = 0.f;
#pragma unroll
    for (int r = 0; r < 3; r++) {
        int j = tid + r * 256;
        long idx = (long)n * D + j;
        float l = lam[idx], dl = dlam[idx];
        float mwn = muhat[idx] * ln_g[4 * D + j] + ln_b[4 * D + j];
        float lnw = l + dl;
        float m = (l * mwn + dl * mhat[idx]) / lnw;
        lam[idx] = lnw;
        mval[r] = m;
        s += m;
    }
    float mean = block_sum(s, red) / D;
    float qv = 0.f;
#pragma unroll
    for (int r = 0; r < 3; r++) { float d = mval[r] - mean; qv += d * d; }
    float var = block_sum(qv, red) / D;
    float inv = rsqrtf(var + 1e-5f);
#pragma unroll
    for (int r = 0; r < 3; r++) {
        int j = tid + r * 256;
        long idx = (long)n * D + j;
        mu[idx] = (mval[r] - mean) * inv * ln_g[5 * D + j] + ln_b[5 * D + j] + so[idx] * 0.1f;
    }
}

// ---------------- launcher ----------------
extern "C" void kernel_launch(void* const* d_in, const int* in_sizes, int n_in,
                              void* d_out, int out_size)
{
    const int*   x        = (const int*)d_in[0];
    const float* emb_w    = (const float*)d_in[1];
    const float* pos_w    = (const float*)d_in[2];
    const float* mu_w     = (const float*)d_in[3];
    const float* mu_b     = (const float*)d_in[4];
    const float* lam_w    = (const float*)d_in[5];
    const float* lam_b    = (const float*)d_in[6];
    const float* tr_w1    = (const float*)d_in[7];
    const float* tr_b1    = (const float*)d_in[8];
    const float* tr_w2    = (const float*)d_in[9];
    const float* tr_b2    = (const float*)d_in[10];
    const float* bank_w1  = (const float*)d_in[11];
    const float* bank_b1  = (const float*)d_in[12];
    const float* bank_w2  = (const float*)d_in[13];
    const float* bank_b2  = (const float*)d_in[14];
    const float* ev_w     = (const float*)d_in[15];
    const float* ev_b     = (const float*)d_in[16];
    const float* rt_q     = (const float*)d_in[17];
    const float* rt_k     = (const float*)d_in[18];
    const float* rt_v     = (const float*)d_in[19];
    const float* wr_lam_w = (const float*)d_in[20];
    const float* wr_lam_b = (const float*)d_in[21];
    const float* wr_mu_w  = (const float*)d_in[22];
    const float* wr_mu_b  = (const float*)d_in[23];
    const float* ln_g     = (const float*)d_in[24];
    const float* ln_b     = (const float*)d_in[25];
    float* out = (float*)d_out;

    cudaFuncSetAttribute(tgemm_k<EPI_GELU, 0>, cudaFuncAttributeMaxDynamicSharedMemorySize, SM_BYTES);
    cudaFuncSetAttribute(tgemm_pair_k<EPI_BIAS, EPI_SP01, 0>, cudaFuncAttributeMaxDynamicSharedMemorySize, SM_BYTES);
    cudaFuncSetAttribute(tgemm_pair_k<EPI_GSP, EPI_BIAS, 0>, cudaFuncAttributeMaxDynamicSharedMemorySize, SM_BYTES);
    cudaFuncSetAttribute(tgemm_pair_k<EPI_GSP, EPI_BIAS, 2>, cudaFuncAttributeMaxDynamicSharedMemorySize, SM_BYTES);
    cudaFuncSetAttribute(tqkv_k<0>, cudaFuncAttributeMaxDynamicSharedMemorySize, SM_BYTES);
    cudaFuncSetAttribute(tqkv_k<2>, cudaFuncAttributeMaxDynamicSharedMemorySize, SM_BYTES);
    cudaFuncSetAttribute(tbank1_k<0>, cudaFuncAttributeMaxDynamicSharedMemorySize, SM_BYTES);
    cudaFuncSetAttribute(tbank1_k<2>, cudaFuncAttributeMaxDynamicSharedMemorySize, SM_BYTES);
    cudaFuncSetAttribute(tbank2_k<0, 0>, cudaFuncAttributeMaxDynamicSharedMemorySize, SM_BYTES);
    cudaFuncSetAttribute(tbank2_k<1, 0>, cudaFuncAttributeMaxDynamicSharedMemorySize, SM_BYTES);
    cudaFuncSetAttribute(tbank2_k<0, 2>, cudaFuncAttributeMaxDynamicSharedMemorySize, SM_BYTES);
    cudaFuncSetAttribute(tbank2_k<1, 2>, cudaFuncAttributeMaxDynamicSharedMemorySize, SM_BYTES);
    cudaFuncSetAttribute(tlogits_k, cudaFuncAttributeMaxDynamicSharedMemorySize, LG_SM_BYTES);

    float* base = nullptr;
    cudaGetSymbolAddress((void**)&base, g_scratch);
    float *whi = nullptr, *wlo = nullptr;
    cudaGetSymbolAddress((void**)&whi, g_whi);
    cudaGetSymbolAddress((void**)&wlo, g_wlo);
    int *cnt, *list, *cnt2, *slot2, *tok2;
    cudaGetSymbolAddress((void**)&cnt, g_cnt);
    cudaGetSymbolAddress((void**)&list, g_list);
    cudaGetSymbolAddress((void**)&cnt2, g_cnt2);
    cudaGetSymbolAddress((void**)&slot2, g_slot2);
    cudaGetSymbolAddress((void**)&tok2, g_tok2);

    float* h     = base + OFF_H;
    float* mu    = base + OFF_MU;
    float* muhat = base + OFF_MUHAT;
    float* mun   = base + OFF_MUN;
    float* mur   = base + OFF_MUR;
    float* so    = base + OFF_SO;
    float* qb    = base + OFF_Q;
    float* lam   = base + OFF_LAM;
    float* msg   = base + OFF_MSG;
    float* dlam  = base + OFF_DLAM;
    float* mhat  = base + OFF_MHAT;
    float* fin   = base + OFF_FIN;
    float* trh   = base + OFF_TRH;
    float* hb    = base + OFF_HB;
    float* pi    = base + OFF_PI;

    const float inv_sqrt_d = 0.03608439182435161f;

    // ---- weight prep: split (and transpose emb hi) into arena ----
    {
        const int DD4 = D * D / 4;
        split_k<<<(DD4 + 255) / 256, 256>>>(mu_w,     whi + W_MU,  wlo + W_MU,  DD4);
        split_k<<<(DD4 + 255) / 256, 256>>>(lam_w,    whi + W_LAM, wlo + W_LAM, DD4);
        split_k<<<(D * 1536 / 4 + 255) / 256, 256>>>(tr_w1, whi + W_TR1, wlo + W_TR1, D * 1536 / 4);
        split_k<<<(DD4 + 255) / 256, 256>>>(rt_q,     whi + W_RTQ, wlo + W_RTQ, DD4);
        split_k<<<(DD4 + 255) / 256, 256>>>(rt_k,     whi + W_RTK, wlo + W_RTK, DD4);
        split_k<<<(DD4 + 255) / 256, 256>>>(rt_v,     whi + W_RTV, wlo + W_RTV, DD4);
        split_k<<<(DD4 + 255) / 256, 256>>>(wr_lam_w, whi + W_WRL, wlo + W_WRL, DD4);
        split_k<<<(DD4 + 255) / 256, 256>>>(wr_mu_w,  whi + W_WRM, wlo + W_WRM, DD4);
        const int B14 = NS * D * FFN / 4;
        split_k<<<(B14 + 255) / 256, 256>>>(bank_w1, whi + W_B1, wlo + W_B1, B14);
        split_k<<<(B14 + 255) / 256, 256>>>(bank_w2, whi + W_B2, wlo + W_B2, B14);
        dim3 gt(VOC / 32, D / 32);
        tsplit_emb_k<<<gt, dim3(32, 8)>>>(emb_w, whi + W_EMBT);
    }

    emb_k<<<NTOK, 256>>>(x, emb_w, pos_w, h);
    {
        dim3 g(D / 128, NTOK / 128, 2);
        tgemm_pair_k<EPI_BIAS, EPI_SP01, 0><<<g, 256, SM_BYTES>>>(
            h, whi + W_MU, wlo + W_MU, mu_b, lam_b, nullptr, mu);
    }
    pi_init_k<<<(NTOK * NS + 255) / 256, 256>>>(pi, cnt, cnt2);

    for (int step = 0; step < 3; step++) {
        const bool last = (step == 2);
        ln012_k<<<NTOK, 256>>>(mu, muhat, mun, mur, ln_g, ln_b);
        {
            dim3 g(1536 / 128, NTOK / 128);
            tgemm_k<EPI_GELU, 0><<<g, 256, SM_BYTES>>>(mu, whi + W_TR1, wlo + W_TR1,
                                                       tr_b1, trh, 1536, D, nullptr);
        }
        build_lists_k<<<NTOK / 256, 256>>>(pi, cnt, list, cnt2, slot2, tok2);
        {
            dim3 g1(FFN / 128, NTOK / 128, NS);
            dim3 g2(D / 128, NTOK / 128, NS);
            if (!last) {
                tbank1_k<0><<<g1, 256, SM_BYTES>>>(mun, whi + W_B1, wlo + W_B1, bank_b1, hb, list, cnt);
                tbank2_k<0, 0><<<g2, 256, SM_BYTES>>>(hb, whi + W_B2, wlo + W_B2, bank_b2,
                                                      so, cnt2, slot2, tok2, pi);
                tbank2_k<1, 0><<<g2, 256, SM_BYTES>>>(hb, whi + W_B2, wlo + W_B2, bank_b2,
                                                      so, cnt2, slot2, tok2, pi);
            } else {
                tbank1_k<2><<<g1, 256, SM_BYTES>>>(mun, whi + W_B1, wlo + W_B1, bank_b1, hb, list, cnt);
                tbank2_k<0, 2><<<g2, 256, SM_BYTES>>>(hb, whi + W_B2, wlo + W_B2, bank_b2,
                                                      so, cnt2, slot2, tok2, pi);
                tbank2_k<1, 2><<<g2, 256, SM_BYTES>>>(hb, whi + W_B2, wlo + W_B2, bank_b2,
                                                      so, cnt2, slot2, tok2, pi);
            }
        }
        ln_gen_k<<<NTOK, 256>>>(so, so, ln_g + 1 * D, ln_b + 1 * D);
        routing_k<<<NTOK, 128>>>(trh, tr_w2, tr_b2, mun, ev_w, ev_b, pi, cnt, cnt2);
        {
            dim3 g(D / 128, NTOK / 128, 3);
            if (!last) tqkv_k<0><<<g, 256, SM_BYTES>>>(mur, whi + W_RTQ, wlo + W_RTQ, qb);
            else       tqkv_k<2><<<g, 256, SM_BYTES>>>(mur, whi + W_RTQ, wlo + W_RTQ, qb);
        }
        attn_k<<<NTOK, 128>>>(qb, qb + ROW, qb + 2 * ROW, pi, ln_g, ln_b, msg);
        {
            dim3 g(D / 128, NTOK / 128, 2);
            if (!last)
                tgemm_pair_k<EPI_GSP, EPI_BIAS, 0><<<g, 256, SM_BYTES>>>(
                    msg, whi + W_WRL, wlo + W_WRL, wr_lam_b, wr_mu_b, pi, dlam);
            else
                tgemm_pair_k<EPI_GSP, EPI_BIAS, 2><<<g, 256, SM_BYTES>>>(
                    msg, whi + W_WRL, wlo + W_WRL, wr_lam_b, wr_mu_b, pi, dlam);
        }
        update_k<<<NTOK, 256>>>(muhat, lam, dlam, mhat, so, ln_g, ln_b, mu);
    }

    // final LN with tf32 rounding at producer; pure-tf32 logits GEMM
    ln_cvt_k<<<NTOK, 256>>>(mu, fin, ln_g + 6 * D, ln_b + 6 * D);
    {
        dim3 g(NTOK / 128, VOC / 128);  // x = M-tiles: concurrent CTAs share B
        tlogits_k<<<g, 256, LG_SM_BYTES>>>(fin, whi + W_EMBT, out, VOC, D, inv_sqrt_d);
    }
}